// round 5
// baseline (speedup 1.0000x reference)
#include <cuda_runtime.h>
#include <math.h>

#define B_ 4
#define T_ 2048
#define C_ 1024
#define H_ 16
#define D_ 64
#define M_ (B_*T_)   /* 8192 rows of x flattened */

// Scratch (device globals: allocation-free per harness rules)
__device__ float g_q[(size_t)B_*H_*T_*D_];   // [B,H,T,D], pre-scaled by 1/sqrt(d)
__device__ float g_k[(size_t)B_*H_*T_*D_];
__device__ float g_v[(size_t)B_*H_*T_*D_];
__device__ float g_o[(size_t)M_*C_];         // attention output, [B*T, C]

// ---------------------------------------------------------------------------
// Register-tiled SGEMM: C[M,NCOLS] = A[M,1024] * Bw[1024,NCOLS] + bias
// 128x128 block tile, BK=16, 256 threads, 8x8 per thread (split 4+4 halves so
// smem compute loads are lane-consecutive float4 -> conflict-free).
// MODE 0: A = x, scatter into g_q/g_k/g_v head layout (q scaled by 0.125)
// MODE 1: A = g_o, plain store to Cout with bias
// ---------------------------------------------------------------------------
template<int NCOLS, int MODE>
__global__ __launch_bounds__(256, 2)
void sgemm_kernel(const float* __restrict__ Ain, const float* __restrict__ Bw,
                  const float* __restrict__ bias, float* __restrict__ Cout)
{
    constexpr int BK = 16;
    __shared__ float As[BK][128];
    __shared__ float Bs[BK][128];

    const int tid = threadIdx.x;
    const int tx = tid & 15, ty = tid >> 4;
    const int m0 = blockIdx.y * 128;
    const int n0 = blockIdx.x * 128;
    const int arow = tid >> 2, ac = (tid & 3) * 4;   // A tile: 64 rows x 16 cols per pass
    const int brow = tid >> 5, bc = (tid & 31) * 4;  // B tile: 8 rows x 128 cols per pass

    const float* A  = (MODE == 0) ? Ain : (const float*)g_o;
    const float* Ab = A + (size_t)m0 * C_;
    const float* Bb = Bw + n0;

    float acc[8][8];
    #pragma unroll
    for (int i = 0; i < 8; ++i) {
        #pragma unroll
        for (int j = 0; j < 8; ++j) acc[i][j] = 0.f;
    }

    // prefetch first tile into registers
    float4 ar0 = *(const float4*)(Ab + (size_t)arow        * C_ + ac);
    float4 ar1 = *(const float4*)(Ab + (size_t)(arow + 64) * C_ + ac);
    float4 br0 = *(const float4*)(Bb + (size_t)brow       * NCOLS + bc);
    float4 br1 = *(const float4*)(Bb + (size_t)(brow + 8) * NCOLS + bc);

    constexpr int NK = C_ / BK;   // 64
    for (int kt = 0; kt < NK; ++kt) {
        // commit prefetched tile to smem (A transposed)
        As[ac+0][arow]    = ar0.x; As[ac+1][arow]    = ar0.y;
        As[ac+2][arow]    = ar0.z; As[ac+3][arow]    = ar0.w;
        As[ac+0][arow+64] = ar1.x; As[ac+1][arow+64] = ar1.y;
        As[ac+2][arow+64] = ar1.z; As[ac+3][arow+64] = ar1.w;
        *(float4*)&Bs[brow][bc]   = br0;
        *(float4*)&Bs[brow+8][bc] = br1;
        __syncthreads();

        if (kt + 1 < NK) {   // prefetch next tile (overlaps with compute below)
            const float* Ap = Ab + (kt + 1) * BK;
            ar0 = *(const float4*)(Ap + (size_t)arow        * C_ + ac);
            ar1 = *(const float4*)(Ap + (size_t)(arow + 64) * C_ + ac);
            const float* Bp = Bb + (size_t)((kt + 1) * BK) * NCOLS;
            br0 = *(const float4*)(Bp + (size_t)brow       * NCOLS + bc);
            br1 = *(const float4*)(Bp + (size_t)(brow + 8) * NCOLS + bc);
        }

        #pragma unroll
        for (int kk = 0; kk < BK; ++kk) {
            float ra[8], rb[8];
            *(float4*)&ra[0] = *(const float4*)&As[kk][ty * 4];
            *(float4*)&ra[4] = *(const float4*)&As[kk][64 + ty * 4];
            *(float4*)&rb[0] = *(const float4*)&Bs[kk][tx * 4];
            *(float4*)&rb[4] = *(const float4*)&Bs[kk][64 + tx * 4];
            #pragma unroll
            for (int i = 0; i < 8; ++i) {
                #pragma unroll
                for (int j = 0; j < 8; ++j) acc[i][j] += ra[i] * rb[j];
            }
        }
        __syncthreads();
    }

    // epilogue
    #pragma unroll
    for (int ih = 0; ih < 2; ++ih) {
        #pragma unroll
        for (int ii = 0; ii < 4; ++ii) {
            const int i = ih * 4 + ii;
            const int r = m0 + ih * 64 + ty * 4 + ii;
            #pragma unroll
            for (int jh = 0; jh < 2; ++jh) {
                const int n = n0 + jh * 64 + tx * 4;
                const float v0 = acc[i][jh*4+0] + bias[n+0];
                const float v1 = acc[i][jh*4+1] + bias[n+1];
                const float v2 = acc[i][jh*4+2] + bias[n+2];
                const float v3 = acc[i][jh*4+3] + bias[n+3];
                if (MODE == 0) {
                    const int which = n >> 10;        // 0=q 1=k 2=v
                    const int cc = n & 1023;
                    const int h  = cc >> 6, dd = cc & 63;
                    const int b  = r >> 11, t  = r & 2047;
                    const size_t idx = (((size_t)(b * H_ + h)) * T_ + t) * D_ + dd;
                    if (which == 0) {
                        // fold 1/sqrt(d_k)=0.125 into q
                        *(float4*)(g_q + idx) =
                            make_float4(v0*0.125f, v1*0.125f, v2*0.125f, v3*0.125f);
                    } else if (which == 1) {
                        *(float4*)(g_k + idx) = make_float4(v0, v1, v2, v3);
                    } else {
                        *(float4*)(g_v + idx) = make_float4(v0, v1, v2, v3);
                    }
                } else {
                    *(float4*)(Cout + (size_t)r * NCOLS + n) = make_float4(v0, v1, v2, v3);
                }
            }
        }
    }
}

// ---------------------------------------------------------------------------
// Causal flash attention, fp32. One block per (b*h, 64-row q-tile).
// 256 threads = 16x16 grid; thread (ty,tx) owns a 4x4 S micro-tile and a
// 4(row) x 4(d-col) O micro-tile. Smem operands stored transposed (Qt/Kt/Ps
// indexed [reduction][lane-consecutive]) so hot LDS.128 are conflict-free.
// ---------------------------------------------------------------------------
__global__ __launch_bounds__(256)
void flash_kernel()
{
    constexpr int LD = 68;   // 64 + 4 pad (floats)
    extern __shared__ float sm[];
    float* Qt = sm;               // [d=64][r=64] (+pad)
    float* Kt = Qt + 64 * LD;     // [d=64][c=64]
    float* Vs = Kt + 64 * LD;     // [c=64][d=64]
    float* Ps = Vs + 64 * LD;     // [c=64][r=64]

    const int tid = threadIdx.x;
    const int tx = tid & 15, ty = tid >> 4;
    const int bh = blockIdx.y;                           // 0..63
    const int qb = (int)gridDim.x - 1 - (int)blockIdx.x; // long blocks first
    const int q0 = qb * 64;
    const size_t base = (size_t)bh * T_ * D_;
    const float* Qg = g_q + base;
    const float* Kg = g_k + base;
    const float* Vg = g_v + base;

    const int lr = tid >> 2;       // 0..63 (tile row for loads)
    const int lf = tid & 3;        // float4-column group

    // load Q tile transposed: Qt[d][r]
    {
        const float* src = Qg + (size_t)(q0 + lr) * D_;
        #pragma unroll
        for (int p = 0; p < 4; ++p) {
            const int f4 = (lf + 4 * p) * 4;
            float4 v = *(const float4*)(src + f4);
            Qt[(f4+0)*LD + lr] = v.x;
            Qt[(f4+1)*LD + lr] = v.y;
            Qt[(f4+2)*LD + lr] = v.z;
            Qt[(f4+3)*LD + lr] = v.w;
        }
    }

    float o[4][4];
    float mr[4], ls[4];
    #pragma unroll
    for (int i = 0; i < 4; ++i) {
        mr[i] = -INFINITY; ls[i] = 0.f;
        #pragma unroll
        for (int j = 0; j < 4; ++j) o[i][j] = 0.f;
    }

    for (int kt = 0; kt <= qb; ++kt) {
        const int k0 = kt * 64;
        __syncthreads();  // prior iter's Kt/Vs/Ps fully consumed
        {
            const float* sK = Kg + (size_t)(k0 + lr) * D_;
            const float* sV = Vg + (size_t)(k0 + lr) * D_;
            #pragma unroll
            for (int p = 0; p < 4; ++p) {
                const int f4 = (lf + 4 * p) * 4;
                float4 kv = *(const float4*)(sK + f4);
                Kt[(f4+0)*LD + lr] = kv.x;
                Kt[(f4+1)*LD + lr] = kv.y;
                Kt[(f4+2)*LD + lr] = kv.z;
                Kt[(f4+3)*LD + lr] = kv.w;
                *(float4*)&Vs[lr * LD + f4] = *(const float4*)(sV + f4);
            }
        }
        __syncthreads();

        // S = Q K^T (q pre-scaled)
        float s[4][4];
        #pragma unroll
        for (int i = 0; i < 4; ++i) {
            #pragma unroll
            for (int j = 0; j < 4; ++j) s[i][j] = 0.f;
        }
        #pragma unroll 16
        for (int d = 0; d < 64; ++d) {
            float qa[4], ka[4];
            *(float4*)qa = *(const float4*)&Qt[d * LD + ty * 4];
            *(float4*)ka = *(const float4*)&Kt[d * LD + tx * 4];
            #pragma unroll
            for (int i = 0; i < 4; ++i) {
                #pragma unroll
                for (int j = 0; j < 4; ++j) s[i][j] += qa[i] * ka[j];
            }
        }

        // causal mask only possible on the diagonal tile (k0 == q0)
        if (kt == qb) {
            #pragma unroll
            for (int i = 0; i < 4; ++i) {
                #pragma unroll
                for (int j = 0; j < 4; ++j)
                    if (tx * 4 + j > ty * 4 + i) s[i][j] = -INFINITY;
            }
        }

        // online softmax; row stats reduced over the 16 lanes sharing ty
        #pragma unroll
        for (int i = 0; i < 4; ++i) {
            float mx = fmaxf(fmaxf(s[i][0], s[i][1]), fmaxf(s[i][2], s[i][3]));
            #pragma unroll
            for (int sh = 8; sh > 0; sh >>= 1)
                mx = fmaxf(mx, __shfl_xor_sync(0xffffffffu, mx, sh));
            const float mnew = fmaxf(mr[i], mx);
            const float corr = __expf(mr[i] - mnew);
            mr[i] = mnew;
            float ps = 0.f;
            #pragma unroll
            for (int j = 0; j < 4; ++j) {
                const float p = __expf(s[i][j] - mnew);
                s[i][j] = p;
                ps += p;
            }
            #pragma unroll
            for (int sh = 8; sh > 0; sh >>= 1)
                ps += __shfl_xor_sync(0xffffffffu, ps, sh);
            ls[i] = ls[i] * corr + ps;
            #pragma unroll
            for (int j = 0; j < 4; ++j) o[i][j] *= corr;
        }

        // stage P transposed: Ps[c][r]
        #pragma unroll
        for (int j = 0; j < 4; ++j) {
            #pragma unroll
            for (int i = 0; i < 4; ++i)
                Ps[(tx * 4 + j) * LD + ty * 4 + i] = s[i][j];
        }
        __syncthreads();

        // O += P V
        #pragma unroll 16
        for (int c = 0; c < 64; ++c) {
            float pa[4], va[4];
            *(float4*)pa = *(const float4*)&Ps[c * LD + ty * 4];
            *(float4*)va = *(const float4*)&Vs[c * LD + tx * 4];
            #pragma unroll
            for (int i = 0; i < 4; ++i) {
                #pragma unroll
                for (int j = 0; j < 4; ++j) o[i][j] += pa[i] * va[j];
            }
        }
    }

    // finalize + write to [B*T, C] layout for the output projection
    const int b = bh >> 4, h = bh & 15;
    #pragma unroll
    for (int i = 0; i < 4; ++i) {
        const int q = q0 + ty * 4 + i;
        const float inv = 1.f / ls[i];
        *(float4*)(g_o + ((size_t)(b * T_ + q)) * C_ + h * D_ + tx * 4) =
            make_float4(o[i][0]*inv, o[i][1]*inv, o[i][2]*inv, o[i][3]*inv);
    }
}

extern "C" void kernel_launch(void* const* d_in, const int* in_sizes, int n_in,
                              void* d_out, int out_size)
{
    (void)in_sizes; (void)n_in; (void)out_size;
    const float* x     = (const float*)d_in[0];
    const float* W_qkv = (const float*)d_in[1];
    const float* b_qkv = (const float*)d_in[2];
    const float* W_out = (const float*)d_in[3];
    const float* b_out = (const float*)d_in[4];
    float* out = (float*)d_out;

    // 1) QKV projection + bias + head-layout scatter (+ q scaling)
    sgemm_kernel<3 * C_, 0><<<dim3(3 * C_ / 128, M_ / 128), 256>>>(x, W_qkv, b_qkv, nullptr);

    // 2) causal flash attention
    const int smem = 4 * 64 * 68 * (int)sizeof(float);  // 69632 B
    cudaFuncSetAttribute(flash_kernel, cudaFuncAttributeMaxDynamicSharedMemorySize, smem);
    flash_kernel<<<dim3(T_ / 64, B_ * H_), 256, smem>>>();

    // 3) output projection + bias
    sgemm_kernel<C_, 1><<<dim3(C_ / 128, M_ / 128), 256>>>(nullptr, W_out, b_out, out);
}

// round 7
// speedup vs baseline: 1.4310x; 1.4310x over previous
#include <cuda_runtime.h>
#include <cuda_bf16.h>
#include <math.h>
#include <stdint.h>

#define B_ 4
#define T_ 2048
#define C_ 1024
#define H_ 16
#define D_ 64
#define M_ (B_*T_)      /* 8192 */
#define NQKV (3*C_)     /* 3072 */

// ---------------------------------------------------------------------------
// Device-global scratch (allocation-free per harness rules)
// ---------------------------------------------------------------------------
__device__ __align__(16) float g_q[(size_t)M_*C_];   // [B,H,T,D] fp32, q pre-scaled
__device__ __align__(16) float g_k[(size_t)M_*C_];
__device__ __align__(16) float g_v[(size_t)M_*C_];

__device__ __align__(16) __nv_bfloat16 g_xhi[(size_t)M_*C_];
__device__ __align__(16) __nv_bfloat16 g_xlo[(size_t)M_*C_];
__device__ __align__(16) __nv_bfloat16 g_wqh[(size_t)NQKV*C_];   // W_qkv^T [3072,1024]
__device__ __align__(16) __nv_bfloat16 g_wql[(size_t)NQKV*C_];
__device__ __align__(16) __nv_bfloat16 g_woh[(size_t)C_*C_];     // W_out^T [1024,1024]
__device__ __align__(16) __nv_bfloat16 g_wol[(size_t)C_*C_];
__device__ __align__(16) __nv_bfloat16 g_ohi[(size_t)M_*C_];     // attn out hi/lo [B*T, C]
__device__ __align__(16) __nv_bfloat16 g_olo[(size_t)M_*C_];

// ---------------------------------------------------------------------------
// Baseline-PTX helpers (compile at plain sm_103 target: no tcgen05)
// ---------------------------------------------------------------------------
__device__ __forceinline__ uint32_t smem_u32(const void* p) {
    uint32_t a;
    asm("{ .reg .u64 t; cvta.to.shared.u64 t, %1; cvt.u32.u64 %0, t; }" : "=r"(a) : "l"(p));
    return a;
}

__device__ __forceinline__ void cpasync16(uint32_t s, const void* g) {
    asm volatile("cp.async.cg.shared.global [%0], [%1], 16;" :: "r"(s), "l"(g));
}

__device__ __forceinline__ void ldsm4(uint32_t* r, uint32_t addr) {
    asm volatile("ldmatrix.sync.aligned.m8n8.x4.shared.b16 {%0,%1,%2,%3}, [%4];"
                 : "=r"(r[0]), "=r"(r[1]), "=r"(r[2]), "=r"(r[3]) : "r"(addr));
}

__device__ __forceinline__ void mma16816(float* c, const uint32_t* a, const uint32_t* b) {
    asm volatile(
        "mma.sync.aligned.m16n8k16.row.col.f32.bf16.bf16.f32 "
        "{%0,%1,%2,%3}, {%4,%5,%6,%7}, {%8,%9}, {%0,%1,%2,%3};"
        : "+f"(c[0]), "+f"(c[1]), "+f"(c[2]), "+f"(c[3])
        : "r"(a[0]), "r"(a[1]), "r"(a[2]), "r"(a[3]), "r"(b[0]), "r"(b[1]));
}

// ---------------------------------------------------------------------------
// Conversion kernels: fp32 -> bf16 hi/lo split
// ---------------------------------------------------------------------------
__global__ void xconvert_kernel(const float4* __restrict__ x)
{
    const size_t i = (size_t)blockIdx.x * blockDim.x + threadIdx.x;  // over M_*C_/4
    float4 v = x[i];
    __align__(8) __nv_bfloat16 h[4], l[4];
    h[0] = __float2bfloat16(v.x); l[0] = __float2bfloat16(v.x - __bfloat162float(h[0]));
    h[1] = __float2bfloat16(v.y); l[1] = __float2bfloat16(v.y - __bfloat162float(h[1]));
    h[2] = __float2bfloat16(v.z); l[2] = __float2bfloat16(v.z - __bfloat162float(h[2]));
    h[3] = __float2bfloat16(v.w); l[3] = __float2bfloat16(v.w - __bfloat162float(h[3]));
    *(uint2*)(g_xhi + 4 * i) = *(const uint2*)h;
    *(uint2*)(g_xlo + 4 * i) = *(const uint2*)l;
}

// Transpose + split: W [1024, NC] fp32 -> Wt hi/lo [NC, 1024] bf16
template<int NC, int WHICH>
__global__ void wconvert_kernel(const float* __restrict__ W)
{
    __shared__ float ts[32][33];
    const int n0 = blockIdx.x * 32, k0 = blockIdx.y * 32;
    const int tx = threadIdx.x, ty = threadIdx.y;  // 32x8
    #pragma unroll
    for (int i = 0; i < 32; i += 8)
        ts[ty + i][tx] = W[(size_t)(k0 + ty + i) * NC + n0 + tx];
    __syncthreads();
    __nv_bfloat16* hi = WHICH ? g_woh : g_wqh;
    __nv_bfloat16* lo = WHICH ? g_wol : g_wql;
    #pragma unroll
    for (int i = 0; i < 32; i += 8) {
        const float v = ts[tx][ty + i];
        const __nv_bfloat16 h = __float2bfloat16(v);
        const __nv_bfloat16 l = __float2bfloat16(v - __bfloat162float(h));
        const size_t o = (size_t)(n0 + ty + i) * C_ + k0 + tx;
        hi[o] = h; lo[o] = l;
    }
}

// ---------------------------------------------------------------------------
// HMMA (mma.sync) GEMM: D[128x128] = A[128,1024] * B^T, 3-MMA bf16 split.
// 256 threads = 8 warps (2m x 4n), warp tile 64x32, BK=32, cp.async 3-stage
// pipeline. Smem tiles [128 rows][32 k] bf16, 64B/row, XOR-swizzled 16B
// chunks: chunk' = chunk ^ ((row>>1)&3) -> all ldmatrix 8-row groups hit
// distinct 128B bank groups.
// MODE 0: A=x(hi/lo), B=Wqkv^T -> scatter q/k/v head layout (+bias, q*0.125)
// MODE 1: A=o(hi/lo), B=Wout^T -> Cout (+bias)
// ---------------------------------------------------------------------------
#define TILE_B  8192                 /* 128 rows x 64 B */
#define STAGE_B (4*TILE_B)           /* Ah, Al, Bh, Bl = 32 KB */
#define NSTAGE  3
#define GEMM_SMEM (NSTAGE*STAGE_B)   /* 96 KB */
#define NKSTEP  (C_/32)              /* 32 */

template<int MODE>
__global__ __launch_bounds__(256, 1)
void mma_gemm_kernel(const float* __restrict__ bias, float* __restrict__ Cout)
{
    extern __shared__ char sm[];
    const uint32_t sb = smem_u32(sm);
    const int tid  = threadIdx.x;
    const int wid  = tid >> 5, lane = tid & 31;
    const int n0 = blockIdx.x * 128;
    const int m0 = blockIdx.y * 128;
    const int wr = wid & 1;          // warp m-row (0..1) -> m offset wr*64
    const int wc = wid >> 1;         // warp n-col (0..3) -> n offset wc*32

    const __nv_bfloat16* srcs[4] = {
        MODE ? g_ohi : g_xhi, MODE ? g_olo : g_xlo,
        MODE ? g_woh : g_wqh, MODE ? g_wol : g_wql
    };

    // ---- stage loader: 8 cp.async(16B) per thread ----
    auto load_stage = [&](int kt, int s) {
        const uint32_t stb = sb + (uint32_t)s * STAGE_B;
        #pragma unroll
        for (int lt = 0; lt < 4; ++lt) {
            const __nv_bfloat16* lg = srcs[lt] + (size_t)(lt < 2 ? m0 : n0) * C_ + kt * 32;
            const uint32_t tb = stb + lt * TILE_B;
            #pragma unroll
            for (int half = 0; half < 2; ++half) {
                const int r = half * 64 + (tid >> 2);
                const int c = tid & 3;
                const int sel = (r >> 1) & 3;
                cpasync16(tb + (uint32_t)(r * 64 + ((c ^ sel) << 4)),
                          lg + (size_t)r * C_ + c * 8);
            }
        }
    };

    float acc[4][4][4];
    #pragma unroll
    for (int mt = 0; mt < 4; ++mt)
        #pragma unroll
        for (int nt = 0; nt < 4; ++nt)
            #pragma unroll
            for (int q = 0; q < 4; ++q) acc[mt][nt][q] = 0.f;

    // per-lane ldmatrix address components
    const int rl = lane & 15, hib = lane >> 4;
    const int s4 = (rl >> 1) & 3;
    const uint32_t xo0 = (uint32_t)(((0 + hib) ^ s4) << 4);  // kk=0
    const uint32_t xo1 = (uint32_t)(((2 + hib) ^ s4) << 4);  // kk=1
    const uint32_t aA = (uint32_t)((wr * 64 + rl) * 64);
    const uint32_t aB = (uint32_t)((wc * 32 + rl) * 64);

    load_stage(0, 0);
    asm volatile("cp.async.commit_group;" ::: "memory");
    load_stage(1, 1);
    asm volatile("cp.async.commit_group;" ::: "memory");

    for (int kt = 0; kt < NKSTEP; ++kt) {
        asm volatile("cp.async.wait_group 1;" ::: "memory");
        __syncthreads();
        const uint32_t stb = sb + (uint32_t)(kt % NSTAGE) * STAGE_B;

        #pragma unroll
        for (int kk = 0; kk < 2; ++kk) {
            const uint32_t xo = kk ? xo1 : xo0;
            uint32_t ah[4][4], al[4][4], bh[2][4], bl[2][4];
            #pragma unroll
            for (int mt = 0; mt < 4; ++mt) {
                ldsm4(ah[mt], stb +              aA + mt * 1024u + xo);
                ldsm4(al[mt], stb +   TILE_B   + aA + mt * 1024u + xo);
            }
            #pragma unroll
            for (int p = 0; p < 2; ++p) {
                ldsm4(bh[p], stb + 2 * TILE_B + aB + p * 1024u + xo);
                ldsm4(bl[p], stb + 3 * TILE_B + aB + p * 1024u + xo);
            }
            #pragma unroll
            for (int mt = 0; mt < 4; ++mt) {
                #pragma unroll
                for (int nt = 0; nt < 4; ++nt) {
                    uint32_t bfh[2] = { bh[nt >> 1][nt & 1], bh[nt >> 1][(nt & 1) + 2] };
                    uint32_t bfl[2] = { bl[nt >> 1][nt & 1], bl[nt >> 1][(nt & 1) + 2] };
                    mma16816(acc[mt][nt], ah[mt], bfh);   // Ah*Bh
                    mma16816(acc[mt][nt], ah[mt], bfl);   // Ah*Bl
                    mma16816(acc[mt][nt], al[mt], bfh);   // Al*Bh
                }
            }
        }

        if (kt + 2 < NKSTEP) load_stage(kt + 2, (kt + 2) % NSTAGE);
        asm volatile("cp.async.commit_group;" ::: "memory");  // empty in tail: keeps group count uniform
    }

    // ---- epilogue: bias + (MODE 0) head scatter ----
    const int gr = lane >> 2;        // row within 16-tile (0..7)
    const int gc = (lane & 3) * 2;   // col pair within 8-tile
    #pragma unroll
    for (int mt = 0; mt < 4; ++mt) {
        #pragma unroll
        for (int nt = 0; nt < 4; ++nt) {
            const int nc = n0 + wc * 32 + nt * 8 + gc;
            const float b0 = bias[nc], b1 = bias[nc + 1];
            #pragma unroll
            for (int half = 0; half < 2; ++half) {
                const int r = m0 + wr * 64 + mt * 16 + gr + half * 8;
                const float v0 = acc[mt][nt][half * 2 + 0] + b0;
                const float v1 = acc[mt][nt][half * 2 + 1] + b1;
                if (MODE == 0) {
                    const int which = nc >> 10;      // 0=q 1=k 2=v
                    const int cc = nc & 1023;
                    const int h = cc >> 6, dd = cc & 63;
                    const int b = r >> 11, t = r & 2047;
                    float* dst = (which == 0 ? g_q : which == 1 ? g_k : g_v)
                                 + (((size_t)(b * H_ + h)) * T_ + t) * D_ + dd;
                    const float sc = (which == 0) ? 0.125f : 1.0f;  // fold 1/sqrt(64)
                    *(float2*)dst = make_float2(v0 * sc, v1 * sc);
                } else {
                    *(float2*)(Cout + (size_t)r * C_ + nc) = make_float2(v0, v1);
                }
            }
        }
    }
}

// ---------------------------------------------------------------------------
// Causal flash attention, fp32 SIMT. Emits o as bf16 hi/lo for the HMMA
// out-projection.
// ---------------------------------------------------------------------------
__global__ __launch_bounds__(256)
void flash_kernel()
{
    constexpr int LD = 68;
    extern __shared__ float smf[];
    float* Qt = smf;
    float* Kt = Qt + 64 * LD;
    float* Vs = Kt + 64 * LD;
    float* Ps = Vs + 64 * LD;

    const int tid = threadIdx.x;
    const int tx = tid & 15, ty = tid >> 4;
    const int bh = blockIdx.y;
    const int qb = (int)gridDim.x - 1 - (int)blockIdx.x;
    const int q0 = qb * 64;
    const size_t base = (size_t)bh * T_ * D_;
    const float* Qg = g_q + base;
    const float* Kg = g_k + base;
    const float* Vg = g_v + base;

    const int lr = tid >> 2;
    const int lf = tid & 3;

    {
        const float* src = Qg + (size_t)(q0 + lr) * D_;
        #pragma unroll
        for (int p = 0; p < 4; ++p) {
            const int f4 = (lf + 4 * p) * 4;
            float4 v = *(const float4*)(src + f4);
            Qt[(f4+0)*LD + lr] = v.x;
            Qt[(f4+1)*LD + lr] = v.y;
            Qt[(f4+2)*LD + lr] = v.z;
            Qt[(f4+3)*LD + lr] = v.w;
        }
    }

    float o[4][4];
    float mr[4], ls[4];
    #pragma unroll
    for (int i = 0; i < 4; ++i) {
        mr[i] = -INFINITY; ls[i] = 0.f;
        #pragma unroll
        for (int j = 0; j < 4; ++j) o[i][j] = 0.f;
    }

    for (int kt = 0; kt <= qb; ++kt) {
        const int k0 = kt * 64;
        __syncthreads();
        {
            const float* sK = Kg + (size_t)(k0 + lr) * D_;
            const float* sV = Vg + (size_t)(k0 + lr) * D_;
            #pragma unroll
            for (int p = 0; p < 4; ++p) {
                const int f4 = (lf + 4 * p) * 4;
                float4 kv = *(const float4*)(sK + f4);
                Kt[(f4+0)*LD + lr] = kv.x;
                Kt[(f4+1)*LD + lr] = kv.y;
                Kt[(f4+2)*LD + lr] = kv.z;
                Kt[(f4+3)*LD + lr] = kv.w;
                *(float4*)&Vs[lr * LD + f4] = *(const float4*)(sV + f4);
            }
        }
        __syncthreads();

        float s[4][4];
        #pragma unroll
        for (int i = 0; i < 4; ++i) {
            #pragma unroll
            for (int j = 0; j < 4; ++j) s[i][j] = 0.f;
        }
        #pragma unroll 16
        for (int d = 0; d < 64; ++d) {
            float qa[4], ka[4];
            *(float4*)qa = *(const float4*)&Qt[d * LD + ty * 4];
            *(float4*)ka = *(const float4*)&Kt[d * LD + tx * 4];
            #pragma unroll
            for (int i = 0; i < 4; ++i) {
                #pragma unroll
                for (int j = 0; j < 4; ++j) s[i][j] += qa[i] * ka[j];
            }
        }

        if (kt == qb) {
            #pragma unroll
            for (int i = 0; i < 4; ++i) {
                #pragma unroll
                for (int j = 0; j < 4; ++j)
                    if (tx * 4 + j > ty * 4 + i) s[i][j] = -INFINITY;
            }
        }

        #pragma unroll
        for (int i = 0; i < 4; ++i) {
            float mx = fmaxf(fmaxf(s[i][0], s[i][1]), fmaxf(s[i][2], s[i][3]));
            #pragma unroll
            for (int sh = 8; sh > 0; sh >>= 1)
                mx = fmaxf(mx, __shfl_xor_sync(0xffffffffu, mx, sh));
            const float mnew = fmaxf(mr[i], mx);
            const float corr = __expf(mr[i] - mnew);
            mr[i] = mnew;
            float ps = 0.f;
            #pragma unroll
            for (int j = 0; j < 4; ++j) {
                const float p = __expf(s[i][j] - mnew);
                s[i][j] = p;
                ps += p;
            }
            #pragma unroll
            for (int sh = 8; sh > 0; sh >>= 1)
                ps += __shfl_xor_sync(0xffffffffu, ps, sh);
            ls[i] = ls[i] * corr + ps;
            #pragma unroll
            for (int j = 0; j < 4; ++j) o[i][j] *= corr;
        }

        #pragma unroll
        for (int j = 0; j < 4; ++j) {
            #pragma unroll
            for (int i = 0; i < 4; ++i)
                Ps[(tx * 4 + j) * LD + ty * 4 + i] = s[i][j];
        }
        __syncthreads();

        #pragma unroll 16
        for (int c = 0; c < 64; ++c) {
            float pa[4], va[4];
            *(float4*)pa = *(const float4*)&Ps[c * LD + ty * 4];
            *(float4*)va = *(const float4*)&Vs[c * LD + tx * 4];
            #pragma unroll
            for (int i = 0; i < 4; ++i) {
                #pragma unroll
                for (int j = 0; j < 4; ++j) o[i][j] += pa[i] * va[j];
            }
        }
    }

    // finalize + write as bf16 hi/lo for the HMMA out-projection
    const int b = bh >> 4, h = bh & 15;
    #pragma unroll
    for (int i = 0; i < 4; ++i) {
        const int q = q0 + ty * 4 + i;
        const float inv = 1.f / ls[i];
        const size_t ob = ((size_t)(b * T_ + q)) * C_ + h * D_ + tx * 4;
        __align__(8) __nv_bfloat16 hh[4], ll[4];
        #pragma unroll
        for (int j = 0; j < 4; ++j) {
            const float v = o[i][j] * inv;
            hh[j] = __float2bfloat16(v);
            ll[j] = __float2bfloat16(v - __bfloat162float(hh[j]));
        }
        *(uint2*)(g_ohi + ob) = *(const uint2*)hh;
        *(uint2*)(g_olo + ob) = *(const uint2*)ll;
    }
}

// ---------------------------------------------------------------------------
extern "C" void kernel_launch(void* const* d_in, const int* in_sizes, int n_in,
                              void* d_out, int out_size)
{
    (void)in_sizes; (void)n_in; (void)out_size;
    const float* x     = (const float*)d_in[0];
    const float* W_qkv = (const float*)d_in[1];
    const float* b_qkv = (const float*)d_in[2];
    const float* W_out = (const float*)d_in[3];
    const float* b_out = (const float*)d_in[4];
    float* out = (float*)d_out;

    // 0) fp32 -> bf16 hi/lo conversions (x elementwise, weights transposed)
    xconvert_kernel<<<M_ * C_ / 4 / 256, 256>>>((const float4*)x);
    wconvert_kernel<NQKV, 0><<<dim3(NQKV / 32, C_ / 32), dim3(32, 8)>>>(W_qkv);
    wconvert_kernel<C_,   1><<<dim3(C_   / 32, C_ / 32), dim3(32, 8)>>>(W_out);

    // 1) QKV projection on HMMA (3-MMA bf16 split) + head scatter
    cudaFuncSetAttribute(mma_gemm_kernel<0>, cudaFuncAttributeMaxDynamicSharedMemorySize, GEMM_SMEM);
    cudaFuncSetAttribute(mma_gemm_kernel<1>, cudaFuncAttributeMaxDynamicSharedMemorySize, GEMM_SMEM);
    mma_gemm_kernel<0><<<dim3(NQKV / 128, M_ / 128), 256, GEMM_SMEM>>>(b_qkv, nullptr);

    // 2) causal flash attention (fp32 SIMT), emits o as bf16 hi/lo
    const int fsmem = 4 * 64 * 68 * (int)sizeof(float);
    cudaFuncSetAttribute(flash_kernel, cudaFuncAttributeMaxDynamicSharedMemorySize, fsmem);
    flash_kernel<<<dim3(T_ / 64, B_ * H_), 256, fsmem>>>();

    // 3) output projection on HMMA
    mma_gemm_kernel<1><<<dim3(C_ / 128, M_ / 128), 256, GEMM_SMEM>>>(b_out, out);
}

// round 9
// speedup vs baseline: 2.5667x; 1.7936x over previous
#include <cuda_runtime.h>
#include <cuda_bf16.h>
#include <math.h>
#include <stdint.h>

#define B_ 4
#define T_ 2048
#define C_ 1024
#define H_ 16
#define D_ 64
#define M_ (B_*T_)      /* 8192 */
#define NQKV (3*C_)     /* 3072 */

// ---------------------------------------------------------------------------
// Device-global scratch (allocation-free per harness rules)
// ---------------------------------------------------------------------------
__device__ __align__(16) __nv_bfloat16 g_xhi[(size_t)M_*C_];
__device__ __align__(16) __nv_bfloat16 g_xlo[(size_t)M_*C_];
__device__ __align__(16) __nv_bfloat16 g_wqh[(size_t)NQKV*C_];   // W_qkv^T [3072,1024]
__device__ __align__(16) __nv_bfloat16 g_wql[(size_t)NQKV*C_];
__device__ __align__(16) __nv_bfloat16 g_woh[(size_t)C_*C_];     // W_out^T [1024,1024]
__device__ __align__(16) __nv_bfloat16 g_wol[(size_t)C_*C_];

__device__ __align__(16) __nv_bfloat16 g_qh[(size_t)M_*C_];      // [B,H,T,D] (q*0.125)
__device__ __align__(16) __nv_bfloat16 g_ql[(size_t)M_*C_];
__device__ __align__(16) __nv_bfloat16 g_kh[(size_t)M_*C_];      // [B,H,T,D]
__device__ __align__(16) __nv_bfloat16 g_kl[(size_t)M_*C_];
__device__ __align__(16) __nv_bfloat16 g_vh[(size_t)M_*C_];      // [B,H,D,T] (transposed!)
__device__ __align__(16) __nv_bfloat16 g_vl[(size_t)M_*C_];

__device__ __align__(16) __nv_bfloat16 g_ohi[(size_t)M_*C_];     // attn out hi/lo [B*T, C]
__device__ __align__(16) __nv_bfloat16 g_olo[(size_t)M_*C_];

// ---------------------------------------------------------------------------
// Baseline-PTX helpers (plain sm_103 target: no tcgen05)
// ---------------------------------------------------------------------------
__device__ __forceinline__ uint32_t smem_u32(const void* p) {
    uint32_t a;
    asm("{ .reg .u64 t; cvta.to.shared.u64 t, %1; cvt.u32.u64 %0, t; }" : "=r"(a) : "l"(p));
    return a;
}

__device__ __forceinline__ void cpasync16(uint32_t s, const void* g) {
    asm volatile("cp.async.cg.shared.global [%0], [%1], 16;" :: "r"(s), "l"(g));
}

__device__ __forceinline__ void ldsm4(uint32_t* r, uint32_t addr) {
    asm volatile("ldmatrix.sync.aligned.m8n8.x4.shared.b16 {%0,%1,%2,%3}, [%4];"
                 : "=r"(r[0]), "=r"(r[1]), "=r"(r[2]), "=r"(r[3]) : "r"(addr));
}

__device__ __forceinline__ void mma16816(float* c, const uint32_t* a, const uint32_t* b) {
    asm volatile(
        "mma.sync.aligned.m16n8k16.row.col.f32.bf16.bf16.f32 "
        "{%0,%1,%2,%3}, {%4,%5,%6,%7}, {%8,%9}, {%0,%1,%2,%3};"
        : "+f"(c[0]), "+f"(c[1]), "+f"(c[2]), "+f"(c[3])
        : "r"(a[0]), "r"(a[1]), "r"(a[2]), "r"(a[3]), "r"(b[0]), "r"(b[1]));
}

// fp32 pair -> bf16 hi pair + bf16 lo (residual) pair, packed as b32
__device__ __forceinline__ void split2(float a, float b, uint32_t& h, uint32_t& l) {
    __nv_bfloat162 hh = __floats2bfloat162_rn(a, b);
    __nv_bfloat162 ll = __floats2bfloat162_rn(a - __bfloat162float(hh.x),
                                              b - __bfloat162float(hh.y));
    h = *(uint32_t*)&hh;
    l = *(uint32_t*)&ll;
}

// ---------------------------------------------------------------------------
// Conversion kernels: fp32 -> bf16 hi/lo split
// ---------------------------------------------------------------------------
__global__ void xconvert_kernel(const float4* __restrict__ x)
{
    const size_t i = (size_t)blockIdx.x * blockDim.x + threadIdx.x;  // over M_*C_/4
    float4 v = x[i];
    __align__(8) __nv_bfloat16 h[4], l[4];
    h[0] = __float2bfloat16(v.x); l[0] = __float2bfloat16(v.x - __bfloat162float(h[0]));
    h[1] = __float2bfloat16(v.y); l[1] = __float2bfloat16(v.y - __bfloat162float(h[1]));
    h[2] = __float2bfloat16(v.z); l[2] = __float2bfloat16(v.z - __bfloat162float(h[2]));
    h[3] = __float2bfloat16(v.w); l[3] = __float2bfloat16(v.w - __bfloat162float(h[3]));
    *(uint2*)(g_xhi + 4 * i) = *(const uint2*)h;
    *(uint2*)(g_xlo + 4 * i) = *(const uint2*)l;
}

// Transpose + split: W [1024, NC] fp32 -> Wt hi/lo [NC, 1024] bf16
template<int NC, int WHICH>
__global__ void wconvert_kernel(const float* __restrict__ W)
{
    __shared__ float ts[32][33];
    const int n0 = blockIdx.x * 32, k0 = blockIdx.y * 32;
    const int tx = threadIdx.x, ty = threadIdx.y;  // 32x8
    #pragma unroll
    for (int i = 0; i < 32; i += 8)
        ts[ty + i][tx] = W[(size_t)(k0 + ty + i) * NC + n0 + tx];
    __syncthreads();
    __nv_bfloat16* hi = WHICH ? g_woh : g_wqh;
    __nv_bfloat16* lo = WHICH ? g_wol : g_wql;
    #pragma unroll
    for (int i = 0; i < 32; i += 8) {
        const float v = ts[tx][ty + i];
        const __nv_bfloat16 h = __float2bfloat16(v);
        const __nv_bfloat16 l = __float2bfloat16(v - __bfloat162float(h));
        const size_t o = (size_t)(n0 + ty + i) * C_ + k0 + tx;
        hi[o] = h; lo[o] = l;
    }
}

// ---------------------------------------------------------------------------
// HMMA GEMM (unchanged mainloop from R7): D[128x128] = A[128,1024]*B^T,
// 3-MMA bf16 split, 8 warps, BK=32, cp.async 3-stage pipeline.
// MODE 0 epilogue: +bias, scale q, split to bf16 hi/lo, scatter q/k head
//                  layout [bh][t][d] and v TRANSPOSED [bh][d][t].
// MODE 1 epilogue: +bias -> fp32 Cout.
// ---------------------------------------------------------------------------
#define TILE_B  8192
#define STAGE_B (4*TILE_B)
#define NSTAGE  3
#define GEMM_SMEM (NSTAGE*STAGE_B)
#define NKSTEP  (C_/32)

template<int MODE>
__global__ __launch_bounds__(256, 1)
void mma_gemm_kernel(const float* __restrict__ bias, float* __restrict__ Cout)
{
    extern __shared__ char sm[];
    const uint32_t sb = smem_u32(sm);
    const int tid  = threadIdx.x;
    const int wid  = tid >> 5, lane = tid & 31;
    const int n0 = blockIdx.x * 128;
    const int m0 = blockIdx.y * 128;
    const int wr = wid & 1;
    const int wc = wid >> 1;

    const __nv_bfloat16* srcs[4] = {
        MODE ? g_ohi : g_xhi, MODE ? g_olo : g_xlo,
        MODE ? g_woh : g_wqh, MODE ? g_wol : g_wql
    };

    auto load_stage = [&](int kt, int s) {
        const uint32_t stb = sb + (uint32_t)s * STAGE_B;
        #pragma unroll
        for (int lt = 0; lt < 4; ++lt) {
            const __nv_bfloat16* lg = srcs[lt] + (size_t)(lt < 2 ? m0 : n0) * C_ + kt * 32;
            const uint32_t tb = stb + lt * TILE_B;
            #pragma unroll
            for (int half = 0; half < 2; ++half) {
                const int r = half * 64 + (tid >> 2);
                const int c = tid & 3;
                const int sel = (r >> 1) & 3;
                cpasync16(tb + (uint32_t)(r * 64 + ((c ^ sel) << 4)),
                          lg + (size_t)r * C_ + c * 8);
            }
        }
    };

    float acc[4][4][4];
    #pragma unroll
    for (int mt = 0; mt < 4; ++mt)
        #pragma unroll
        for (int nt = 0; nt < 4; ++nt)
            #pragma unroll
            for (int q = 0; q < 4; ++q) acc[mt][nt][q] = 0.f;

    const int rl = lane & 15, hib = lane >> 4;
    const int s4 = (rl >> 1) & 3;
    const uint32_t xo0 = (uint32_t)(((0 + hib) ^ s4) << 4);
    const uint32_t xo1 = (uint32_t)(((2 + hib) ^ s4) << 4);
    const uint32_t aA = (uint32_t)((wr * 64 + rl) * 64);
    const uint32_t aB = (uint32_t)((wc * 32 + rl) * 64);

    load_stage(0, 0);
    asm volatile("cp.async.commit_group;" ::: "memory");
    load_stage(1, 1);
    asm volatile("cp.async.commit_group;" ::: "memory");

    for (int kt = 0; kt < NKSTEP; ++kt) {
        asm volatile("cp.async.wait_group 1;" ::: "memory");
        __syncthreads();
        const uint32_t stb = sb + (uint32_t)(kt % NSTAGE) * STAGE_B;

        #pragma unroll
        for (int kk = 0; kk < 2; ++kk) {
            const uint32_t xo = kk ? xo1 : xo0;
            uint32_t ah[4][4], al[4][4], bh[2][4], bl[2][4];
            #pragma unroll
            for (int mt = 0; mt < 4; ++mt) {
                ldsm4(ah[mt], stb +              aA + mt * 1024u + xo);
                ldsm4(al[mt], stb +   TILE_B   + aA + mt * 1024u + xo);
            }
            #pragma unroll
            for (int p = 0; p < 2; ++p) {
                ldsm4(bh[p], stb + 2 * TILE_B + aB + p * 1024u + xo);
                ldsm4(bl[p], stb + 3 * TILE_B + aB + p * 1024u + xo);
            }
            #pragma unroll
            for (int mt = 0; mt < 4; ++mt) {
                #pragma unroll
                for (int nt = 0; nt < 4; ++nt) {
                    uint32_t bfh[2] = { bh[nt >> 1][nt & 1], bh[nt >> 1][(nt & 1) + 2] };
                    uint32_t bfl[2] = { bl[nt >> 1][nt & 1], bl[nt >> 1][(nt & 1) + 2] };
                    mma16816(acc[mt][nt], ah[mt], bfh);
                    mma16816(acc[mt][nt], ah[mt], bfl);
                    mma16816(acc[mt][nt], al[mt], bfh);
                }
            }
        }

        if (kt + 2 < NKSTEP) load_stage(kt + 2, (kt + 2) % NSTAGE);
        asm volatile("cp.async.commit_group;" ::: "memory");
    }

    const int gr = lane >> 2;
    const int gc = (lane & 3) * 2;
    #pragma unroll
    for (int mt = 0; mt < 4; ++mt) {
        #pragma unroll
        for (int nt = 0; nt < 4; ++nt) {
            const int nc = n0 + wc * 32 + nt * 8 + gc;
            const float b0 = bias[nc], b1 = bias[nc + 1];
            #pragma unroll
            for (int half = 0; half < 2; ++half) {
                const int r = m0 + wr * 64 + mt * 16 + gr + half * 8;
                const float v0 = acc[mt][nt][half * 2 + 0] + b0;
                const float v1 = acc[mt][nt][half * 2 + 1] + b1;
                if (MODE == 0) {
                    const int which = nc >> 10;      // 0=q 1=k 2=v
                    const int cc = nc & 1023;
                    const int h = cc >> 6, dd = cc & 63;
                    const int b = r >> 11, t = r & 2047;
                    const float sc = (which == 0) ? 0.125f : 1.0f;
                    uint32_t ph, pl;
                    split2(v0 * sc, v1 * sc, ph, pl);
                    if (which == 2) {
                        const size_t vo = (((size_t)(b * H_ + h)) * D_ + dd) * T_ + t;
                        __nv_bfloat162 hh = *(__nv_bfloat162*)&ph;
                        __nv_bfloat162 ll = *(__nv_bfloat162*)&pl;
                        g_vh[vo] = hh.x; g_vh[vo + T_] = hh.y;
                        g_vl[vo] = ll.x; g_vl[vo + T_] = ll.y;
                    } else {
                        const size_t qo = (((size_t)(b * H_ + h)) * T_ + t) * D_ + dd;
                        __nv_bfloat16* dh = which ? g_kh : g_qh;
                        __nv_bfloat16* dl = which ? g_kl : g_ql;
                        *(uint32_t*)(dh + qo) = ph;
                        *(uint32_t*)(dl + qo) = pl;
                    }
                } else {
                    *(float2*)(Cout + (size_t)r * C_ + nc) = make_float2(v0, v1);
                }
            }
        }
    }
}

// ---------------------------------------------------------------------------
// Tensorized causal flash attention (HMMA, 3-MMA bf16 split everywhere).
// Block: 128 q-rows, 8 warps (16 rows each), k-tile 64, 2-stage cp.async.
// Q/K: [bh][t][64] hi/lo; V: [bh][d][t] hi/lo (pre-transposed) -> all
// ldmatrix are non-trans. Smem rows 128B, 16B-chunk XOR swizzle c^(r&7).
// S C-fragments feed P A-fragments directly (pack f32 pairs -> bf16x2).
// ---------------------------------------------------------------------------
#define FL_STAGE 32768
#define FL_SMEM  (2*FL_STAGE)

__global__ __launch_bounds__(256)
void flash_mma_kernel()
{
    extern __shared__ char sm[];
    const uint32_t sb = smem_u32(sm);
    const int tid  = threadIdx.x;
    const int lane = tid & 31, w = tid >> 5;
    const int g = lane >> 2, t4 = lane & 3;
    const int bh = blockIdx.y;
    const int qb = (int)gridDim.x - 1 - (int)blockIdx.x;  // long blocks first
    const int q0 = qb * 128;
    const size_t cb = (size_t)bh * T_ * D_;
    const __nv_bfloat16 *Qh = g_qh + cb, *Ql = g_ql + cb;
    const __nv_bfloat16 *Kh = g_kh + cb, *Kl = g_kl + cb;
    const __nv_bfloat16 *Vh = g_vh + cb, *Vl = g_vl + cb;   // [d][t]

    // ---- stage Q (hi/lo, 128x64) into stage0, read A-fragments ----
    #pragma unroll
    for (int i = 0; i < 4; ++i) {
        const int idx = i * 256 + tid;          // 0..1023
        const int r = idx >> 3, c = idx & 7;
        const uint32_t d = sb + (uint32_t)(r * 128 + ((c ^ (r & 7)) << 4));
        cpasync16(d,         Qh + (size_t)(q0 + r) * D_ + c * 8);
        cpasync16(d + 16384, Ql + (size_t)(q0 + r) * D_ + c * 8);
    }
    asm volatile("cp.async.commit_group;\n\tcp.async.wait_group 0;" ::: "memory");
    __syncthreads();

    uint32_t qfh[4][4], qfl[4][4];
    {
        const int qr = w * 16 + (lane & 7) + (lane & 8);
        const int half = (lane >> 4) & 1;
        #pragma unroll
        for (int s = 0; s < 4; ++s) {
            const int qc = 2 * s + half;
            const uint32_t off = (uint32_t)(qr * 128 + ((qc ^ (qr & 7)) << 4));
            ldsm4(qfh[s], sb + off);
            ldsm4(qfl[s], sb + 16384 + off);
        }
    }
    __syncthreads();   // all warps done with stage0 before KV overwrite

    // ---- KV tile loader: Kh@0 Kl@8K Vh@16K Vl@24K within a 32KB stage ----
    auto load_kv = [&](int kt, int st) {
        const uint32_t stb = sb + (uint32_t)st * FL_STAGE;
        #pragma unroll
        for (int i = 0; i < 2; ++i) {
            const int idx = i * 256 + tid;      // 0..511
            const int r = idx >> 3, c = idx & 7;
            const uint32_t d = stb + (uint32_t)(r * 128 + ((c ^ (r & 7)) << 4));
            const size_t ko = (size_t)(kt * 64 + r) * D_ + c * 8;
            const size_t vo = (size_t)r * T_ + kt * 64 + c * 8;
            cpasync16(d,         Kh + ko);
            cpasync16(d + 8192,  Kl + ko);
            cpasync16(d + 16384, Vh + vo);
            cpasync16(d + 24576, Vl + vo);
        }
    };

    float oacc[8][4];
    #pragma unroll
    for (int dj = 0; dj < 8; ++dj)
        #pragma unroll
        for (int q = 0; q < 4; ++q) oacc[dj][q] = 0.f;
    float mA = -INFINITY, mB = -INFINITY, lA = 0.f, lB = 0.f;

    const int nkt = 2 * qb + 2;
    load_kv(0, 0);
    asm volatile("cp.async.commit_group;" ::: "memory");
    load_kv(1, 1);
    asm volatile("cp.async.commit_group;" ::: "memory");

    const int ktmax_w = (q0 + w * 16 + 15) >> 6;     // last tile this warp needs
    const int rowA = q0 + w * 16 + g, rowB = rowA + 8;

    for (int kt = 0; kt < nkt; ++kt) {
        asm volatile("cp.async.wait_group 1;" ::: "memory");
        __syncthreads();
        const uint32_t stb = sb + (uint32_t)(kt & 1) * FL_STAGE;

        if (kt <= ktmax_w) {
            // ---- S = Q K^T (3-MMA split) ----
            float sc[8][4];
            #pragma unroll
            for (int j = 0; j < 8; ++j) {
                uint32_t kh0[4], kh1[4], kl0[4], kl1[4];
                const int kr = 8 * j + (lane & 7);
                const int c0 = lane >> 3;            // chunk 0..3
                const uint32_t o0 = (uint32_t)(kr * 128 + ((c0 ^ (kr & 7)) << 4));
                const uint32_t o1 = (uint32_t)(kr * 128 + (((c0 + 4) ^ (kr & 7)) << 4));
                ldsm4(kh0, stb + o0);        ldsm4(kh1, stb + o1);
                ldsm4(kl0, stb + 8192 + o0); ldsm4(kl1, stb + 8192 + o1);
                sc[j][0] = sc[j][1] = sc[j][2] = sc[j][3] = 0.f;
                #pragma unroll
                for (int s = 0; s < 4; ++s) {
                    const uint32_t* kh = (s < 2) ? kh0 : kh1;
                    const uint32_t* kl = (s < 2) ? kl0 : kl1;
                    uint32_t bh2[2] = { kh[2 * (s & 1)], kh[2 * (s & 1) + 1] };
                    uint32_t bl2[2] = { kl[2 * (s & 1)], kl[2 * (s & 1) + 1] };
                    mma16816(sc[j], qfh[s], bh2);
                    mma16816(sc[j], qfh[s], bl2);
                    mma16816(sc[j], qfl[s], bh2);
                }
            }

            // ---- causal mask (only near-diagonal tiles) ----
            if (kt * 64 + 63 > q0 + w * 16) {
                #pragma unroll
                for (int j = 0; j < 8; ++j) {
                    const int c = kt * 64 + 8 * j + 2 * t4;
                    if (c     > rowA) sc[j][0] = -INFINITY;
                    if (c + 1 > rowA) sc[j][1] = -INFINITY;
                    if (c     > rowB) sc[j][2] = -INFINITY;
                    if (c + 1 > rowB) sc[j][3] = -INFINITY;
                }
            }

            // ---- online softmax (rows A=g, B=g+8; stats over tid4 group) ----
            float mxA = -INFINITY, mxB = -INFINITY;
            #pragma unroll
            for (int j = 0; j < 8; ++j) {
                mxA = fmaxf(mxA, fmaxf(sc[j][0], sc[j][1]));
                mxB = fmaxf(mxB, fmaxf(sc[j][2], sc[j][3]));
            }
            #pragma unroll
            for (int sh = 1; sh <= 2; sh <<= 1) {
                mxA = fmaxf(mxA, __shfl_xor_sync(0xffffffffu, mxA, sh));
                mxB = fmaxf(mxB, __shfl_xor_sync(0xffffffffu, mxB, sh));
            }
            const float mAn = fmaxf(mA, mxA), mBn = fmaxf(mB, mxB);
            const float cA = __expf(mA - mAn), cB = __expf(mB - mBn);
            mA = mAn; mB = mBn;
            float sA = 0.f, sB = 0.f;
            #pragma unroll
            for (int j = 0; j < 8; ++j) {
                sc[j][0] = __expf(sc[j][0] - mAn);
                sc[j][1] = __expf(sc[j][1] - mAn);
                sc[j][2] = __expf(sc[j][2] - mBn);
                sc[j][3] = __expf(sc[j][3] - mBn);
                sA += sc[j][0] + sc[j][1];
                sB += sc[j][2] + sc[j][3];
            }
            #pragma unroll
            for (int sh = 1; sh <= 2; sh <<= 1) {
                sA += __shfl_xor_sync(0xffffffffu, sA, sh);
                sB += __shfl_xor_sync(0xffffffffu, sB, sh);
            }
            lA = lA * cA + sA;
            lB = lB * cB + sB;
            #pragma unroll
            for (int dj = 0; dj < 8; ++dj) {
                oacc[dj][0] *= cA; oacc[dj][1] *= cA;
                oacc[dj][2] *= cB; oacc[dj][3] *= cB;
            }

            // ---- P fragments straight from S fragments ----
            uint32_t pha[4][4], pla[4][4];
            #pragma unroll
            for (int s = 0; s < 4; ++s) {
                split2(sc[2*s][0],   sc[2*s][1],   pha[s][0], pla[s][0]);
                split2(sc[2*s][2],   sc[2*s][3],   pha[s][1], pla[s][1]);
                split2(sc[2*s+1][0], sc[2*s+1][1], pha[s][2], pla[s][2]);
                split2(sc[2*s+1][2], sc[2*s+1][3], pha[s][3], pla[s][3]);
            }

            // ---- O += P V (3-MMA split); V^T smem rows = d ----
            #pragma unroll
            for (int dj = 0; dj < 8; ++dj) {
                uint32_t vh0[4], vh1[4], vl0[4], vl1[4];
                const int vr = 8 * dj + (lane & 7);
                const int c0 = lane >> 3;
                const uint32_t o0 = (uint32_t)(vr * 128 + ((c0 ^ (vr & 7)) << 4));
                const uint32_t o1 = (uint32_t)(vr * 128 + (((c0 + 4) ^ (vr & 7)) << 4));
                ldsm4(vh0, stb + 16384 + o0);  ldsm4(vh1, stb + 16384 + o1);
                ldsm4(vl0, stb + 24576 + o0);  ldsm4(vl1, stb + 24576 + o1);
                #pragma unroll
                for (int s = 0; s < 4; ++s) {
                    const uint32_t* vh = (s < 2) ? vh0 : vh1;
                    const uint32_t* vl = (s < 2) ? vl0 : vl1;
                    uint32_t bvh[2] = { vh[2 * (s & 1)], vh[2 * (s & 1) + 1] };
                    uint32_t bvl[2] = { vl[2 * (s & 1)], vl[2 * (s & 1) + 1] };
                    mma16816(oacc[dj], pha[s], bvh);
                    mma16816(oacc[dj], pha[s], bvl);
                    mma16816(oacc[dj], pla[s], bvh);
                }
            }
        }

        __syncthreads();
        if (kt + 2 < nkt) load_kv(kt + 2, kt & 1);
        asm volatile("cp.async.commit_group;" ::: "memory");
    }

    // ---- finalize: /l, split bf16 hi/lo, write [B*T, C] ----
    const int b = bh >> 4, h = bh & 15;
    const float iA = 1.f / lA, iB = 1.f / lB;
    const size_t rAo = (size_t)(b * T_ + rowA) * C_ + h * 64 + 2 * t4;
    const size_t rBo = rAo + 8 * (size_t)C_;
    #pragma unroll
    for (int dj = 0; dj < 8; ++dj) {
        uint32_t hA, lA2, hB, lB2;
        split2(oacc[dj][0] * iA, oacc[dj][1] * iA, hA, lA2);
        split2(oacc[dj][2] * iB, oacc[dj][3] * iB, hB, lB2);
        *(uint32_t*)(g_ohi + rAo + 8 * dj) = hA;
        *(uint32_t*)(g_olo + rAo + 8 * dj) = lA2;
        *(uint32_t*)(g_ohi + rBo + 8 * dj) = hB;
        *(uint32_t*)(g_olo + rBo + 8 * dj) = lB2;
    }
}

// ---------------------------------------------------------------------------
extern "C" void kernel_launch(void* const* d_in, const int* in_sizes, int n_in,
                              void* d_out, int out_size)
{
    (void)in_sizes; (void)n_in; (void)out_size;
    const float* x     = (const float*)d_in[0];
    const float* W_qkv = (const float*)d_in[1];
    const float* b_qkv = (const float*)d_in[2];
    const float* W_out = (const float*)d_in[3];
    const float* b_out = (const float*)d_in[4];
    float* out = (float*)d_out;

    // 0) fp32 -> bf16 hi/lo conversions
    xconvert_kernel<<<M_ * C_ / 4 / 256, 256>>>((const float4*)x);
    wconvert_kernel<NQKV, 0><<<dim3(NQKV / 32, C_ / 32), dim3(32, 8)>>>(W_qkv);
    wconvert_kernel<C_,   1><<<dim3(C_   / 32, C_ / 32), dim3(32, 8)>>>(W_out);

    // 1) QKV projection (HMMA 3-split) -> q/k [bh][t][d], v [bh][d][t], bf16 hi/lo
    cudaFuncSetAttribute(mma_gemm_kernel<0>, cudaFuncAttributeMaxDynamicSharedMemorySize, GEMM_SMEM);
    cudaFuncSetAttribute(mma_gemm_kernel<1>, cudaFuncAttributeMaxDynamicSharedMemorySize, GEMM_SMEM);
    mma_gemm_kernel<0><<<dim3(NQKV / 128, M_ / 128), 256, GEMM_SMEM>>>(b_qkv, nullptr);

    // 2) causal flash attention on HMMA
    cudaFuncSetAttribute(flash_mma_kernel, cudaFuncAttributeMaxDynamicSharedMemorySize, FL_SMEM);
    flash_mma_kernel<<<dim3(T_ / 128, B_ * H_), 256, FL_SMEM>>>();

    // 3) output projection (HMMA 3-split)
    mma_gemm_kernel<1><<<dim3(C_ / 128, M_ / 128), 256, GEMM_SMEM>>>(b_out, out);
}

// round 10
// speedup vs baseline: 2.6185x; 1.0202x over previous
#include <cuda_runtime.h>
#include <cuda_bf16.h>
#include <math.h>
#include <stdint.h>

#define B_ 4
#define T_ 2048
#define C_ 1024
#define H_ 16
#define D_ 64
#define M_ (B_*T_)      /* 8192 */
#define NQKV (3*C_)     /* 3072 */

// ---------------------------------------------------------------------------
// Device-global scratch (allocation-free per harness rules)
// ---------------------------------------------------------------------------
__device__ __align__(16) __nv_bfloat16 g_xhi[(size_t)M_*C_];
__device__ __align__(16) __nv_bfloat16 g_xlo[(size_t)M_*C_];
__device__ __align__(16) __nv_bfloat16 g_wqh[(size_t)NQKV*C_];   // W_qkv^T [3072,1024]
__device__ __align__(16) __nv_bfloat16 g_wql[(size_t)NQKV*C_];
__device__ __align__(16) __nv_bfloat16 g_woh[(size_t)C_*C_];     // W_out^T [1024,1024]
__device__ __align__(16) __nv_bfloat16 g_wol[(size_t)C_*C_];

__device__ __align__(16) __nv_bfloat16 g_qh[(size_t)M_*C_];      // [B,H,T,D] (q*0.125)
__device__ __align__(16) __nv_bfloat16 g_ql[(size_t)M_*C_];
__device__ __align__(16) __nv_bfloat16 g_kh[(size_t)M_*C_];      // [B,H,T,D]
__device__ __align__(16) __nv_bfloat16 g_kl[(size_t)M_*C_];
__device__ __align__(16) __nv_bfloat16 g_vh[(size_t)M_*C_];      // [B,H,D,T] (transposed!)
__device__ __align__(16) __nv_bfloat16 g_vl[(size_t)M_*C_];

__device__ __align__(16) __nv_bfloat16 g_ohi[(size_t)M_*C_];     // attn out hi/lo [B*T, C]
__device__ __align__(16) __nv_bfloat16 g_olo[(size_t)M_*C_];

// ---------------------------------------------------------------------------
// Baseline-PTX helpers (plain sm_103 target: no tcgen05)
// ---------------------------------------------------------------------------
__device__ __forceinline__ uint32_t smem_u32(const void* p) {
    uint32_t a;
    asm("{ .reg .u64 t; cvta.to.shared.u64 t, %1; cvt.u32.u64 %0, t; }" : "=r"(a) : "l"(p));
    return a;
}

__device__ __forceinline__ void cpasync16(uint32_t s, const void* g) {
    asm volatile("cp.async.cg.shared.global [%0], [%1], 16;" :: "r"(s), "l"(g));
}

__device__ __forceinline__ void ldsm4(uint32_t* r, uint32_t addr) {
    asm volatile("ldmatrix.sync.aligned.m8n8.x4.shared.b16 {%0,%1,%2,%3}, [%4];"
                 : "=r"(r[0]), "=r"(r[1]), "=r"(r[2]), "=r"(r[3]) : "r"(addr));
}

__device__ __forceinline__ void mma16816(float* c, const uint32_t* a, const uint32_t* b) {
    asm volatile(
        "mma.sync.aligned.m16n8k16.row.col.f32.bf16.bf16.f32 "
        "{%0,%1,%2,%3}, {%4,%5,%6,%7}, {%8,%9}, {%0,%1,%2,%3};"
        : "+f"(c[0]), "+f"(c[1]), "+f"(c[2]), "+f"(c[3])
        : "r"(a[0]), "r"(a[1]), "r"(a[2]), "r"(a[3]), "r"(b[0]), "r"(b[1]));
}

// fp32 pair -> bf16 hi pair + bf16 lo (residual) pair, packed as b32
__device__ __forceinline__ void split2(float a, float b, uint32_t& h, uint32_t& l) {
    __nv_bfloat162 hh = __floats2bfloat162_rn(a, b);
    __nv_bfloat162 ll = __floats2bfloat162_rn(a - __bfloat162float(hh.x),
                                              b - __bfloat162float(hh.y));
    h = *(uint32_t*)&hh;
    l = *(uint32_t*)&ll;
}

// ---------------------------------------------------------------------------
// Conversion kernels: fp32 -> bf16 hi/lo split
// ---------------------------------------------------------------------------
__global__ void xconvert_kernel(const float4* __restrict__ x)
{
    const size_t i = (size_t)blockIdx.x * blockDim.x + threadIdx.x;  // over M_*C_/4
    float4 v = x[i];
    __align__(8) __nv_bfloat16 h[4], l[4];
    h[0] = __float2bfloat16(v.x); l[0] = __float2bfloat16(v.x - __bfloat162float(h[0]));
    h[1] = __float2bfloat16(v.y); l[1] = __float2bfloat16(v.y - __bfloat162float(h[1]));
    h[2] = __float2bfloat16(v.z); l[2] = __float2bfloat16(v.z - __bfloat162float(h[2]));
    h[3] = __float2bfloat16(v.w); l[3] = __float2bfloat16(v.w - __bfloat162float(h[3]));
    *(uint2*)(g_xhi + 4 * i) = *(const uint2*)h;
    *(uint2*)(g_xlo + 4 * i) = *(const uint2*)l;
}

// Transpose + split: W [1024, NC] fp32 -> Wt hi/lo [NC, 1024] bf16
template<int NC, int WHICH>
__global__ void wconvert_kernel(const float* __restrict__ W)
{
    __shared__ float ts[32][33];
    const int n0 = blockIdx.x * 32, k0 = blockIdx.y * 32;
    const int tx = threadIdx.x, ty = threadIdx.y;  // 32x8
    #pragma unroll
    for (int i = 0; i < 32; i += 8)
        ts[ty + i][tx] = W[(size_t)(k0 + ty + i) * NC + n0 + tx];
    __syncthreads();
    __nv_bfloat16* hi = WHICH ? g_woh : g_wqh;
    __nv_bfloat16* lo = WHICH ? g_wol : g_wql;
    #pragma unroll
    for (int i = 0; i < 32; i += 8) {
        const float v = ts[tx][ty + i];
        const __nv_bfloat16 h = __float2bfloat16(v);
        const __nv_bfloat16 l = __float2bfloat16(v - __bfloat162float(h));
        const size_t o = (size_t)(n0 + ty + i) * C_ + k0 + tx;
        hi[o] = h; lo[o] = l;
    }
}

// ---------------------------------------------------------------------------
// HMMA GEMM: D[128x128] = A[128,1024]*B^T, 3-MMA bf16 split, 8 warps,
// BK=32, cp.async 3-stage pipeline. NOW 2 CTAs/SM (192KB smem, regs<=128)
// so the second CTA fills LDSM->HMMA bubbles and sync gaps.
// MODE 0 epilogue: +bias, scale q, split to bf16 hi/lo, scatter q/k head
//                  layout [bh][t][d] and v TRANSPOSED [bh][d][t].
// MODE 1 epilogue: +bias -> fp32 Cout.
// ---------------------------------------------------------------------------
#define TILE_B  8192
#define STAGE_B (4*TILE_B)
#define NSTAGE  3
#define GEMM_SMEM (NSTAGE*STAGE_B)
#define NKSTEP  (C_/32)

template<int MODE>
__global__ __launch_bounds__(256, 2)
void mma_gemm_kernel(const float* __restrict__ bias, float* __restrict__ Cout)
{
    extern __shared__ char sm[];
    const uint32_t sb = smem_u32(sm);
    const int tid  = threadIdx.x;
    const int wid  = tid >> 5, lane = tid & 31;
    const int n0 = blockIdx.x * 128;
    const int m0 = blockIdx.y * 128;
    const int wr = wid & 1;
    const int wc = wid >> 1;

    const __nv_bfloat16* srcs[4] = {
        MODE ? g_ohi : g_xhi, MODE ? g_olo : g_xlo,
        MODE ? g_woh : g_wqh, MODE ? g_wol : g_wql
    };

    auto load_stage = [&](int kt, int s) {
        const uint32_t stb = sb + (uint32_t)s * STAGE_B;
        #pragma unroll
        for (int lt = 0; lt < 4; ++lt) {
            const __nv_bfloat16* lg = srcs[lt] + (size_t)(lt < 2 ? m0 : n0) * C_ + kt * 32;
            const uint32_t tb = stb + lt * TILE_B;
            #pragma unroll
            for (int half = 0; half < 2; ++half) {
                const int r = half * 64 + (tid >> 2);
                const int c = tid & 3;
                const int sel = (r >> 1) & 3;
                cpasync16(tb + (uint32_t)(r * 64 + ((c ^ sel) << 4)),
                          lg + (size_t)r * C_ + c * 8);
            }
        }
    };

    float acc[4][4][4];
    #pragma unroll
    for (int mt = 0; mt < 4; ++mt)
        #pragma unroll
        for (int nt = 0; nt < 4; ++nt)
            #pragma unroll
            for (int q = 0; q < 4; ++q) acc[mt][nt][q] = 0.f;

    const int rl = lane & 15, hib = lane >> 4;
    const int s4 = (rl >> 1) & 3;
    const uint32_t xo0 = (uint32_t)(((0 + hib) ^ s4) << 4);
    const uint32_t xo1 = (uint32_t)(((2 + hib) ^ s4) << 4);
    const uint32_t aA = (uint32_t)((wr * 64 + rl) * 64);
    const uint32_t aB = (uint32_t)((wc * 32 + rl) * 64);

    load_stage(0, 0);
    asm volatile("cp.async.commit_group;" ::: "memory");
    load_stage(1, 1);
    asm volatile("cp.async.commit_group;" ::: "memory");

    for (int kt = 0; kt < NKSTEP; ++kt) {
        asm volatile("cp.async.wait_group 1;" ::: "memory");
        __syncthreads();
        const uint32_t stb = sb + (uint32_t)(kt % NSTAGE) * STAGE_B;

        #pragma unroll
        for (int kk = 0; kk < 2; ++kk) {
            const uint32_t xo = kk ? xo1 : xo0;
            uint32_t ah[4][4], al[4][4], bh[2][4], bl[2][4];
            #pragma unroll
            for (int mt = 0; mt < 4; ++mt) {
                ldsm4(ah[mt], stb +              aA + mt * 1024u + xo);
                ldsm4(al[mt], stb +   TILE_B   + aA + mt * 1024u + xo);
            }
            #pragma unroll
            for (int p = 0; p < 2; ++p) {
                ldsm4(bh[p], stb + 2 * TILE_B + aB + p * 1024u + xo);
                ldsm4(bl[p], stb + 3 * TILE_B + aB + p * 1024u + xo);
            }
            #pragma unroll
            for (int mt = 0; mt < 4; ++mt) {
                #pragma unroll
                for (int nt = 0; nt < 4; ++nt) {
                    uint32_t bfh[2] = { bh[nt >> 1][nt & 1], bh[nt >> 1][(nt & 1) + 2] };
                    uint32_t bfl[2] = { bl[nt >> 1][nt & 1], bl[nt >> 1][(nt & 1) + 2] };
                    mma16816(acc[mt][nt], ah[mt], bfh);
                    mma16816(acc[mt][nt], ah[mt], bfl);
                    mma16816(acc[mt][nt], al[mt], bfh);
                }
            }
        }

        if (kt + 2 < NKSTEP) load_stage(kt + 2, (kt + 2) % NSTAGE);
        asm volatile("cp.async.commit_group;" ::: "memory");
    }

    const int gr = lane >> 2;
    const int gc = (lane & 3) * 2;
    #pragma unroll
    for (int mt = 0; mt < 4; ++mt) {
        #pragma unroll
        for (int nt = 0; nt < 4; ++nt) {
            const int nc = n0 + wc * 32 + nt * 8 + gc;
            const float b0 = bias[nc], b1 = bias[nc + 1];
            #pragma unroll
            for (int half = 0; half < 2; ++half) {
                const int r = m0 + wr * 64 + mt * 16 + gr + half * 8;
                const float v0 = acc[mt][nt][half * 2 + 0] + b0;
                const float v1 = acc[mt][nt][half * 2 + 1] + b1;
                if (MODE == 0) {
                    const int which = nc >> 10;      // 0=q 1=k 2=v
                    const int cc = nc & 1023;
                    const int h = cc >> 6, dd = cc & 63;
                    const int b = r >> 11, t = r & 2047;
                    const float sc = (which == 0) ? 0.125f : 1.0f;
                    uint32_t ph, pl;
                    split2(v0 * sc, v1 * sc, ph, pl);
                    if (which == 2) {
                        const size_t vo = (((size_t)(b * H_ + h)) * D_ + dd) * T_ + t;
                        __nv_bfloat162 hh = *(__nv_bfloat162*)&ph;
                        __nv_bfloat162 ll = *(__nv_bfloat162*)&pl;
                        g_vh[vo] = hh.x; g_vh[vo + T_] = hh.y;
                        g_vl[vo] = ll.x; g_vl[vo + T_] = ll.y;
                    } else {
                        const size_t qo = (((size_t)(b * H_ + h)) * T_ + t) * D_ + dd;
                        __nv_bfloat16* dh = which ? g_kh : g_qh;
                        __nv_bfloat16* dl = which ? g_kl : g_ql;
                        *(uint32_t*)(dh + qo) = ph;
                        *(uint32_t*)(dl + qo) = pl;
                    }
                } else {
                    *(float2*)(Cout + (size_t)r * C_ + nc) = make_float2(v0, v1);
                }
            }
        }
    }
}

// ---------------------------------------------------------------------------
// Tensorized causal flash attention (HMMA, 3-MMA bf16 split everywhere).
// Block: 128 q-rows, 8 warps (16 rows each), k-tile 64, 2-stage cp.async.
// NOW 2 CTAs/SM (128KB smem, regs capped 128): softmax MUFU/FMA phases and
// LDSM->HMMA gaps of one CTA are covered by the other.
// ---------------------------------------------------------------------------
#define FL_STAGE 32768
#define FL_SMEM  (2*FL_STAGE)

__global__ __launch_bounds__(256, 2)
void flash_mma_kernel()
{
    extern __shared__ char sm[];
    const uint32_t sb = smem_u32(sm);
    const int tid  = threadIdx.x;
    const int lane = tid & 31, w = tid >> 5;
    const int g = lane >> 2, t4 = lane & 3;
    const int bh = blockIdx.y;
    const int qb = (int)gridDim.x - 1 - (int)blockIdx.x;  // long blocks first
    const int q0 = qb * 128;
    const size_t cb = (size_t)bh * T_ * D_;
    const __nv_bfloat16 *Qh = g_qh + cb, *Ql = g_ql + cb;
    const __nv_bfloat16 *Kh = g_kh + cb, *Kl = g_kl + cb;
    const __nv_bfloat16 *Vh = g_vh + cb, *Vl = g_vl + cb;   // [d][t]

    // ---- stage Q (hi/lo, 128x64) into stage0, read A-fragments ----
    #pragma unroll
    for (int i = 0; i < 4; ++i) {
        const int idx = i * 256 + tid;          // 0..1023
        const int r = idx >> 3, c = idx & 7;
        const uint32_t d = sb + (uint32_t)(r * 128 + ((c ^ (r & 7)) << 4));
        cpasync16(d,         Qh + (size_t)(q0 + r) * D_ + c * 8);
        cpasync16(d + 16384, Ql + (size_t)(q0 + r) * D_ + c * 8);
    }
    asm volatile("cp.async.commit_group;\n\tcp.async.wait_group 0;" ::: "memory");
    __syncthreads();

    uint32_t qfh[4][4], qfl[4][4];
    {
        const int qr = w * 16 + (lane & 7) + (lane & 8);
        const int half = (lane >> 4) & 1;
        #pragma unroll
        for (int s = 0; s < 4; ++s) {
            const int qc = 2 * s + half;
            const uint32_t off = (uint32_t)(qr * 128 + ((qc ^ (qr & 7)) << 4));
            ldsm4(qfh[s], sb + off);
            ldsm4(qfl[s], sb + 16384 + off);
        }
    }
    __syncthreads();   // all warps done with stage0 before KV overwrite

    // ---- KV tile loader: Kh@0 Kl@8K Vh@16K Vl@24K within a 32KB stage ----
    auto load_kv = [&](int kt, int st) {
        const uint32_t stb = sb + (uint32_t)st * FL_STAGE;
        #pragma unroll
        for (int i = 0; i < 2; ++i) {
            const int idx = i * 256 + tid;      // 0..511
            const int r = idx >> 3, c = idx & 7;
            const uint32_t d = stb + (uint32_t)(r * 128 + ((c ^ (r & 7)) << 4));
            const size_t ko = (size_t)(kt * 64 + r) * D_ + c * 8;
            const size_t vo = (size_t)r * T_ + kt * 64 + c * 8;
            cpasync16(d,         Kh + ko);
            cpasync16(d + 8192,  Kl + ko);
            cpasync16(d + 16384, Vh + vo);
            cpasync16(d + 24576, Vl + vo);
        }
    };

    float oacc[8][4];
    #pragma unroll
    for (int dj = 0; dj < 8; ++dj)
        #pragma unroll
        for (int q = 0; q < 4; ++q) oacc[dj][q] = 0.f;
    float mA = -INFINITY, mB = -INFINITY, lA = 0.f, lB = 0.f;

    const int nkt = 2 * qb + 2;
    load_kv(0, 0);
    asm volatile("cp.async.commit_group;" ::: "memory");
    load_kv(1, 1);
    asm volatile("cp.async.commit_group;" ::: "memory");

    const int ktmax_w = (q0 + w * 16 + 15) >> 6;     // last tile this warp needs
    const int rowA = q0 + w * 16 + g, rowB = rowA + 8;

    for (int kt = 0; kt < nkt; ++kt) {
        asm volatile("cp.async.wait_group 1;" ::: "memory");
        __syncthreads();
        const uint32_t stb = sb + (uint32_t)(kt & 1) * FL_STAGE;

        if (kt <= ktmax_w) {
            // ---- S = Q K^T (3-MMA split) ----
            float sc[8][4];
            #pragma unroll
            for (int j = 0; j < 8; ++j) {
                uint32_t kh0[4], kh1[4], kl0[4], kl1[4];
                const int kr = 8 * j + (lane & 7);
                const int c0 = lane >> 3;            // chunk 0..3
                const uint32_t o0 = (uint32_t)(kr * 128 + ((c0 ^ (kr & 7)) << 4));
                const uint32_t o1 = (uint32_t)(kr * 128 + (((c0 + 4) ^ (kr & 7)) << 4));
                ldsm4(kh0, stb + o0);        ldsm4(kh1, stb + o1);
                ldsm4(kl0, stb + 8192 + o0); ldsm4(kl1, stb + 8192 + o1);
                sc[j][0] = sc[j][1] = sc[j][2] = sc[j][3] = 0.f;
                #pragma unroll
                for (int s = 0; s < 4; ++s) {
                    const uint32_t* kh = (s < 2) ? kh0 : kh1;
                    const uint32_t* kl = (s < 2) ? kl0 : kl1;
                    uint32_t bh2[2] = { kh[2 * (s & 1)], kh[2 * (s & 1) + 1] };
                    uint32_t bl2[2] = { kl[2 * (s & 1)], kl[2 * (s & 1) + 1] };
                    mma16816(sc[j], qfh[s], bh2);
                    mma16816(sc[j], qfh[s], bl2);
                    mma16816(sc[j], qfl[s], bh2);
                }
            }

            // ---- causal mask (only near-diagonal tiles) ----
            if (kt * 64 + 63 > q0 + w * 16) {
                #pragma unroll
                for (int j = 0; j < 8; ++j) {
                    const int c = kt * 64 + 8 * j + 2 * t4;
                    if (c     > rowA) sc[j][0] = -INFINITY;
                    if (c + 1 > rowA) sc[j][1] = -INFINITY;
                    if (c     > rowB) sc[j][2] = -INFINITY;
                    if (c + 1 > rowB) sc[j][3] = -INFINITY;
                }
            }

            // ---- online softmax (rows A=g, B=g+8; stats over tid4 group) ----
            float mxA = -INFINITY, mxB = -INFINITY;
            #pragma unroll
            for (int j = 0; j < 8; ++j) {
                mxA = fmaxf(mxA, fmaxf(sc[j][0], sc[j][1]));
                mxB = fmaxf(mxB, fmaxf(sc[j][2], sc[j][3]));
            }
            #pragma unroll
            for (int sh = 1; sh <= 2; sh <<= 1) {
                mxA = fmaxf(mxA, __shfl_xor_sync(0xffffffffu, mxA, sh));
                mxB = fmaxf(mxB, __shfl_xor_sync(0xffffffffu, mxB, sh));
            }
            const float mAn = fmaxf(mA, mxA), mBn = fmaxf(mB, mxB);
            const float cA = __expf(mA - mAn), cB = __expf(mB - mBn);
            mA = mAn; mB = mBn;
            float sA = 0.f, sB = 0.f;
            #pragma unroll
            for (int j = 0; j < 8; ++j) {
                sc[j][0] = __expf(sc[j][0] - mAn);
                sc[j][1] = __expf(sc[j][1] - mAn);
                sc[j][2] = __expf(sc[j][2] - mBn);
                sc[j][3] = __expf(sc[j][3] - mBn);
                sA += sc[j][0] + sc[j][1];
                sB += sc[j][2] + sc[j][3];
            }
            #pragma unroll
            for (int sh = 1; sh <= 2; sh <<= 1) {
                sA += __shfl_xor_sync(0xffffffffu, sA, sh);
                sB += __shfl_xor_sync(0xffffffffu, sB, sh);
            }
            lA = lA * cA + sA;
            lB = lB * cB + sB;
            #pragma unroll
            for (int dj = 0; dj < 8; ++dj) {
                oacc[dj][0] *= cA; oacc[dj][1] *= cA;
                oacc[dj][2] *= cB; oacc[dj][3] *= cB;
            }

            // ---- P fragments straight from S fragments ----
            uint32_t pha[4][4], pla[4][4];
            #pragma unroll
            for (int s = 0; s < 4; ++s) {
                split2(sc[2*s][0],   sc[2*s][1],   pha[s][0], pla[s][0]);
                split2(sc[2*s][2],   sc[2*s][3],   pha[s][1], pla[s][1]);
                split2(sc[2*s+1][0], sc[2*s+1][1], pha[s][2], pla[s][2]);
                split2(sc[2*s+1][2], sc[2*s+1][3], pha[s][3], pla[s][3]);
            }

            // ---- O += P V (3-MMA split); V^T smem rows = d ----
            #pragma unroll
            for (int dj = 0; dj < 8; ++dj) {
                uint32_t vh0[4], vh1[4], vl0[4], vl1[4];
                const int vr = 8 * dj + (lane & 7);
                const int c0 = lane >> 3;
                const uint32_t o0 = (uint32_t)(vr * 128 + ((c0 ^ (vr & 7)) << 4));
                const uint32_t o1 = (uint32_t)(vr * 128 + (((c0 + 4) ^ (vr & 7)) << 4));
                ldsm4(vh0, stb + 16384 + o0);  ldsm4(vh1, stb + 16384 + o1);
                ldsm4(vl0, stb + 24576 + o0);  ldsm4(vl1, stb + 24576 + o1);
                #pragma unroll
                for (int s = 0; s < 4; ++s) {
                    const uint32_t* vh = (s < 2) ? vh0 : vh1;
                    const uint32_t* vl = (s < 2) ? vl0 : vl1;
                    uint32_t bvh[2] = { vh[2 * (s & 1)], vh[2 * (s & 1) + 1] };
                    uint32_t bvl[2] = { vl[2 * (s & 1)], vl[2 * (s & 1) + 1] };
                    mma16816(oacc[dj], pha[s], bvh);
                    mma16816(oacc[dj], pha[s], bvl);
                    mma16816(oacc[dj], pla[s], bvh);
                }
            }
        }

        __syncthreads();
        if (kt + 2 < nkt) load_kv(kt + 2, kt & 1);
        asm volatile("cp.async.commit_group;" ::: "memory");
    }

    // ---- finalize: /l, split bf16 hi/lo, write [B*T, C] ----
    const int b = bh >> 4, h = bh & 15;
    const float iA = 1.f / lA, iB = 1.f / lB;
    const size_t rAo = (size_t)(b * T_ + rowA) * C_ + h * 64 + 2 * t4;
    const size_t rBo = rAo + 8 * (size_t)C_;
    #pragma unroll
    for (int dj = 0; dj < 8; ++dj) {
        uint32_t hA, lA2, hB, lB2;
        split2(oacc[dj][0] * iA, oacc[dj][1] * iA, hA, lA2);
        split2(oacc[dj][2] * iB, oacc[dj][3] * iB, hB, lB2);
        *(uint32_t*)(g_ohi + rAo + 8 * dj) = hA;
        *(uint32_t*)(g_olo + rAo + 8 * dj) = lA2;
        *(uint32_t*)(g_ohi + rBo + 8 * dj) = hB;
        *(uint32_t*)(g_olo + rBo + 8 * dj) = lB2;
    }
}

// ---------------------------------------------------------------------------
extern "C" void kernel_launch(void* const* d_in, const int* in_sizes, int n_in,
                              void* d_out, int out_size)
{
    (void)in_sizes; (void)n_in; (void)out_size;
    const float* x     = (const float*)d_in[0];
    const float* W_qkv = (const float*)d_in[1];
    const float* b_qkv = (const float*)d_in[2];
    const float* W_out = (const float*)d_in[3];
    const float* b_out = (const float*)d_in[4];
    float* out = (float*)d_out;

    // 0) fp32 -> bf16 hi/lo conversions
    xconvert_kernel<<<M_ * C_ / 4 / 256, 256>>>((const float4*)x);
    wconvert_kernel<NQKV, 0><<<dim3(NQKV / 32, C_ / 32), dim3(32, 8)>>>(W_qkv);
    wconvert_kernel<C_,   1><<<dim3(C_   / 32, C_ / 32), dim3(32, 8)>>>(W_out);

    // 1) QKV projection (HMMA 3-split) -> q/k [bh][t][d], v [bh][d][t], bf16 hi/lo
    cudaFuncSetAttribute(mma_gemm_kernel<0>, cudaFuncAttributeMaxDynamicSharedMemorySize, GEMM_SMEM);
    cudaFuncSetAttribute(mma_gemm_kernel<1>, cudaFuncAttributeMaxDynamicSharedMemorySize, GEMM_SMEM);
    mma_gemm_kernel<0><<<dim3(NQKV / 128, M_ / 128), 256, GEMM_SMEM>>>(b_qkv, nullptr);

    // 2) causal flash attention on HMMA (2 CTAs/SM)
    cudaFuncSetAttribute(flash_mma_kernel, cudaFuncAttributeMaxDynamicSharedMemorySize, FL_SMEM);
    flash_mma_kernel<<<dim3(T_ / 128, B_ * H_), 256, FL_SMEM>>>();

    // 3) output projection (HMMA 3-split)
    mma_gemm_kernel<1><<<dim3(C_ / 128, M_ / 128), 256, GEMM_SMEM>>>(b_out, out);
}

// round 11
// speedup vs baseline: 3.6876x; 1.4083x over previous
#include <cuda_runtime.h>
#include <cuda_fp16.h>
#include <math.h>
#include <stdint.h>

#define B_ 4
#define T_ 2048
#define C_ 1024
#define H_ 16
#define D_ 64
#define M_ (B_*T_)      /* 8192 */
#define NQKV (3*C_)     /* 3072 */

// ---------------------------------------------------------------------------
// Device-global scratch (allocation-free per harness rules)
// ---------------------------------------------------------------------------
__device__ __align__(16) __half g_xhi[(size_t)M_*C_];
__device__ __align__(16) __half g_xlo[(size_t)M_*C_];
__device__ __align__(16) __half g_wq [(size_t)NQKV*C_];   // W_qkv^T [3072,1024] single fp16
__device__ __align__(16) __half g_wo [(size_t)C_*C_];     // W_out^T [1024,1024] single fp16

__device__ __align__(16) __half g_qh[(size_t)M_*C_];      // [B,H,T,D] hi (q*0.125)
__device__ __align__(16) __half g_ql[(size_t)M_*C_];      // [B,H,T,D] lo
__device__ __align__(16) __half g_k [(size_t)M_*C_];      // [B,H,T,D] single
__device__ __align__(16) __half g_v [(size_t)M_*C_];      // [B,H,D,T] single (transposed!)

__device__ __align__(16) __half g_ohi[(size_t)M_*C_];     // attn out hi/lo [B*T, C]
__device__ __align__(16) __half g_olo[(size_t)M_*C_];

// ---------------------------------------------------------------------------
// Baseline-PTX helpers (plain sm_103 target: no tcgen05)
// ---------------------------------------------------------------------------
__device__ __forceinline__ uint32_t smem_u32(const void* p) {
    uint32_t a;
    asm("{ .reg .u64 t; cvta.to.shared.u64 t, %1; cvt.u32.u64 %0, t; }" : "=r"(a) : "l"(p));
    return a;
}

__device__ __forceinline__ void cpasync16(uint32_t s, const void* g) {
    asm volatile("cp.async.cg.shared.global [%0], [%1], 16;" :: "r"(s), "l"(g));
}

__device__ __forceinline__ void ldsm4(uint32_t* r, uint32_t addr) {
    asm volatile("ldmatrix.sync.aligned.m8n8.x4.shared.b16 {%0,%1,%2,%3}, [%4];"
                 : "=r"(r[0]), "=r"(r[1]), "=r"(r[2]), "=r"(r[3]) : "r"(addr));
}

// fp16 MMA, fp32 accumulate
__device__ __forceinline__ void mma16816(float* c, const uint32_t* a, const uint32_t* b) {
    asm volatile(
        "mma.sync.aligned.m16n8k16.row.col.f32.f16.f16.f32 "
        "{%0,%1,%2,%3}, {%4,%5,%6,%7}, {%8,%9}, {%0,%1,%2,%3};"
        : "+f"(c[0]), "+f"(c[1]), "+f"(c[2]), "+f"(c[3])
        : "r"(a[0]), "r"(a[1]), "r"(a[2]), "r"(a[3]), "r"(b[0]), "r"(b[1]));
}

// fp32 pair -> fp16 hi pair + fp16 lo (residual) pair, packed as b32
__device__ __forceinline__ void split2h(float a, float b, uint32_t& h, uint32_t& l) {
    __half2 hh = __floats2half2_rn(a, b);
    float2 hf = __half22float2(hh);
    __half2 ll = __floats2half2_rn(a - hf.x, b - hf.y);
    h = *(uint32_t*)&hh;
    l = *(uint32_t*)&ll;
}

// ---------------------------------------------------------------------------
// Conversion kernels
// ---------------------------------------------------------------------------
__global__ void xconvert_kernel(const float4* __restrict__ x)
{
    const size_t i = (size_t)blockIdx.x * blockDim.x + threadIdx.x;  // over M_*C_/4
    float4 v = x[i];
    uint32_t h0, l0, h1, l1;
    split2h(v.x, v.y, h0, l0);
    split2h(v.z, v.w, h1, l1);
    *(uint2*)(g_xhi + 4 * i) = make_uint2(h0, h1);
    *(uint2*)(g_xlo + 4 * i) = make_uint2(l0, l1);
}

// Transpose: W [1024, NC] fp32 -> Wt [NC, 1024] single fp16
template<int NC, int WHICH>
__global__ void wconvert_kernel(const float* __restrict__ W)
{
    __shared__ float ts[32][33];
    const int n0 = blockIdx.x * 32, k0 = blockIdx.y * 32;
    const int tx = threadIdx.x, ty = threadIdx.y;  // 32x8
    #pragma unroll
    for (int i = 0; i < 32; i += 8)
        ts[ty + i][tx] = W[(size_t)(k0 + ty + i) * NC + n0 + tx];
    __syncthreads();
    __half* dst = WHICH ? g_wo : g_wq;
    #pragma unroll
    for (int i = 0; i < 32; i += 8)
        dst[(size_t)(n0 + ty + i) * C_ + k0 + tx] = __float2half_rn(ts[tx][ty + i]);
}

// ---------------------------------------------------------------------------
// HMMA GEMM: D[128x128] = A[128,1024]*B^T, 2-MMA fp16 split (A hi/lo, B single).
// 8 warps (2m x 4n), warp tile 64x32, BK=32, cp.async 3-stage pipeline.
// Stage = Ah(8K) + Al(8K) + B(8K) = 24KB; 3 stages = 72KB -> 2+ CTAs/SM.
// MODE 0 epilogue: +bias, scale q, scatter q hi/lo + k single ([bh][t][d])
//                  and v single TRANSPOSED ([bh][d][t]).
// MODE 1 epilogue: +bias -> fp32 Cout.
// ---------------------------------------------------------------------------
#define TILE_B  8192
#define STAGE_B (3*TILE_B)
#define NSTAGE  3
#define GEMM_SMEM (NSTAGE*STAGE_B)   /* 73728 */
#define NKSTEP  (C_/32)

template<int MODE>
__global__ __launch_bounds__(256, 2)
void mma_gemm_kernel(const float* __restrict__ bias, float* __restrict__ Cout)
{
    extern __shared__ char sm[];
    const uint32_t sb = smem_u32(sm);
    const int tid  = threadIdx.x;
    const int wid  = tid >> 5, lane = tid & 31;
    const int n0 = blockIdx.x * 128;
    const int m0 = blockIdx.y * 128;
    const int wr = wid & 1;
    const int wc = wid >> 1;

    const __half* srcs[3] = {
        MODE ? g_ohi : g_xhi, MODE ? g_olo : g_xlo, MODE ? g_wo : g_wq
    };

    auto load_stage = [&](int kt, int s) {
        const uint32_t stb = sb + (uint32_t)s * STAGE_B;
        #pragma unroll
        for (int lt = 0; lt < 3; ++lt) {
            const __half* lg = srcs[lt] + (size_t)(lt < 2 ? m0 : n0) * C_ + kt * 32;
            const uint32_t tb = stb + lt * TILE_B;
            #pragma unroll
            for (int half_ = 0; half_ < 2; ++half_) {
                const int r = half_ * 64 + (tid >> 2);
                const int c = tid & 3;
                const int sel = (r >> 1) & 3;
                cpasync16(tb + (uint32_t)(r * 64 + ((c ^ sel) << 4)),
                          lg + (size_t)r * C_ + c * 8);
            }
        }
    };

    float acc[4][4][4];
    #pragma unroll
    for (int mt = 0; mt < 4; ++mt)
        #pragma unroll
        for (int nt = 0; nt < 4; ++nt)
            #pragma unroll
            for (int q = 0; q < 4; ++q) acc[mt][nt][q] = 0.f;

    const int rl = lane & 15, hib = lane >> 4;
    const int s4 = (rl >> 1) & 3;
    const uint32_t xo0 = (uint32_t)(((0 + hib) ^ s4) << 4);
    const uint32_t xo1 = (uint32_t)(((2 + hib) ^ s4) << 4);
    const uint32_t aA = (uint32_t)((wr * 64 + rl) * 64);
    const uint32_t aB = (uint32_t)((wc * 32 + rl) * 64);

    load_stage(0, 0);
    asm volatile("cp.async.commit_group;" ::: "memory");
    load_stage(1, 1);
    asm volatile("cp.async.commit_group;" ::: "memory");

    for (int kt = 0; kt < NKSTEP; ++kt) {
        asm volatile("cp.async.wait_group 1;" ::: "memory");
        __syncthreads();
        const uint32_t stb = sb + (uint32_t)(kt % NSTAGE) * STAGE_B;

        #pragma unroll
        for (int kk = 0; kk < 2; ++kk) {
            const uint32_t xo = kk ? xo1 : xo0;
            uint32_t ah[4][4], al[4][4], bh[2][4];
            #pragma unroll
            for (int mt = 0; mt < 4; ++mt) {
                ldsm4(ah[mt], stb +            aA + mt * 1024u + xo);
                ldsm4(al[mt], stb + TILE_B   + aA + mt * 1024u + xo);
            }
            #pragma unroll
            for (int p = 0; p < 2; ++p)
                ldsm4(bh[p], stb + 2 * TILE_B + aB + p * 1024u + xo);
            #pragma unroll
            for (int mt = 0; mt < 4; ++mt) {
                #pragma unroll
                for (int nt = 0; nt < 4; ++nt) {
                    uint32_t bf[2] = { bh[nt >> 1][nt & 1], bh[nt >> 1][(nt & 1) + 2] };
                    mma16816(acc[mt][nt], ah[mt], bf);
                    mma16816(acc[mt][nt], al[mt], bf);
                }
            }
        }

        if (kt + 2 < NKSTEP) load_stage(kt + 2, (kt + 2) % NSTAGE);
        asm volatile("cp.async.commit_group;" ::: "memory");
    }

    const int gr = lane >> 2;
    const int gc = (lane & 3) * 2;
    #pragma unroll
    for (int mt = 0; mt < 4; ++mt) {
        #pragma unroll
        for (int nt = 0; nt < 4; ++nt) {
            const int nc = n0 + wc * 32 + nt * 8 + gc;
            const float b0 = bias[nc], b1 = bias[nc + 1];
            #pragma unroll
            for (int half_ = 0; half_ < 2; ++half_) {
                const int r = m0 + wr * 64 + mt * 16 + gr + half_ * 8;
                const float v0 = acc[mt][nt][half_ * 2 + 0] + b0;
                const float v1 = acc[mt][nt][half_ * 2 + 1] + b1;
                if (MODE == 0) {
                    const int which = nc >> 10;      // 0=q 1=k 2=v
                    const int cc = nc & 1023;
                    const int h = cc >> 6, dd = cc & 63;
                    const int b = r >> 11, t = r & 2047;
                    if (which == 0) {
                        // q: fold 1/sqrt(64)=0.125, split fp16 hi/lo
                        uint32_t ph, pl;
                        split2h(v0 * 0.125f, v1 * 0.125f, ph, pl);
                        const size_t qo = (((size_t)(b * H_ + h)) * T_ + t) * D_ + dd;
                        *(uint32_t*)(g_qh + qo) = ph;
                        *(uint32_t*)(g_ql + qo) = pl;
                    } else if (which == 1) {
                        __half2 kk2 = __floats2half2_rn(v0, v1);
                        const size_t qo = (((size_t)(b * H_ + h)) * T_ + t) * D_ + dd;
                        *(__half2*)(g_k + qo) = kk2;
                    } else {
                        const size_t vo = (((size_t)(b * H_ + h)) * D_ + dd) * T_ + t;
                        g_v[vo]      = __float2half_rn(v0);
                        g_v[vo + T_] = __float2half_rn(v1);
                    }
                } else {
                    *(float2*)(Cout + (size_t)r * C_ + nc) = make_float2(v0, v1);
                }
            }
        }
    }
}

// ---------------------------------------------------------------------------
// Tensorized causal flash attention, 2-MMA fp16 split.
// S = (Qh+Ql)·K^T (K single, 2 MMAs); O += (Ph+Pl)·V (V single, 2 MMAs).
// Block: 128 q-rows, 8 warps, k-tile 64, 2-stage cp.async (16KB/stage).
// V pre-transposed [bh][d][t] -> all ldmatrix non-trans.
// ---------------------------------------------------------------------------
#define FL_STAGE 16384
#define FL_SMEM  32768

__global__ __launch_bounds__(256, 2)
void flash_mma_kernel()
{
    extern __shared__ char sm[];
    const uint32_t sb = smem_u32(sm);
    const int tid  = threadIdx.x;
    const int lane = tid & 31, w = tid >> 5;
    const int g = lane >> 2, t4 = lane & 3;
    const int bh = blockIdx.y;
    const int qb = (int)gridDim.x - 1 - (int)blockIdx.x;  // long blocks first
    const int q0 = qb * 128;
    const size_t cb = (size_t)bh * T_ * D_;
    const __half *Qh = g_qh + cb, *Ql = g_ql + cb;
    const __half *Kg = g_k + cb;
    const __half *Vg = g_v + cb;   // [d][t]

    // ---- stage Q (hi at 0, lo at 16K), read A-fragments ----
    #pragma unroll
    for (int i = 0; i < 4; ++i) {
        const int idx = i * 256 + tid;          // 0..1023
        const int r = idx >> 3, c = idx & 7;
        const uint32_t d = sb + (uint32_t)(r * 128 + ((c ^ (r & 7)) << 4));
        cpasync16(d,         Qh + (size_t)(q0 + r) * D_ + c * 8);
        cpasync16(d + 16384, Ql + (size_t)(q0 + r) * D_ + c * 8);
    }
    asm volatile("cp.async.commit_group;\n\tcp.async.wait_group 0;" ::: "memory");
    __syncthreads();

    uint32_t qfh[4][4], qfl[4][4];
    {
        const int qr = w * 16 + (lane & 7) + (lane & 8);
        const int half_ = (lane >> 4) & 1;
        #pragma unroll
        for (int s = 0; s < 4; ++s) {
            const int qc = 2 * s + half_;
            const uint32_t off = (uint32_t)(qr * 128 + ((qc ^ (qr & 7)) << 4));
            ldsm4(qfh[s], sb + off);
            ldsm4(qfl[s], sb + 16384 + off);
        }
    }
    __syncthreads();   // all warps done with Q staging before KV overwrite

    // ---- KV tile loader: K@0 (8K), V@8K (8K) within a 16KB stage ----
    auto load_kv = [&](int kt, int st) {
        const uint32_t stb = sb + (uint32_t)st * FL_STAGE;
        #pragma unroll
        for (int i = 0; i < 2; ++i) {
            const int idx = i * 256 + tid;      // 0..511
            const int r = idx >> 3, c = idx & 7;
            const uint32_t d = stb + (uint32_t)(r * 128 + ((c ^ (r & 7)) << 4));
            cpasync16(d,        Kg + (size_t)(kt * 64 + r) * D_ + c * 8);
            cpasync16(d + 8192, Vg + (size_t)r * T_ + kt * 64 + c * 8);
        }
    };

    float oacc[8][4];
    #pragma unroll
    for (int dj = 0; dj < 8; ++dj)
        #pragma unroll
        for (int q = 0; q < 4; ++q) oacc[dj][q] = 0.f;
    float mA = -INFINITY, mB = -INFINITY, lA = 0.f, lB = 0.f;

    const int nkt = 2 * qb + 2;
    load_kv(0, 0);
    asm volatile("cp.async.commit_group;" ::: "memory");
    load_kv(1, 1);
    asm volatile("cp.async.commit_group;" ::: "memory");

    const int ktmax_w = (q0 + w * 16 + 15) >> 6;     // last tile this warp needs
    const int rowA = q0 + w * 16 + g, rowB = rowA + 8;

    for (int kt = 0; kt < nkt; ++kt) {
        asm volatile("cp.async.wait_group 1;" ::: "memory");
        __syncthreads();
        const uint32_t stb = sb + (uint32_t)(kt & 1) * FL_STAGE;

        if (kt <= ktmax_w) {
            // ---- S = Q K^T (2-MMA split) ----
            float sc[8][4];
            #pragma unroll
            for (int j = 0; j < 8; ++j) {
                uint32_t kf0[4], kf1[4];
                const int kr = 8 * j + (lane & 7);
                const int c0 = lane >> 3;            // chunk 0..3
                const uint32_t o0 = (uint32_t)(kr * 128 + ((c0 ^ (kr & 7)) << 4));
                const uint32_t o1 = (uint32_t)(kr * 128 + (((c0 + 4) ^ (kr & 7)) << 4));
                ldsm4(kf0, stb + o0);
                ldsm4(kf1, stb + o1);
                sc[j][0] = sc[j][1] = sc[j][2] = sc[j][3] = 0.f;
                #pragma unroll
                for (int s = 0; s < 4; ++s) {
                    const uint32_t* kf = (s < 2) ? kf0 : kf1;
                    uint32_t bf[2] = { kf[2 * (s & 1)], kf[2 * (s & 1) + 1] };
                    mma16816(sc[j], qfh[s], bf);
                    mma16816(sc[j], qfl[s], bf);
                }
            }

            // ---- causal mask (only near-diagonal tiles) ----
            if (kt * 64 + 63 > q0 + w * 16) {
                #pragma unroll
                for (int j = 0; j < 8; ++j) {
                    const int c = kt * 64 + 8 * j + 2 * t4;
                    if (c     > rowA) sc[j][0] = -INFINITY;
                    if (c + 1 > rowA) sc[j][1] = -INFINITY;
                    if (c     > rowB) sc[j][2] = -INFINITY;
                    if (c + 1 > rowB) sc[j][3] = -INFINITY;
                }
            }

            // ---- online softmax (rows A=g, B=g+8; stats over tid4 group) ----
            float mxA = -INFINITY, mxB = -INFINITY;
            #pragma unroll
            for (int j = 0; j < 8; ++j) {
                mxA = fmaxf(mxA, fmaxf(sc[j][0], sc[j][1]));
                mxB = fmaxf(mxB, fmaxf(sc[j][2], sc[j][3]));
            }
            #pragma unroll
            for (int sh = 1; sh <= 2; sh <<= 1) {
                mxA = fmaxf(mxA, __shfl_xor_sync(0xffffffffu, mxA, sh));
                mxB = fmaxf(mxB, __shfl_xor_sync(0xffffffffu, mxB, sh));
            }
            const float mAn = fmaxf(mA, mxA), mBn = fmaxf(mB, mxB);
            const float cA = __expf(mA - mAn), cB = __expf(mB - mBn);
            mA = mAn; mB = mBn;
            float sA = 0.f, sB = 0.f;
            #pragma unroll
            for (int j = 0; j < 8; ++j) {
                sc[j][0] = __expf(sc[j][0] - mAn);
                sc[j][1] = __expf(sc[j][1] - mAn);
                sc[j][2] = __expf(sc[j][2] - mBn);
                sc[j][3] = __expf(sc[j][3] - mBn);
                sA += sc[j][0] + sc[j][1];
                sB += sc[j][2] + sc[j][3];
            }
            #pragma unroll
            for (int sh = 1; sh <= 2; sh <<= 1) {
                sA += __shfl_xor_sync(0xffffffffu, sA, sh);
                sB += __shfl_xor_sync(0xffffffffu, sB, sh);
            }
            lA = lA * cA + sA;
            lB = lB * cB + sB;
            #pragma unroll
            for (int dj = 0; dj < 8; ++dj) {
                oacc[dj][0] *= cA; oacc[dj][1] *= cA;
                oacc[dj][2] *= cB; oacc[dj][3] *= cB;
            }

            // ---- P fragments straight from S fragments (fp16 hi/lo) ----
            uint32_t pha[4][4], pla[4][4];
            #pragma unroll
            for (int s = 0; s < 4; ++s) {
                split2h(sc[2*s][0],   sc[2*s][1],   pha[s][0], pla[s][0]);
                split2h(sc[2*s][2],   sc[2*s][3],   pha[s][1], pla[s][1]);
                split2h(sc[2*s+1][0], sc[2*s+1][1], pha[s][2], pla[s][2]);
                split2h(sc[2*s+1][2], sc[2*s+1][3], pha[s][3], pla[s][3]);
            }

            // ---- O += P V (2-MMA split); V^T smem rows = d ----
            #pragma unroll
            for (int dj = 0; dj < 8; ++dj) {
                uint32_t vf0[4], vf1[4];
                const int vr = 8 * dj + (lane & 7);
                const int c0 = lane >> 3;
                const uint32_t o0 = (uint32_t)(vr * 128 + ((c0 ^ (vr & 7)) << 4));
                const uint32_t o1 = (uint32_t)(vr * 128 + (((c0 + 4) ^ (vr & 7)) << 4));
                ldsm4(vf0, stb + 8192 + o0);
                ldsm4(vf1, stb + 8192 + o1);
                #pragma unroll
                for (int s = 0; s < 4; ++s) {
                    const uint32_t* vf = (s < 2) ? vf0 : vf1;
                    uint32_t bf[2] = { vf[2 * (s & 1)], vf[2 * (s & 1) + 1] };
                    mma16816(oacc[dj], pha[s], bf);
                    mma16816(oacc[dj], pla[s], bf);
                }
            }
        }

        __syncthreads();
        if (kt + 2 < nkt) load_kv(kt + 2, kt & 1);
        asm volatile("cp.async.commit_group;" ::: "memory");
    }

    // ---- finalize: /l, split fp16 hi/lo, write [B*T, C] ----
    const int b = bh >> 4, h = bh & 15;
    const float iA = 1.f / lA, iB = 1.f / lB;
    const size_t rAo = (size_t)(b * T_ + rowA) * C_ + h * 64 + 2 * t4;
    const size_t rBo = rAo + 8 * (size_t)C_;
    #pragma unroll
    for (int dj = 0; dj < 8; ++dj) {
        uint32_t hA, lA2, hB, lB2;
        split2h(oacc[dj][0] * iA, oacc[dj][1] * iA, hA, lA2);
        split2h(oacc[dj][2] * iB, oacc[dj][3] * iB, hB, lB2);
        *(uint32_t*)(g_ohi + rAo + 8 * dj) = hA;
        *(uint32_t*)(g_olo + rAo + 8 * dj) = lA2;
        *(uint32_t*)(g_ohi + rBo + 8 * dj) = hB;
        *(uint32_t*)(g_olo + rBo + 8 * dj) = lB2;
    }
}

// ---------------------------------------------------------------------------
extern "C" void kernel_launch(void* const* d_in, const int* in_sizes, int n_in,
                              void* d_out, int out_size)
{
    (void)in_sizes; (void)n_in; (void)out_size;
    const float* x     = (const float*)d_in[0];
    const float* W_qkv = (const float*)d_in[1];
    const float* b_qkv = (const float*)d_in[2];
    const float* W_out = (const float*)d_in[3];
    const float* b_out = (const float*)d_in[4];
    float* out = (float*)d_out;

    // 0) fp32 -> fp16 conversions (x hi/lo split; weights single, transposed)
    xconvert_kernel<<<M_ * C_ / 4 / 256, 256>>>((const float4*)x);
    wconvert_kernel<NQKV, 0><<<dim3(NQKV / 32, C_ / 32), dim3(32, 8)>>>(W_qkv);
    wconvert_kernel<C_,   1><<<dim3(C_   / 32, C_ / 32), dim3(32, 8)>>>(W_out);

    // 1) QKV projection (2-MMA fp16) -> q hi/lo, k, v^T
    cudaFuncSetAttribute(mma_gemm_kernel<0>, cudaFuncAttributeMaxDynamicSharedMemorySize, GEMM_SMEM);
    cudaFuncSetAttribute(mma_gemm_kernel<1>, cudaFuncAttributeMaxDynamicSharedMemorySize, GEMM_SMEM);
    mma_gemm_kernel<0><<<dim3(NQKV / 128, M_ / 128), 256, GEMM_SMEM>>>(b_qkv, nullptr);

    // 2) causal flash attention (2-MMA fp16)
    cudaFuncSetAttribute(flash_mma_kernel, cudaFuncAttributeMaxDynamicSharedMemorySize, FL_SMEM);
    flash_mma_kernel<<<dim3(T_ / 128, B_ * H_), 256, FL_SMEM>>>();

    // 3) output projection (2-MMA fp16)
    mma_gemm_kernel<1><<<dim3(C_ / 128, M_ / 128), 256, GEMM_SMEM>>>(b_out, out);
}

// round 12
// speedup vs baseline: 6.4406x; 1.7465x over previous
#include <cuda_runtime.h>
#include <cuda_fp16.h>
#include <math.h>
#include <stdint.h>

#define B_ 4
#define T_ 2048
#define C_ 1024
#define H_ 16
#define D_ 64
#define M_ (B_*T_)      /* 8192 */
#define NQKV (3*C_)     /* 3072 */

// ---------------------------------------------------------------------------
// Device-global scratch (allocation-free per harness rules)
// ---------------------------------------------------------------------------
__device__ __align__(16) __half g_x [(size_t)M_*C_];      // x fp16
__device__ __align__(16) __half g_wq[(size_t)NQKV*C_];    // W_qkv^T [3072,1024]
__device__ __align__(16) __half g_wo[(size_t)C_*C_];      // W_out^T [1024,1024]

__device__ __align__(16) __half g_q [(size_t)M_*C_];      // [B,H,T,D] (q*0.125)
__device__ __align__(16) __half g_k [(size_t)M_*C_];      // [B,H,T,D]
__device__ __align__(16) __half g_v [(size_t)M_*C_];      // [B,H,D,T] (transposed!)

__device__ __align__(16) __half g_o [(size_t)M_*C_];      // attn out [B*T, C]

// ---------------------------------------------------------------------------
// Baseline-PTX helpers (plain sm_103 target: no tcgen05)
// ---------------------------------------------------------------------------
__device__ __forceinline__ uint32_t smem_u32(const void* p) {
    uint32_t a;
    asm("{ .reg .u64 t; cvta.to.shared.u64 t, %1; cvt.u32.u64 %0, t; }" : "=r"(a) : "l"(p));
    return a;
}

__device__ __forceinline__ void cpasync16(uint32_t s, const void* g) {
    asm volatile("cp.async.cg.shared.global [%0], [%1], 16;" :: "r"(s), "l"(g));
}

__device__ __forceinline__ void ldsm4(uint32_t* r, uint32_t addr) {
    asm volatile("ldmatrix.sync.aligned.m8n8.x4.shared.b16 {%0,%1,%2,%3}, [%4];"
                 : "=r"(r[0]), "=r"(r[1]), "=r"(r[2]), "=r"(r[3]) : "r"(addr));
}

// fp16 MMA, fp32 accumulate
__device__ __forceinline__ void mma16816(float* c, const uint32_t* a, const uint32_t* b) {
    asm volatile(
        "mma.sync.aligned.m16n8k16.row.col.f32.f16.f16.f32 "
        "{%0,%1,%2,%3}, {%4,%5,%6,%7}, {%8,%9}, {%0,%1,%2,%3};"
        : "+f"(c[0]), "+f"(c[1]), "+f"(c[2]), "+f"(c[3])
        : "r"(a[0]), "r"(a[1]), "r"(a[2]), "r"(a[3]), "r"(b[0]), "r"(b[1]));
}

__device__ __forceinline__ uint32_t pack2h(float a, float b) {
    __half2 hh = __floats2half2_rn(a, b);
    return *(uint32_t*)&hh;
}

// ---------------------------------------------------------------------------
// Conversion kernels (fp32 -> single fp16)
// ---------------------------------------------------------------------------
__global__ void xconvert_kernel(const float4* __restrict__ x)
{
    const size_t i = (size_t)blockIdx.x * blockDim.x + threadIdx.x;  // over M_*C_/4
    float4 v = x[i];
    *(uint2*)(g_x + 4 * i) = make_uint2(pack2h(v.x, v.y), pack2h(v.z, v.w));
}

// Transpose: W [1024, NC] fp32 -> Wt [NC, 1024] fp16
template<int NC, int WHICH>
__global__ void wconvert_kernel(const float* __restrict__ W)
{
    __shared__ float ts[32][33];
    const int n0 = blockIdx.x * 32, k0 = blockIdx.y * 32;
    const int tx = threadIdx.x, ty = threadIdx.y;  // 32x8
    #pragma unroll
    for (int i = 0; i < 32; i += 8)
        ts[ty + i][tx] = W[(size_t)(k0 + ty + i) * NC + n0 + tx];
    __syncthreads();
    __half* dst = WHICH ? g_wo : g_wq;
    #pragma unroll
    for (int i = 0; i < 32; i += 8)
        dst[(size_t)(n0 + ty + i) * C_ + k0 + tx] = __float2half_rn(ts[tx][ty + i]);
}

// ---------------------------------------------------------------------------
// HMMA GEMM: D[128x128] = A[128,1024]*B^T, single fp16 (1 MMA per product).
// 8 warps (2m x 4n), warp tile 64x32, BK=32, cp.async 3-stage pipeline.
// Stage = A(8K) + B(8K) = 16KB; 3 stages = 48KB.
// MODE 0 epilogue: +bias, scale q, scatter q/k ([bh][t][d]) and v TRANSPOSED
//                  ([bh][d][t]), all single fp16.
// MODE 1 epilogue: +bias -> fp32 Cout.
// ---------------------------------------------------------------------------
#define TILE_B  8192
#define STAGE_B (2*TILE_B)
#define NSTAGE  3
#define GEMM_SMEM (NSTAGE*STAGE_B)   /* 49152 */
#define NKSTEP  (C_/32)

template<int MODE>
__global__ __launch_bounds__(256, 2)
void mma_gemm_kernel(const float* __restrict__ bias, float* __restrict__ Cout)
{
    extern __shared__ char sm[];
    const uint32_t sb = smem_u32(sm);
    const int tid  = threadIdx.x;
    const int wid  = tid >> 5, lane = tid & 31;
    const int n0 = blockIdx.x * 128;
    const int m0 = blockIdx.y * 128;
    const int wr = wid & 1;
    const int wc = wid >> 1;

    const __half* srcA = MODE ? g_o  : g_x;
    const __half* srcB = MODE ? g_wo : g_wq;

    auto load_stage = [&](int kt, int s) {
        const uint32_t stb = sb + (uint32_t)s * STAGE_B;
        #pragma unroll
        for (int lt = 0; lt < 2; ++lt) {
            const __half* lg = (lt == 0 ? srcA + (size_t)m0 * C_
                                        : srcB + (size_t)n0 * C_) + kt * 32;
            const uint32_t tb = stb + lt * TILE_B;
            #pragma unroll
            for (int half_ = 0; half_ < 2; ++half_) {
                const int r = half_ * 64 + (tid >> 2);
                const int c = tid & 3;
                const int sel = (r >> 1) & 3;
                cpasync16(tb + (uint32_t)(r * 64 + ((c ^ sel) << 4)),
                          lg + (size_t)r * C_ + c * 8);
            }
        }
    };

    float acc[4][4][4];
    #pragma unroll
    for (int mt = 0; mt < 4; ++mt)
        #pragma unroll
        for (int nt = 0; nt < 4; ++nt)
            #pragma unroll
            for (int q = 0; q < 4; ++q) acc[mt][nt][q] = 0.f;

    const int rl = lane & 15, hib = lane >> 4;
    const int s4 = (rl >> 1) & 3;
    const uint32_t xo0 = (uint32_t)(((0 + hib) ^ s4) << 4);
    const uint32_t xo1 = (uint32_t)(((2 + hib) ^ s4) << 4);
    const uint32_t aA = (uint32_t)((wr * 64 + rl) * 64);
    const uint32_t aB = (uint32_t)((wc * 32 + rl) * 64);

    load_stage(0, 0);
    asm volatile("cp.async.commit_group;" ::: "memory");
    load_stage(1, 1);
    asm volatile("cp.async.commit_group;" ::: "memory");

    for (int kt = 0; kt < NKSTEP; ++kt) {
        asm volatile("cp.async.wait_group 1;" ::: "memory");
        __syncthreads();
        const uint32_t stb = sb + (uint32_t)(kt % NSTAGE) * STAGE_B;

        #pragma unroll
        for (int kk = 0; kk < 2; ++kk) {
            const uint32_t xo = kk ? xo1 : xo0;
            uint32_t ah[4][4], bh[2][4];
            #pragma unroll
            for (int mt = 0; mt < 4; ++mt)
                ldsm4(ah[mt], stb + aA + mt * 1024u + xo);
            #pragma unroll
            for (int p = 0; p < 2; ++p)
                ldsm4(bh[p], stb + TILE_B + aB + p * 1024u + xo);
            #pragma unroll
            for (int mt = 0; mt < 4; ++mt) {
                #pragma unroll
                for (int nt = 0; nt < 4; ++nt) {
                    uint32_t bf[2] = { bh[nt >> 1][nt & 1], bh[nt >> 1][(nt & 1) + 2] };
                    mma16816(acc[mt][nt], ah[mt], bf);
                }
            }
        }

        if (kt + 2 < NKSTEP) load_stage(kt + 2, (kt + 2) % NSTAGE);
        asm volatile("cp.async.commit_group;" ::: "memory");
    }

    const int gr = lane >> 2;
    const int gc = (lane & 3) * 2;
    #pragma unroll
    for (int mt = 0; mt < 4; ++mt) {
        #pragma unroll
        for (int nt = 0; nt < 4; ++nt) {
            const int nc = n0 + wc * 32 + nt * 8 + gc;
            const float b0 = bias[nc], b1 = bias[nc + 1];
            #pragma unroll
            for (int half_ = 0; half_ < 2; ++half_) {
                const int r = m0 + wr * 64 + mt * 16 + gr + half_ * 8;
                const float v0 = acc[mt][nt][half_ * 2 + 0] + b0;
                const float v1 = acc[mt][nt][half_ * 2 + 1] + b1;
                if (MODE == 0) {
                    const int which = nc >> 10;      // 0=q 1=k 2=v
                    const int cc = nc & 1023;
                    const int h = cc >> 6, dd = cc & 63;
                    const int b = r >> 11, t = r & 2047;
                    if (which == 2) {
                        const size_t vo = (((size_t)(b * H_ + h)) * D_ + dd) * T_ + t;
                        g_v[vo]      = __float2half_rn(v0);
                        g_v[vo + T_] = __float2half_rn(v1);
                    } else {
                        const float sc = (which == 0) ? 0.125f : 1.0f;  // fold 1/sqrt(64)
                        const size_t qo = (((size_t)(b * H_ + h)) * T_ + t) * D_ + dd;
                        *(uint32_t*)((which ? g_k : g_q) + qo) = pack2h(v0 * sc, v1 * sc);
                    }
                } else {
                    *(float2*)(Cout + (size_t)r * C_ + nc) = make_float2(v0, v1);
                }
            }
        }
    }
}

// ---------------------------------------------------------------------------
// Tensorized causal flash attention, single fp16 (1 MMA per product).
// Block: 128 q-rows, 8 warps, k-tile 64, 2-stage cp.async (16KB/stage).
// V pre-transposed [bh][d][t] -> all ldmatrix non-trans.
// ---------------------------------------------------------------------------
#define FL_STAGE 16384
#define FL_SMEM  32768

__global__ __launch_bounds__(256, 2)
void flash_mma_kernel()
{
    extern __shared__ char sm[];
    const uint32_t sb = smem_u32(sm);
    const int tid  = threadIdx.x;
    const int lane = tid & 31, w = tid >> 5;
    const int g = lane >> 2, t4 = lane & 3;
    const int bh = blockIdx.y;
    const int qb = (int)gridDim.x - 1 - (int)blockIdx.x;  // long blocks first
    const int q0 = qb * 128;
    const size_t cb = (size_t)bh * T_ * D_;
    const __half *Qg = g_q + cb;
    const __half *Kg = g_k + cb;
    const __half *Vg = g_v + cb;   // [d][t]

    // ---- stage Q (128x64 fp16 = 16KB) into stage0, read A-fragments ----
    #pragma unroll
    for (int i = 0; i < 4; ++i) {
        const int idx = i * 256 + tid;          // 0..1023
        const int r = idx >> 3, c = idx & 7;
        cpasync16(sb + (uint32_t)(r * 128 + ((c ^ (r & 7)) << 4)),
                  Qg + (size_t)(q0 + r) * D_ + c * 8);
    }
    asm volatile("cp.async.commit_group;\n\tcp.async.wait_group 0;" ::: "memory");
    __syncthreads();

    uint32_t qf[4][4];
    {
        const int qr = w * 16 + (lane & 7) + (lane & 8);
        const int half_ = (lane >> 4) & 1;
        #pragma unroll
        for (int s = 0; s < 4; ++s) {
            const int qc = 2 * s + half_;
            ldsm4(qf[s], sb + (uint32_t)(qr * 128 + ((qc ^ (qr & 7)) << 4)));
        }
    }
    __syncthreads();   // all warps done with Q staging before KV overwrite

    // ---- KV tile loader: K@0 (8K), V@8K (8K) within a 16KB stage ----
    auto load_kv = [&](int kt, int st) {
        const uint32_t stb = sb + (uint32_t)st * FL_STAGE;
        #pragma unroll
        for (int i = 0; i < 2; ++i) {
            const int idx = i * 256 + tid;      // 0..511
            const int r = idx >> 3, c = idx & 7;
            const uint32_t d = stb + (uint32_t)(r * 128 + ((c ^ (r & 7)) << 4));
            cpasync16(d,        Kg + (size_t)(kt * 64 + r) * D_ + c * 8);
            cpasync16(d + 8192, Vg + (size_t)r * T_ + kt * 64 + c * 8);
        }
    };

    float oacc[8][4];
    #pragma unroll
    for (int dj = 0; dj < 8; ++dj)
        #pragma unroll
        for (int q = 0; q < 4; ++q) oacc[dj][q] = 0.f;
    float mA = -INFINITY, mB = -INFINITY, lA = 0.f, lB = 0.f;

    const int nkt = 2 * qb + 2;
    load_kv(0, 0);
    asm volatile("cp.async.commit_group;" ::: "memory");
    load_kv(1, 1);
    asm volatile("cp.async.commit_group;" ::: "memory");

    const int ktmax_w = (q0 + w * 16 + 15) >> 6;     // last tile this warp needs
    const int rowA = q0 + w * 16 + g, rowB = rowA + 8;

    for (int kt = 0; kt < nkt; ++kt) {
        asm volatile("cp.async.wait_group 1;" ::: "memory");
        __syncthreads();
        const uint32_t stb = sb + (uint32_t)(kt & 1) * FL_STAGE;

        if (kt <= ktmax_w) {
            // ---- S = Q K^T ----
            float sc[8][4];
            #pragma unroll
            for (int j = 0; j < 8; ++j) {
                uint32_t kf0[4], kf1[4];
                const int kr = 8 * j + (lane & 7);
                const int c0 = lane >> 3;            // chunk 0..3
                ldsm4(kf0, stb + (uint32_t)(kr * 128 + ((c0 ^ (kr & 7)) << 4)));
                ldsm4(kf1, stb + (uint32_t)(kr * 128 + (((c0 + 4) ^ (kr & 7)) << 4)));
                sc[j][0] = sc[j][1] = sc[j][2] = sc[j][3] = 0.f;
                #pragma unroll
                for (int s = 0; s < 4; ++s) {
                    const uint32_t* kf = (s < 2) ? kf0 : kf1;
                    uint32_t bf[2] = { kf[2 * (s & 1)], kf[2 * (s & 1) + 1] };
                    mma16816(sc[j], qf[s], bf);
                }
            }

            // ---- causal mask (only near-diagonal tiles) ----
            if (kt * 64 + 63 > q0 + w * 16) {
                #pragma unroll
                for (int j = 0; j < 8; ++j) {
                    const int c = kt * 64 + 8 * j + 2 * t4;
                    if (c     > rowA) sc[j][0] = -INFINITY;
                    if (c + 1 > rowA) sc[j][1] = -INFINITY;
                    if (c     > rowB) sc[j][2] = -INFINITY;
                    if (c + 1 > rowB) sc[j][3] = -INFINITY;
                }
            }

            // ---- online softmax (rows A=g, B=g+8; stats over tid4 group) ----
            float mxA = -INFINITY, mxB = -INFINITY;
            #pragma unroll
            for (int j = 0; j < 8; ++j) {
                mxA = fmaxf(mxA, fmaxf(sc[j][0], sc[j][1]));
                mxB = fmaxf(mxB, fmaxf(sc[j][2], sc[j][3]));
            }
            #pragma unroll
            for (int sh = 1; sh <= 2; sh <<= 1) {
                mxA = fmaxf(mxA, __shfl_xor_sync(0xffffffffu, mxA, sh));
                mxB = fmaxf(mxB, __shfl_xor_sync(0xffffffffu, mxB, sh));
            }
            const float mAn = fmaxf(mA, mxA), mBn = fmaxf(mB, mxB);
            const float cA = __expf(mA - mAn), cB = __expf(mB - mBn);
            mA = mAn; mB = mBn;
            float sA = 0.f, sB = 0.f;
            #pragma unroll
            for (int j = 0; j < 8; ++j) {
                sc[j][0] = __expf(sc[j][0] - mAn);
                sc[j][1] = __expf(sc[j][1] - mAn);
                sc[j][2] = __expf(sc[j][2] - mBn);
                sc[j][3] = __expf(sc[j][3] - mBn);
                sA += sc[j][0] + sc[j][1];
                sB += sc[j][2] + sc[j][3];
            }
            #pragma unroll
            for (int sh = 1; sh <= 2; sh <<= 1) {
                sA += __shfl_xor_sync(0xffffffffu, sA, sh);
                sB += __shfl_xor_sync(0xffffffffu, sB, sh);
            }
            lA = lA * cA + sA;
            lB = lB * cB + sB;
            #pragma unroll
            for (int dj = 0; dj < 8; ++dj) {
                oacc[dj][0] *= cA; oacc[dj][1] *= cA;
                oacc[dj][2] *= cB; oacc[dj][3] *= cB;
            }

            // ---- P fragments straight from S fragments (single fp16) ----
            uint32_t pf[4][4];
            #pragma unroll
            for (int s = 0; s < 4; ++s) {
                pf[s][0] = pack2h(sc[2*s][0],   sc[2*s][1]);
                pf[s][1] = pack2h(sc[2*s][2],   sc[2*s][3]);
                pf[s][2] = pack2h(sc[2*s+1][0], sc[2*s+1][1]);
                pf[s][3] = pack2h(sc[2*s+1][2], sc[2*s+1][3]);
            }

            // ---- O += P V; V^T smem rows = d ----
            #pragma unroll
            for (int dj = 0; dj < 8; ++dj) {
                uint32_t vf0[4], vf1[4];
                const int vr = 8 * dj + (lane & 7);
                const int c0 = lane >> 3;
                ldsm4(vf0, stb + 8192 + (uint32_t)(vr * 128 + ((c0 ^ (vr & 7)) << 4)));
                ldsm4(vf1, stb + 8192 + (uint32_t)(vr * 128 + (((c0 + 4) ^ (vr & 7)) << 4)));
                #pragma unroll
                for (int s = 0; s < 4; ++s) {
                    const uint32_t* vf = (s < 2) ? vf0 : vf1;
                    uint32_t bf[2] = { vf[2 * (s & 1)], vf[2 * (s & 1) + 1] };
                    mma16816(oacc[dj], pf[s], bf);
                }
            }
        }

        __syncthreads();
        if (kt + 2 < nkt) load_kv(kt + 2, kt & 1);
        asm volatile("cp.async.commit_group;" ::: "memory");
    }

    // ---- finalize: /l, write single fp16 to [B*T, C] ----
    const int b = bh >> 4, h = bh & 15;
    const float iA = 1.f / lA, iB = 1.f / lB;
    const size_t rAo = (size_t)(b * T_ + rowA) * C_ + h * 64 + 2 * t4;
    const size_t rBo = rAo + 8 * (size_t)C_;
    #pragma unroll
    for (int dj = 0; dj < 8; ++dj) {
        *(uint32_t*)(g_o + rAo + 8 * dj) = pack2h(oacc[dj][0] * iA, oacc[dj][1] * iA);
        *(uint32_t*)(g_o + rBo + 8 * dj) = pack2h(oacc[dj][2] * iB, oacc[dj][3] * iB);
    }
}

// ---------------------------------------------------------------------------
extern "C" void kernel_launch(void* const* d_in, const int* in_sizes, int n_in,
                              void* d_out, int out_size)
{
    (void)in_sizes; (void)n_in; (void)out_size;
    const float* x     = (const float*)d_in[0];
    const float* W_qkv = (const float*)d_in[1];
    const float* b_qkv = (const float*)d_in[2];
    const float* W_out = (const float*)d_in[3];
    const float* b_out = (const float*)d_in[4];
    float* out = (float*)d_out;

    // 0) fp32 -> fp16 conversions
    xconvert_kernel<<<M_ * C_ / 4 / 256, 256>>>((const float4*)x);
    wconvert_kernel<NQKV, 0><<<dim3(NQKV / 32, C_ / 32), dim3(32, 8)>>>(W_qkv);
    wconvert_kernel<C_,   1><<<dim3(C_   / 32, C_ / 32), dim3(32, 8)>>>(W_out);

    // 1) QKV projection (single fp16 HMMA) -> q, k, v^T
    cudaFuncSetAttribute(mma_gemm_kernel<0>, cudaFuncAttributeMaxDynamicSharedMemorySize, GEMM_SMEM);
    cudaFuncSetAttribute(mma_gemm_kernel<1>, cudaFuncAttributeMaxDynamicSharedMemorySize, GEMM_SMEM);
    mma_gemm_kernel<0><<<dim3(NQKV / 128, M_ / 128), 256, GEMM_SMEM>>>(b_qkv, nullptr);

    // 2) causal flash attention (single fp16 HMMA)
    cudaFuncSetAttribute(flash_mma_kernel, cudaFuncAttributeMaxDynamicSharedMemorySize, FL_SMEM);
    flash_mma_kernel<<<dim3(T_ / 128, B_ * H_), 256, FL_SMEM>>>();

    // 3) output projection (single fp16 HMMA)
    mma_gemm_kernel<1><<<dim3(C_ / 128, M_ / 128), 256, GEMM_SMEM>>>(b_out, out);
}

// round 13
// speedup vs baseline: 6.5400x; 1.0154x over previous
#include <cuda_runtime.h>
#include <cuda_fp16.h>
#include <math.h>
#include <stdint.h>

#define B_ 4
#define T_ 2048
#define C_ 1024
#define H_ 16
#define D_ 64
#define M_ (B_*T_)      /* 8192 */
#define NQKV (3*C_)     /* 3072 */

// ---------------------------------------------------------------------------
// Device-global scratch (allocation-free per harness rules)
// ---------------------------------------------------------------------------
__device__ __align__(16) __half g_x [(size_t)M_*C_];      // x fp16
__device__ __align__(16) __half g_wq[(size_t)NQKV*C_];    // W_qkv^T [3072,1024]
__device__ __align__(16) __half g_wo[(size_t)C_*C_];      // W_out^T [1024,1024]

__device__ __align__(16) __half g_q [(size_t)M_*C_];      // [B,H,T,D] (q*0.125)
__device__ __align__(16) __half g_k [(size_t)M_*C_];      // [B,H,T,D]
__device__ __align__(16) __half g_v [(size_t)M_*C_];      // [B,H,D,T] (transposed!)

__device__ __align__(16) __half g_o [(size_t)M_*C_];      // attn out [B*T, C]

// ---------------------------------------------------------------------------
// Baseline-PTX helpers (plain sm_103 target: no tcgen05)
// ---------------------------------------------------------------------------
__device__ __forceinline__ uint32_t smem_u32(const void* p) {
    uint32_t a;
    asm("{ .reg .u64 t; cvta.to.shared.u64 t, %1; cvt.u32.u64 %0, t; }" : "=r"(a) : "l"(p));
    return a;
}

__device__ __forceinline__ void cpasync16(uint32_t s, const void* g) {
    asm volatile("cp.async.cg.shared.global [%0], [%1], 16;" :: "r"(s), "l"(g));
}

__device__ __forceinline__ void ldsm4(uint32_t* r, uint32_t addr) {
    asm volatile("ldmatrix.sync.aligned.m8n8.x4.shared.b16 {%0,%1,%2,%3}, [%4];"
                 : "=r"(r[0]), "=r"(r[1]), "=r"(r[2]), "=r"(r[3]) : "r"(addr));
}

// fp16 MMA, fp32 accumulate
__device__ __forceinline__ void mma16816(float* c, const uint32_t* a, const uint32_t* b) {
    asm volatile(
        "mma.sync.aligned.m16n8k16.row.col.f32.f16.f16.f32 "
        "{%0,%1,%2,%3}, {%4,%5,%6,%7}, {%8,%9}, {%0,%1,%2,%3};"
        : "+f"(c[0]), "+f"(c[1]), "+f"(c[2]), "+f"(c[3])
        : "r"(a[0]), "r"(a[1]), "r"(a[2]), "r"(a[3]), "r"(b[0]), "r"(b[1]));
}

__device__ __forceinline__ uint32_t pack2h(float a, float b) {
    __half2 hh = __floats2half2_rn(a, b);
    return *(uint32_t*)&hh;
}

// ---------------------------------------------------------------------------
// Conversion kernels (fp32 -> single fp16)
// ---------------------------------------------------------------------------
__global__ void xconvert_kernel(const float4* __restrict__ x)
{
    const size_t i = (size_t)blockIdx.x * blockDim.x + threadIdx.x;  // over M_*C_/4
    float4 v = x[i];
    *(uint2*)(g_x + 4 * i) = make_uint2(pack2h(v.x, v.y), pack2h(v.z, v.w));
}

// Transpose: W [1024, NC] fp32 -> Wt [NC, 1024] fp16
template<int NC, int WHICH>
__global__ void wconvert_kernel(const float* __restrict__ W)
{
    __shared__ float ts[32][33];
    const int n0 = blockIdx.x * 32, k0 = blockIdx.y * 32;
    const int tx = threadIdx.x, ty = threadIdx.y;  // 32x8
    #pragma unroll
    for (int i = 0; i < 32; i += 8)
        ts[ty + i][tx] = W[(size_t)(k0 + ty + i) * NC + n0 + tx];
    __syncthreads();
    __half* dst = WHICH ? g_wo : g_wq;
    #pragma unroll
    for (int i = 0; i < 32; i += 8)
        dst[(size_t)(n0 + ty + i) * C_ + k0 + tx] = __float2half_rn(ts[tx][ty + i]);
}

// ---------------------------------------------------------------------------
// HMMA GEMM: D[128x128] = A[128,1024]*B^T, single fp16.
// 8 warps (2m x 4n), warp tile 64x32, BK=64 (64 MMAs per barrier), 3-stage
// cp.async ring (32KB/stage, 96KB total -> 2 CTAs/SM). Loads for kt+2 are
// issued at the TOP of each iteration (ring stage provably free after the
// barrier) so DMA overlaps the whole MMA body.
// Smem rows 128B, 16B-chunk XOR swizzle c^(r&7).
// MODE 0 epilogue: +bias, scale q, scatter q/k ([bh][t][d]) and v TRANSPOSED
//                  ([bh][d][t]), all single fp16.
// MODE 1 epilogue: +bias -> fp32 Cout.
// ---------------------------------------------------------------------------
#define GTILE_B  16384               /* 128 rows x 128 B */
#define GSTAGE_B (2*GTILE_B)         /* A + B = 32 KB */
#define GEMM_SMEM (3*GSTAGE_B)       /* 98304 */
#define NKSTEP   (C_/64)             /* 16 */

template<int MODE>
__global__ __launch_bounds__(256, 2)
void mma_gemm_kernel(const float* __restrict__ bias, float* __restrict__ Cout)
{
    extern __shared__ char sm[];
    const uint32_t sb = smem_u32(sm);
    const int tid  = threadIdx.x;
    const int wid  = tid >> 5, lane = tid & 31;
    const int n0 = blockIdx.x * 128;
    const int m0 = blockIdx.y * 128;
    const int wr = wid & 1;
    const int wc = wid >> 1;

    const __half* srcA = MODE ? g_o  : g_x;
    const __half* srcB = MODE ? g_wo : g_wq;

    // stage loader: 8 cp.async(16B) per thread (A tile + B tile, 128x64 fp16 each)
    auto load_stage = [&](int kt, int s) {
        const uint32_t stb = sb + (uint32_t)s * GSTAGE_B;
        #pragma unroll
        for (int lt = 0; lt < 2; ++lt) {
            const __half* lg = (lt == 0 ? srcA + (size_t)m0 * C_
                                        : srcB + (size_t)n0 * C_) + kt * 64;
            const uint32_t tb = stb + lt * GTILE_B;
            #pragma unroll
            for (int i = 0; i < 4; ++i) {
                const int idx = i * 256 + tid;   // 0..1023
                const int r = idx >> 3, c = idx & 7;
                cpasync16(tb + (uint32_t)(r * 128 + ((c ^ (r & 7)) << 4)),
                          lg + (size_t)r * C_ + c * 8);
            }
        }
    };

    float acc[4][4][4];
    #pragma unroll
    for (int mt = 0; mt < 4; ++mt)
        #pragma unroll
        for (int nt = 0; nt < 4; ++nt)
            #pragma unroll
            for (int q = 0; q < 4; ++q) acc[mt][nt][q] = 0.f;

    const int rl = lane & 15, hib = lane >> 4;
    const int s7 = rl & 7;
    uint32_t aAr[4], aBr[2];
    #pragma unroll
    for (int mt = 0; mt < 4; ++mt) aAr[mt] = (uint32_t)((wr * 64 + mt * 16 + rl) * 128);
    #pragma unroll
    for (int p = 0; p < 2; ++p)    aBr[p]  = (uint32_t)((wc * 32 + p * 16 + rl) * 128) + GTILE_B;

    load_stage(0, 0);
    asm volatile("cp.async.commit_group;" ::: "memory");
    load_stage(1, 1);
    asm volatile("cp.async.commit_group;" ::: "memory");

    for (int kt = 0; kt < NKSTEP; ++kt) {
        asm volatile("cp.async.wait_group 1;" ::: "memory");
        __syncthreads();
        if (kt + 2 < NKSTEP) load_stage(kt + 2, (kt + 2) % 3);
        asm volatile("cp.async.commit_group;" ::: "memory");

        const uint32_t stb = sb + (uint32_t)(kt % 3) * GSTAGE_B;
        #pragma unroll
        for (int kk = 0; kk < 4; ++kk) {
            const uint32_t xo = (uint32_t)(((2 * kk + hib) ^ s7) << 4);
            uint32_t ah[4][4], bh[2][4];
            #pragma unroll
            for (int mt = 0; mt < 4; ++mt)
                ldsm4(ah[mt], stb + aAr[mt] + xo);
            #pragma unroll
            for (int p = 0; p < 2; ++p)
                ldsm4(bh[p], stb + aBr[p] + xo);
            #pragma unroll
            for (int mt = 0; mt < 4; ++mt) {
                #pragma unroll
                for (int nt = 0; nt < 4; ++nt) {
                    uint32_t bf[2] = { bh[nt >> 1][nt & 1], bh[nt >> 1][(nt & 1) + 2] };
                    mma16816(acc[mt][nt], ah[mt], bf);
                }
            }
        }
    }

    const int gr = lane >> 2;
    const int gc = (lane & 3) * 2;
    #pragma unroll
    for (int mt = 0; mt < 4; ++mt) {
        #pragma unroll
        for (int nt = 0; nt < 4; ++nt) {
            const int nc = n0 + wc * 32 + nt * 8 + gc;
            const float b0 = bias[nc], b1 = bias[nc + 1];
            #pragma unroll
            for (int half_ = 0; half_ < 2; ++half_) {
                const int r = m0 + wr * 64 + mt * 16 + gr + half_ * 8;
                const float v0 = acc[mt][nt][half_ * 2 + 0] + b0;
                const float v1 = acc[mt][nt][half_ * 2 + 1] + b1;
                if (MODE == 0) {
                    const int which = nc >> 10;      // 0=q 1=k 2=v
                    const int cc = nc & 1023;
                    const int h = cc >> 6, dd = cc & 63;
                    const int b = r >> 11, t = r & 2047;
                    if (which == 2) {
                        const size_t vo = (((size_t)(b * H_ + h)) * D_ + dd) * T_ + t;
                        g_v[vo]      = __float2half_rn(v0);
                        g_v[vo + T_] = __float2half_rn(v1);
                    } else {
                        const float sc = (which == 0) ? 0.125f : 1.0f;  // fold 1/sqrt(64)
                        const size_t qo = (((size_t)(b * H_ + h)) * T_ + t) * D_ + dd;
                        *(uint32_t*)((which ? g_k : g_q) + qo) = pack2h(v0 * sc, v1 * sc);
                    }
                } else {
                    *(float2*)(Cout + (size_t)r * C_ + nc) = make_float2(v0, v1);
                }
            }
        }
    }
}

// ---------------------------------------------------------------------------
// Tensorized causal flash attention, single fp16.
// Block: 128 q-rows, 8 warps, k-tile 64, 3-stage cp.async ring (16KB/stage,
// 48KB total -> 2 CTAs/SM). One barrier per k-tile; loads for kt+2 issued at
// the top of the iteration. V pre-transposed [bh][d][t].
// ---------------------------------------------------------------------------
#define FL_STAGE 16384
#define FL_SMEM  (3*FL_STAGE)        /* 49152 */

__global__ __launch_bounds__(256, 2)
void flash_mma_kernel()
{
    extern __shared__ char sm[];
    const uint32_t sb = smem_u32(sm);
    const int tid  = threadIdx.x;
    const int lane = tid & 31, w = tid >> 5;
    const int g = lane >> 2, t4 = lane & 3;
    const int bh = blockIdx.y;
    const int qb = (int)gridDim.x - 1 - (int)blockIdx.x;  // long blocks first
    const int q0 = qb * 128;
    const size_t cb = (size_t)bh * T_ * D_;
    const __half *Qg = g_q + cb;
    const __half *Kg = g_k + cb;
    const __half *Vg = g_v + cb;   // [d][t]

    // ---- stage Q (128x64 fp16 = 16KB) into stage0, read A-fragments ----
    #pragma unroll
    for (int i = 0; i < 4; ++i) {
        const int idx = i * 256 + tid;          // 0..1023
        const int r = idx >> 3, c = idx & 7;
        cpasync16(sb + (uint32_t)(r * 128 + ((c ^ (r & 7)) << 4)),
                  Qg + (size_t)(q0 + r) * D_ + c * 8);
    }
    asm volatile("cp.async.commit_group;\n\tcp.async.wait_group 0;" ::: "memory");
    __syncthreads();

    uint32_t qf[4][4];
    {
        const int qr = w * 16 + (lane & 7) + (lane & 8);
        const int half_ = (lane >> 4) & 1;
        #pragma unroll
        for (int s = 0; s < 4; ++s) {
            const int qc = 2 * s + half_;
            ldsm4(qf[s], sb + (uint32_t)(qr * 128 + ((qc ^ (qr & 7)) << 4)));
        }
    }
    __syncthreads();   // all warps done with Q staging before KV overwrite

    // ---- KV tile loader: K@0 (8K), V@8K (8K) within a 16KB stage ----
    auto load_kv = [&](int kt, int st) {
        const uint32_t stb = sb + (uint32_t)st * FL_STAGE;
        #pragma unroll
        for (int i = 0; i < 2; ++i) {
            const int idx = i * 256 + tid;      // 0..511
            const int r = idx >> 3, c = idx & 7;
            const uint32_t d = stb + (uint32_t)(r * 128 + ((c ^ (r & 7)) << 4));
            cpasync16(d,        Kg + (size_t)(kt * 64 + r) * D_ + c * 8);
            cpasync16(d + 8192, Vg + (size_t)r * T_ + kt * 64 + c * 8);
        }
    };

    float oacc[8][4];
    #pragma unroll
    for (int dj = 0; dj < 8; ++dj)
        #pragma unroll
        for (int q = 0; q < 4; ++q) oacc[dj][q] = 0.f;
    float mA = -INFINITY, mB = -INFINITY, lA = 0.f, lB = 0.f;

    const int nkt = 2 * qb + 2;
    load_kv(0, 0);
    asm volatile("cp.async.commit_group;" ::: "memory");
    load_kv(1, 1);
    asm volatile("cp.async.commit_group;" ::: "memory");

    const int ktmax_w = (q0 + w * 16 + 15) >> 6;     // last tile this warp needs
    const int rowA = q0 + w * 16 + g, rowB = rowA + 8;

    for (int kt = 0; kt < nkt; ++kt) {
        asm volatile("cp.async.wait_group 1;" ::: "memory");
        __syncthreads();
        if (kt + 2 < nkt) load_kv(kt + 2, (kt + 2) % 3);
        asm volatile("cp.async.commit_group;" ::: "memory");

        const uint32_t stb = sb + (uint32_t)(kt % 3) * FL_STAGE;

        if (kt <= ktmax_w) {
            // ---- S = Q K^T ----
            float sc[8][4];
            #pragma unroll
            for (int j = 0; j < 8; ++j) {
                uint32_t kf0[4], kf1[4];
                const int kr = 8 * j + (lane & 7);
                const int c0 = lane >> 3;            // chunk 0..3
                ldsm4(kf0, stb + (uint32_t)(kr * 128 + ((c0 ^ (kr & 7)) << 4)));
                ldsm4(kf1, stb + (uint32_t)(kr * 128 + (((c0 + 4) ^ (kr & 7)) << 4)));
                sc[j][0] = sc[j][1] = sc[j][2] = sc[j][3] = 0.f;
                #pragma unroll
                for (int s = 0; s < 4; ++s) {
                    const uint32_t* kf = (s < 2) ? kf0 : kf1;
                    uint32_t bf[2] = { kf[2 * (s & 1)], kf[2 * (s & 1) + 1] };
                    mma16816(sc[j], qf[s], bf);
                }
            }

            // ---- causal mask (only near-diagonal tiles) ----
            if (kt * 64 + 63 > q0 + w * 16) {
                #pragma unroll
                for (int j = 0; j < 8; ++j) {
                    const int c = kt * 64 + 8 * j + 2 * t4;
                    if (c     > rowA) sc[j][0] = -INFINITY;
                    if (c + 1 > rowA) sc[j][1] = -INFINITY;
                    if (c     > rowB) sc[j][2] = -INFINITY;
                    if (c + 1 > rowB) sc[j][3] = -INFINITY;
                }
            }

            // ---- online softmax (rows A=g, B=g+8; stats over tid4 group) ----
            float mxA = -INFINITY, mxB = -INFINITY;
            #pragma unroll
            for (int j = 0; j < 8; ++j) {
                mxA = fmaxf(mxA, fmaxf(sc[j][0], sc[j][1]));
                mxB = fmaxf(mxB, fmaxf(sc[j][2], sc[j][3]));
            }
            #pragma unroll
            for (int sh = 1; sh <= 2; sh <<= 1) {
                mxA = fmaxf(mxA, __shfl_xor_sync(0xffffffffu, mxA, sh));
                mxB = fmaxf(mxB, __shfl_xor_sync(0xffffffffu, mxB, sh));
            }
            const float mAn = fmaxf(mA, mxA), mBn = fmaxf(mB, mxB);
            const float cA = __expf(mA - mAn), cB = __expf(mB - mBn);
            mA = mAn; mB = mBn;
            float sA = 0.f, sB = 0.f;
            #pragma unroll
            for (int j = 0; j < 8; ++j) {
                sc[j][0] = __expf(sc[j][0] - mAn);
                sc[j][1] = __expf(sc[j][1] - mAn);
                sc[j][2] = __expf(sc[j][2] - mBn);
                sc[j][3] = __expf(sc[j][3] - mBn);
                sA += sc[j][0] + sc[j][1];
                sB += sc[j][2] + sc[j][3];
            }
            #pragma unroll
            for (int sh = 1; sh <= 2; sh <<= 1) {
                sA += __shfl_xor_sync(0xffffffffu, sA, sh);
                sB += __shfl_xor_sync(0xffffffffu, sB, sh);
            }
            lA = lA * cA + sA;
            lB = lB * cB + sB;
            #pragma unroll
            for (int dj = 0; dj < 8; ++dj) {
                oacc[dj][0] *= cA; oacc[dj][1] *= cA;
                oacc[dj][2] *= cB; oacc[dj][3] *= cB;
            }

            // ---- P fragments straight from S fragments (single fp16) ----
            uint32_t pf[4][4];
            #pragma unroll
            for (int s = 0; s < 4; ++s) {
                pf[s][0] = pack2h(sc[2*s][0],   sc[2*s][1]);
                pf[s][1] = pack2h(sc[2*s][2],   sc[2*s][3]);
                pf[s][2] = pack2h(sc[2*s+1][0], sc[2*s+1][1]);
                pf[s][3] = pack2h(sc[2*s+1][2], sc[2*s+1][3]);
            }

            // ---- O += P V; V^T smem rows = d ----
            #pragma unroll
            for (int dj = 0; dj < 8; ++dj) {
                uint32_t vf0[4], vf1[4];
                const int vr = 8 * dj + (lane & 7);
                const int c0 = lane >> 3;
                ldsm4(vf0, stb + 8192 + (uint32_t)(vr * 128 + ((c0 ^ (vr & 7)) << 4)));
                ldsm4(vf1, stb + 8192 + (uint32_t)(vr * 128 + (((c0 + 4) ^ (vr & 7)) << 4)));
                #pragma unroll
                for (int s = 0; s < 4; ++s) {
                    const uint32_t* vf = (s < 2) ? vf0 : vf1;
                    uint32_t bf[2] = { vf[2 * (s & 1)], vf[2 * (s & 1) + 1] };
                    mma16816(oacc[dj], pf[s], bf);
                }
            }
        }
    }

    // ---- finalize: /l, write single fp16 to [B*T, C] ----
    const int b = bh >> 4, h = bh & 15;
    const float iA = 1.f / lA, iB = 1.f / lB;
    const size_t rAo = (size_t)(b * T_ + rowA) * C_ + h * 64 + 2 * t4;
    const size_t rBo = rAo + 8 * (size_t)C_;
    #pragma unroll
    for (int dj = 0; dj < 8; ++dj) {
        *(uint32_t*)(g_o + rAo + 8 * dj) = pack2h(oacc[dj][0] * iA, oacc[dj][1] * iA);
        *(uint32_t*)(g_o + rBo + 8 * dj) = pack2h(oacc[dj][2] * iB, oacc[dj][3] * iB);
    }
}

// ---------------------------------------------------------------------------
extern "C" void kernel_launch(void* const* d_in, const int* in_sizes, int n_in,
                              void* d_out, int out_size)
{
    (void)in_sizes; (void)n_in; (void)out_size;
    const float* x     = (const float*)d_in[0];
    const float* W_qkv = (const float*)d_in[1];
    const float* b_qkv = (const float*)d_in[2];
    const float* W_out = (const float*)d_in[3];
    const float* b_out = (const float*)d_in[4];
    float* out = (float*)d_out;

    // 0) fp32 -> fp16 conversions
    xconvert_kernel<<<M_ * C_ / 4 / 256, 256>>>((const float4*)x);
    wconvert_kernel<NQKV, 0><<<dim3(NQKV / 32, C_ / 32), dim3(32, 8)>>>(W_qkv);
    wconvert_kernel<C_,   1><<<dim3(C_   / 32, C_ / 32), dim3(32, 8)>>>(W_out);

    // 1) QKV projection (single fp16 HMMA, BK=64) -> q, k, v^T
    cudaFuncSetAttribute(mma_gemm_kernel<0>, cudaFuncAttributeMaxDynamicSharedMemorySize, GEMM_SMEM);
    cudaFuncSetAttribute(mma_gemm_kernel<1>, cudaFuncAttributeMaxDynamicSharedMemorySize, GEMM_SMEM);
    mma_gemm_kernel<0><<<dim3(NQKV / 128, M_ / 128), 256, GEMM_SMEM>>>(b_qkv, nullptr);

    // 2) causal flash attention (single fp16 HMMA, 3-stage ring)
    cudaFuncSetAttribute(flash_mma_kernel, cudaFuncAttributeMaxDynamicSharedMemorySize, FL_SMEM);
    flash_mma_kernel<<<dim3(T_ / 128, B_ * H_), 256, FL_SMEM>>>();

    // 3) output projection (single fp16 HMMA, BK=64)
    mma_gemm_kernel<1><<<dim3(C_ / 128, M_ / 128), 256, GEMM_SMEM>>>(b_out, out);
}

// round 16
// speedup vs baseline: 6.6819x; 1.0217x over previous
#include <cuda_runtime.h>
#include <cuda_fp16.h>
#include <math.h>
#include <stdint.h>

#define B_ 4
#define T_ 2048
#define C_ 1024
#define H_ 16
#define D_ 64
#define M_ (B_*T_)      /* 8192 */
#define NQKV (3*C_)     /* 3072 */

// ---------------------------------------------------------------------------
// Device-global scratch (allocation-free per harness rules)
// ---------------------------------------------------------------------------
__device__ __align__(16) __half g_x [(size_t)M_*C_];      // x fp16
__device__ __align__(16) __half g_wq[(size_t)NQKV*C_];    // W_qkv^T [3072,1024]
__device__ __align__(16) __half g_wo[(size_t)C_*C_];      // W_out^T [1024,1024]

__device__ __align__(16) __half g_q [(size_t)M_*C_];      // [B,H,T,D] (q*0.125)
__device__ __align__(16) __half g_k [(size_t)M_*C_];      // [B,H,T,D]
__device__ __align__(16) __half g_v [(size_t)M_*C_];      // [B,H,D,T] (transposed!)

__device__ __align__(16) __half g_o [(size_t)M_*C_];      // attn out [B*T, C]

// ---------------------------------------------------------------------------
// Baseline-PTX helpers (plain sm_103 target: no tcgen05)
// ---------------------------------------------------------------------------
__device__ __forceinline__ uint32_t smem_u32(const void* p) {
    uint32_t a;
    asm("{ .reg .u64 t; cvta.to.shared.u64 t, %1; cvt.u32.u64 %0, t; }" : "=r"(a) : "l"(p));
    return a;
}

__device__ __forceinline__ void cpasync16(uint32_t s, const void* g) {
    asm volatile("cp.async.cg.shared.global [%0], [%1], 16;" :: "r"(s), "l"(g));
}

__device__ __forceinline__ void ldsm4(uint32_t* r, uint32_t addr) {
    asm volatile("ldmatrix.sync.aligned.m8n8.x4.shared.b16 {%0,%1,%2,%3}, [%4];"
                 : "=r"(r[0]), "=r"(r[1]), "=r"(r[2]), "=r"(r[3]) : "r"(addr));
}

// fp16 MMA, fp32 accumulate
__device__ __forceinline__ void mma16816(float* c, const uint32_t* a, const uint32_t* b) {
    asm volatile(
        "mma.sync.aligned.m16n8k16.row.col.f32.f16.f16.f32 "
        "{%0,%1,%2,%3}, {%4,%5,%6,%7}, {%8,%9}, {%0,%1,%2,%3};"
        : "+f"(c[0]), "+f"(c[1]), "+f"(c[2]), "+f"(c[3])
        : "r"(a[0]), "r"(a[1]), "r"(a[2]), "r"(a[3]), "r"(b[0]), "r"(b[1]));
}

__device__ __forceinline__ uint32_t pack2h(float a, float b) {
    __half2 hh = __floats2half2_rn(a, b);
    return *(uint32_t*)&hh;
}

// ---------------------------------------------------------------------------
// Conversion kernels (fp32 -> single fp16)
// ---------------------------------------------------------------------------
__global__ void xconvert_kernel(const float4* __restrict__ x)
{
    const size_t i = (size_t)blockIdx.x * blockDim.x + threadIdx.x;  // over M_*C_/4
    float4 v = x[i];
    *(uint2*)(g_x + 4 * i) = make_uint2(pack2h(v.x, v.y), pack2h(v.z, v.w));
}

// Transpose: W [1024, NC] fp32 -> Wt [NC, 1024] fp16
template<int NC, int WHICH>
__global__ void wconvert_kernel(const float* __restrict__ W)
{
    __shared__ float ts[32][33];
    const int n0 = blockIdx.x * 32, k0 = blockIdx.y * 32;
    const int tx = threadIdx.x, ty = threadIdx.y;  // 32x8
    #pragma unroll
    for (int i = 0; i < 32; i += 8)
        ts[ty + i][tx] = W[(size_t)(k0 + ty + i) * NC + n0 + tx];
    __syncthreads();
    __half* dst = WHICH ? g_wo : g_wq;
    #pragma unroll
    for (int i = 0; i < 32; i += 8)
        dst[(size_t)(n0 + ty + i) * C_ + k0 + tx] = __float2half_rn(ts[tx][ty + i]);
}

// ---------------------------------------------------------------------------
// HMMA GEMM: D[128x128] = A[128,1024]*B^T, single fp16.
// 128 threads = 4 warps (2m x 2n), warp tile 64x64 -> per kk: 8 LDSM feed
// 32 MMAs (was 6:16) and smem amplification drops (A 4x->2x).
// BK=64, 3-stage cp.async ring (32KB/stage, 96KB -> 2 CTAs/SM).
// MODE 0 epilogue: +bias, scale q, scatter q/k ([bh][t][d]) and v TRANSPOSED
//                  ([bh][d][t]), all single fp16.
// MODE 1 epilogue: +bias -> fp32 Cout.
// ---------------------------------------------------------------------------
#define GTILE_B  16384               /* 128 rows x 128 B */
#define GSTAGE_B (2*GTILE_B)         /* A + B = 32 KB */
#define GEMM_SMEM (3*GSTAGE_B)       /* 98304 */
#define NKSTEP   (C_/64)             /* 16 */

template<int MODE>
__global__ __launch_bounds__(128, 2)
void mma_gemm_kernel(const float* __restrict__ bias, float* __restrict__ Cout)
{
    extern __shared__ char sm[];
    const uint32_t sb = smem_u32(sm);
    const int tid  = threadIdx.x;
    const int wid  = tid >> 5, lane = tid & 31;
    const int n0 = blockIdx.x * 128;
    const int m0 = blockIdx.y * 128;
    const int wr = wid & 1;          // m offset wr*64
    const int wc = wid >> 1;         // n offset wc*64

    const __half* srcA = MODE ? g_o  : g_x;
    const __half* srcB = MODE ? g_wo : g_wq;

    // stage loader: 16 cp.async(16B) per thread (A tile + B tile, 128x64 fp16)
    auto load_stage = [&](int kt, int s) {
        const uint32_t stb = sb + (uint32_t)s * GSTAGE_B;
        #pragma unroll
        for (int lt = 0; lt < 2; ++lt) {
            const __half* lg = (lt == 0 ? srcA + (size_t)m0 * C_
                                        : srcB + (size_t)n0 * C_) + kt * 64;
            const uint32_t tb = stb + lt * GTILE_B;
            #pragma unroll
            for (int i = 0; i < 8; ++i) {
                const int idx = i * 128 + tid;   // 0..1023
                const int r = idx >> 3, c = idx & 7;
                cpasync16(tb + (uint32_t)(r * 128 + ((c ^ (r & 7)) << 4)),
                          lg + (size_t)r * C_ + c * 8);
            }
        }
    };

    float acc[4][8][4];
    #pragma unroll
    for (int mt = 0; mt < 4; ++mt)
        #pragma unroll
        for (int nt = 0; nt < 8; ++nt)
            #pragma unroll
            for (int q = 0; q < 4; ++q) acc[mt][nt][q] = 0.f;

    const int rl = lane & 15, hib = lane >> 4;
    const int s7 = rl & 7;
    uint32_t aAr[4], aBr[4];
    #pragma unroll
    for (int mt = 0; mt < 4; ++mt) aAr[mt] = (uint32_t)((wr * 64 + mt * 16 + rl) * 128);
    #pragma unroll
    for (int p = 0; p < 4; ++p)    aBr[p]  = (uint32_t)((wc * 64 + p * 16 + rl) * 128) + GTILE_B;

    load_stage(0, 0);
    asm volatile("cp.async.commit_group;" ::: "memory");
    load_stage(1, 1);
    asm volatile("cp.async.commit_group;" ::: "memory");

    for (int kt = 0; kt < NKSTEP; ++kt) {
        asm volatile("cp.async.wait_group 1;" ::: "memory");
        __syncthreads();
        if (kt + 2 < NKSTEP) load_stage(kt + 2, (kt + 2) % 3);
        asm volatile("cp.async.commit_group;" ::: "memory");

        const uint32_t stb = sb + (uint32_t)(kt % 3) * GSTAGE_B;
        #pragma unroll
        for (int kk = 0; kk < 4; ++kk) {
            const uint32_t xo = (uint32_t)(((2 * kk + hib) ^ s7) << 4);
            uint32_t ah[4][4], bh[4][4];
            #pragma unroll
            for (int mt = 0; mt < 4; ++mt)
                ldsm4(ah[mt], stb + aAr[mt] + xo);
            #pragma unroll
            for (int p = 0; p < 4; ++p)
                ldsm4(bh[p], stb + aBr[p] + xo);
            #pragma unroll
            for (int mt = 0; mt < 4; ++mt) {
                #pragma unroll
                for (int p = 0; p < 4; ++p) {
                    uint32_t bf0[2] = { bh[p][0], bh[p][2] };
                    uint32_t bf1[2] = { bh[p][1], bh[p][3] };
                    mma16816(acc[mt][2 * p],     ah[mt], bf0);
                    mma16816(acc[mt][2 * p + 1], ah[mt], bf1);
                }
            }
        }
    }

    const int gr = lane >> 2;
    const int gc = (lane & 3) * 2;
    #pragma unroll
    for (int mt = 0; mt < 4; ++mt) {
        #pragma unroll
        for (int nt = 0; nt < 8; ++nt) {
            const int nc = n0 + wc * 64 + nt * 8 + gc;
            const float b0 = bias[nc], b1 = bias[nc + 1];
            #pragma unroll
            for (int half_ = 0; half_ < 2; ++half_) {
                const int r = m0 + wr * 64 + mt * 16 + gr + half_ * 8;
                const float v0 = acc[mt][nt][half_ * 2 + 0] + b0;
                const float v1 = acc[mt][nt][half_ * 2 + 1] + b1;
                if (MODE == 0) {
                    const int which = nc >> 10;      // 0=q 1=k 2=v
                    const int cc = nc & 1023;
                    const int h = cc >> 6, dd = cc & 63;
                    const int b = r >> 11, t = r & 2047;
                    if (which == 2) {
                        const size_t vo = (((size_t)(b * H_ + h)) * D_ + dd) * T_ + t;
                        g_v[vo]      = __float2half_rn(v0);
                        g_v[vo + T_] = __float2half_rn(v1);
                    } else {
                        const float sc = (which == 0) ? 0.125f : 1.0f;  // fold 1/sqrt(64)
                        const size_t qo = (((size_t)(b * H_ + h)) * T_ + t) * D_ + dd;
                        *(uint32_t*)((which ? g_k : g_q) + qo) = pack2h(v0 * sc, v1 * sc);
                    }
                } else {
                    *(float2*)(Cout + (size_t)r * C_ + nc) = make_float2(v0, v1);
                }
            }
        }
    }
}

// ---------------------------------------------------------------------------
// Tensorized causal flash attention, single fp16.
// 128 threads = 4 warps; each warp owns 32 q-rows (2 row-groups of 16).
// K/V smem amplification 8x -> 4x; per warp per kt: 32 LDSM feed 128 MMAs.
// k-tile 64, 3-stage cp.async ring (16KB/stage, 48KB -> 2 CTAs/SM).
// V pre-transposed [bh][d][t] -> all ldmatrix non-trans.
// ---------------------------------------------------------------------------
#define FL_STAGE 16384
#define FL_SMEM  (3*FL_STAGE)        /* 49152 */

__global__ __launch_bounds__(128, 2)
void flash_mma_kernel()
{
    extern __shared__ char sm[];
    const uint32_t sb = smem_u32(sm);
    const int tid  = threadIdx.x;
    const int lane = tid & 31, w = tid >> 5;     // 4 warps
    const int g = lane >> 2, t4 = lane & 3;
    const int bh = blockIdx.y;
    const int qb = (int)gridDim.x - 1 - (int)blockIdx.x;  // long blocks first
    const int q0 = qb * 128;
    const size_t cb = (size_t)bh * T_ * D_;
    const __half *Qg = g_q + cb;
    const __half *Kg = g_k + cb;
    const __half *Vg = g_v + cb;   // [d][t]

    // ---- stage Q (128x64 fp16 = 16KB) into stage0, read A-fragments ----
    #pragma unroll
    for (int i = 0; i < 8; ++i) {
        const int idx = i * 128 + tid;          // 0..1023
        const int r = idx >> 3, c = idx & 7;
        cpasync16(sb + (uint32_t)(r * 128 + ((c ^ (r & 7)) << 4)),
                  Qg + (size_t)(q0 + r) * D_ + c * 8);
    }
    asm volatile("cp.async.commit_group;\n\tcp.async.wait_group 0;" ::: "memory");
    __syncthreads();

    uint32_t qf[2][4][4];
    {
        const int half_ = (lane >> 4) & 1;
        #pragma unroll
        for (int rg = 0; rg < 2; ++rg) {
            const int qr = w * 32 + rg * 16 + (lane & 7) + (lane & 8);
            #pragma unroll
            for (int s = 0; s < 4; ++s) {
                const int qc = 2 * s + half_;
                ldsm4(qf[rg][s], sb + (uint32_t)(qr * 128 + ((qc ^ (qr & 7)) << 4)));
            }
        }
    }
    __syncthreads();   // all warps done with Q staging before KV overwrite

    // ---- KV tile loader: K@0 (8K), V@8K (8K) within a 16KB stage ----
    auto load_kv = [&](int kt, int st) {
        const uint32_t stb = sb + (uint32_t)st * FL_STAGE;
        #pragma unroll
        for (int i = 0; i < 4; ++i) {
            const int idx = i * 128 + tid;      // 0..511
            const int r = idx >> 3, c = idx & 7;
            const uint32_t d = stb + (uint32_t)(r * 128 + ((c ^ (r & 7)) << 4));
            cpasync16(d,        Kg + (size_t)(kt * 64 + r) * D_ + c * 8);
            cpasync16(d + 8192, Vg + (size_t)r * T_ + kt * 64 + c * 8);
        }
    };

    float oacc[2][8][4];
    #pragma unroll
    for (int rg = 0; rg < 2; ++rg)
        #pragma unroll
        for (int dj = 0; dj < 8; ++dj)
            #pragma unroll
            for (int q = 0; q < 4; ++q) oacc[rg][dj][q] = 0.f;
    float mr[2][2], lr[2][2];
    #pragma unroll
    for (int rg = 0; rg < 2; ++rg) {
        mr[rg][0] = mr[rg][1] = -INFINITY;
        lr[rg][0] = lr[rg][1] = 0.f;
    }

    const int nkt = 2 * qb + 2;
    load_kv(0, 0);
    asm volatile("cp.async.commit_group;" ::: "memory");
    load_kv(1, 1);
    asm volatile("cp.async.commit_group;" ::: "memory");

    const int ktmax_w = (q0 + w * 32 + 31) >> 6;     // last tile this warp needs
    int rowA[2], rowB[2];
    #pragma unroll
    for (int rg = 0; rg < 2; ++rg) {
        rowA[rg] = q0 + w * 32 + rg * 16 + g;
        rowB[rg] = rowA[rg] + 8;
    }

    for (int kt = 0; kt < nkt; ++kt) {
        asm volatile("cp.async.wait_group 1;" ::: "memory");
        __syncthreads();
        if (kt + 2 < nkt) load_kv(kt + 2, (kt + 2) % 3);
        asm volatile("cp.async.commit_group;" ::: "memory");

        const uint32_t stb = sb + (uint32_t)(kt % 3) * FL_STAGE;

        if (kt <= ktmax_w) {
            // ---- S = Q K^T ----
            float sc[2][8][4];
            #pragma unroll
            for (int j = 0; j < 8; ++j) {
                uint32_t kf0[4], kf1[4];
                const int kr = 8 * j + (lane & 7);
                const int c0 = lane >> 3;            // chunk 0..3
                ldsm4(kf0, stb + (uint32_t)(kr * 128 + ((c0 ^ (kr & 7)) << 4)));
                ldsm4(kf1, stb + (uint32_t)(kr * 128 + (((c0 + 4) ^ (kr & 7)) << 4)));
                #pragma unroll
                for (int rg = 0; rg < 2; ++rg) {
                    sc[rg][j][0] = sc[rg][j][1] = sc[rg][j][2] = sc[rg][j][3] = 0.f;
                    #pragma unroll
                    for (int s = 0; s < 4; ++s) {
                        const uint32_t* kf = (s < 2) ? kf0 : kf1;
                        uint32_t bf[2] = { kf[2 * (s & 1)], kf[2 * (s & 1) + 1] };
                        mma16816(sc[rg][j], qf[rg][s], bf);
                    }
                }
            }

            // ---- causal mask (only near-diagonal tiles) ----
            if (kt * 64 + 63 > q0 + w * 32) {
                #pragma unroll
                for (int rg = 0; rg < 2; ++rg) {
                    #pragma unroll
                    for (int j = 0; j < 8; ++j) {
                        const int c = kt * 64 + 8 * j + 2 * t4;
                        if (c     > rowA[rg]) sc[rg][j][0] = -INFINITY;
                        if (c + 1 > rowA[rg]) sc[rg][j][1] = -INFINITY;
                        if (c     > rowB[rg]) sc[rg][j][2] = -INFINITY;
                        if (c + 1 > rowB[rg]) sc[rg][j][3] = -INFINITY;
                    }
                }
            }

            // ---- online softmax per row-group (stats over tid4 group) ----
            #pragma unroll
            for (int rg = 0; rg < 2; ++rg) {
                float mxA = -INFINITY, mxB = -INFINITY;
                #pragma unroll
                for (int j = 0; j < 8; ++j) {
                    mxA = fmaxf(mxA, fmaxf(sc[rg][j][0], sc[rg][j][1]));
                    mxB = fmaxf(mxB, fmaxf(sc[rg][j][2], sc[rg][j][3]));
                }
                #pragma unroll
                for (int sh = 1; sh <= 2; sh <<= 1) {
                    mxA = fmaxf(mxA, __shfl_xor_sync(0xffffffffu, mxA, sh));
                    mxB = fmaxf(mxB, __shfl_xor_sync(0xffffffffu, mxB, sh));
                }
                const float mAn = fmaxf(mr[rg][0], mxA), mBn = fmaxf(mr[rg][1], mxB);
                const float cA = __expf(mr[rg][0] - mAn), cB = __expf(mr[rg][1] - mBn);
                mr[rg][0] = mAn; mr[rg][1] = mBn;
                float sA = 0.f, sB = 0.f;
                #pragma unroll
                for (int j = 0; j < 8; ++j) {
                    sc[rg][j][0] = __expf(sc[rg][j][0] - mAn);
                    sc[rg][j][1] = __expf(sc[rg][j][1] - mAn);
                    sc[rg][j][2] = __expf(sc[rg][j][2] - mBn);
                    sc[rg][j][3] = __expf(sc[rg][j][3] - mBn);
                    sA += sc[rg][j][0] + sc[rg][j][1];
                    sB += sc[rg][j][2] + sc[rg][j][3];
                }
                #pragma unroll
                for (int sh = 1; sh <= 2; sh <<= 1) {
                    sA += __shfl_xor_sync(0xffffffffu, sA, sh);
                    sB += __shfl_xor_sync(0xffffffffu, sB, sh);
                }
                lr[rg][0] = lr[rg][0] * cA + sA;
                lr[rg][1] = lr[rg][1] * cB + sB;
                #pragma unroll
                for (int dj = 0; dj < 8; ++dj) {
                    oacc[rg][dj][0] *= cA; oacc[rg][dj][1] *= cA;
                    oacc[rg][dj][2] *= cB; oacc[rg][dj][3] *= cB;
                }
            }

            // ---- P fragments straight from S fragments (single fp16) ----
            uint32_t pf[2][4][4];
            #pragma unroll
            for (int rg = 0; rg < 2; ++rg) {
                #pragma unroll
                for (int s = 0; s < 4; ++s) {
                    pf[rg][s][0] = pack2h(sc[rg][2*s][0],   sc[rg][2*s][1]);
                    pf[rg][s][1] = pack2h(sc[rg][2*s][2],   sc[rg][2*s][3]);
                    pf[rg][s][2] = pack2h(sc[rg][2*s+1][0], sc[rg][2*s+1][1]);
                    pf[rg][s][3] = pack2h(sc[rg][2*s+1][2], sc[rg][2*s+1][3]);
                }
            }

            // ---- O += P V; V^T smem rows = d ----
            #pragma unroll
            for (int dj = 0; dj < 8; ++dj) {
                uint32_t vf0[4], vf1[4];
                const int vr = 8 * dj + (lane & 7);
                const int c0 = lane >> 3;
                ldsm4(vf0, stb + 8192 + (uint32_t)(vr * 128 + ((c0 ^ (vr & 7)) << 4)));
                ldsm4(vf1, stb + 8192 + (uint32_t)(vr * 128 + (((c0 + 4) ^ (vr & 7)) << 4)));
                #pragma unroll
                for (int rg = 0; rg < 2; ++rg) {
                    #pragma unroll
                    for (int s = 0; s < 4; ++s) {
                        const uint32_t* vf = (s < 2) ? vf0 : vf1;
                        uint32_t bf[2] = { vf[2 * (s & 1)], vf[2 * (s & 1) + 1] };
                        mma16816(oacc[rg][dj], pf[rg][s], bf);
                    }
                }
            }
        }
    }

    // ---- finalize: /l, write single fp16 to [B*T, C] ----
    const int b = bh >> 4, h = bh & 15;
    #pragma unroll
    for (int rg = 0; rg < 2; ++rg) {
        const float iA = 1.f / lr[rg][0], iB = 1.f / lr[rg][1];
        const size_t rAo = (size_t)(b * T_ + rowA[rg]) * C_ + h * 64 + 2 * t4;
        const size_t rBo = rAo + 8 * (size_t)C_;
        #pragma unroll
        for (int dj = 0; dj < 8; ++dj) {
            *(uint32_t*)(g_o + rAo + 8 * dj) = pack2h(oacc[rg][dj][0] * iA, oacc[rg][dj][1] * iA);
            *(uint32_t*)(g_o + rBo + 8 * dj) = pack2h(oacc[rg][dj][2] * iB, oacc[rg][dj][3] * iB);
        }
    }
}

// ---------------------------------------------------------------------------
extern "C" void kernel_launch(void* const* d_in, const int* in_sizes, int n_in,
                              void* d_out, int out_size)
{
    (void)in_sizes; (void)n_in; (void)out_size;
    const float* x     = (const float*)d_in[0];
    const float* W_qkv = (const float*)d_in[1];
    const float* b_qkv = (const float*)d_in[2];
    const float* W_out = (const float*)d_in[3];
    const float* b_out = (const float*)d_in[4];
    float* out = (float*)d_out;

    // 0) fp32 -> fp16 conversions
    xconvert_kernel<<<M_ * C_ / 4 / 256, 256>>>((const float4*)x);
    wconvert_kernel<NQKV, 0><<<dim3(NQKV / 32, C_ / 32), dim3(32, 8)>>>(W_qkv);
    wconvert_kernel<C_,   1><<<dim3(C_   / 32, C_ / 32), dim3(32, 8)>>>(W_out);

    // 1) QKV projection (single fp16 HMMA, 64x64 warp tiles) -> q, k, v^T
    cudaFuncSetAttribute(mma_gemm_kernel<0>, cudaFuncAttributeMaxDynamicSharedMemorySize, GEMM_SMEM);
    cudaFuncSetAttribute(mma_gemm_kernel<1>, cudaFuncAttributeMaxDynamicSharedMemorySize, GEMM_SMEM);
    mma_gemm_kernel<0><<<dim3(NQKV / 128, M_ / 128), 128, GEMM_SMEM>>>(b_qkv, nullptr);

    // 2) causal flash attention (single fp16 HMMA, 32-row warps)
    cudaFuncSetAttribute(flash_mma_kernel, cudaFuncAttributeMaxDynamicSharedMemorySize, FL_SMEM);
    flash_mma_kernel<<<dim3(T_ / 128, B_ * H_), 128, FL_SMEM>>>();

    // 3) output projection (single fp16 HMMA, 64x64 warp tiles)
    mma_gemm_kernel<1><<<dim3(C_ / 128, M_ / 128), 128, GEMM_SMEM>>>(b_out, out);
}

// round 17
// speedup vs baseline: 6.6894x; 1.0011x over previous
#include <cuda_runtime.h>
#include <cuda_fp16.h>
#include <math.h>
#include <stdint.h>

#define B_ 4
#define T_ 2048
#define C_ 1024
#define H_ 16
#define D_ 64
#define M_ (B_*T_)      /* 8192 */
#define NQKV (3*C_)     /* 3072 */

// ---------------------------------------------------------------------------
// Device-global scratch (allocation-free per harness rules)
// ---------------------------------------------------------------------------
__device__ __align__(16) __half g_x [(size_t)M_*C_];      // x fp16
__device__ __align__(16) __half g_wq[(size_t)NQKV*C_];    // W_qkv^T [3072,1024]
__device__ __align__(16) __half g_wo[(size_t)C_*C_];      // W_out^T [1024,1024]

__device__ __align__(16) __half g_q [(size_t)M_*C_];      // [B,H,T,D] (q*0.125)
__device__ __align__(16) __half g_k [(size_t)M_*C_];      // [B,H,T,D]
__device__ __align__(16) __half g_v [(size_t)M_*C_];      // [B,H,D,T] (transposed!)

__device__ __align__(16) __half g_o [(size_t)M_*C_];      // attn out [B*T, C]

// ---------------------------------------------------------------------------
// Baseline-PTX helpers (plain sm_103 target: no tcgen05)
// ---------------------------------------------------------------------------
__device__ __forceinline__ uint32_t smem_u32(const void* p) {
    uint32_t a;
    asm("{ .reg .u64 t; cvta.to.shared.u64 t, %1; cvt.u32.u64 %0, t; }" : "=r"(a) : "l"(p));
    return a;
}

__device__ __forceinline__ void cpasync16(uint32_t s, const void* g) {
    asm volatile("cp.async.cg.shared.global [%0], [%1], 16;" :: "r"(s), "l"(g));
}

__device__ __forceinline__ void ldsm4(uint32_t* r, uint32_t addr) {
    asm volatile("ldmatrix.sync.aligned.m8n8.x4.shared.b16 {%0,%1,%2,%3}, [%4];"
                 : "=r"(r[0]), "=r"(r[1]), "=r"(r[2]), "=r"(r[3]) : "r"(addr));
}

// fp16 MMA, fp32 accumulate
__device__ __forceinline__ void mma16816(float* c, const uint32_t* a, const uint32_t* b) {
    asm volatile(
        "mma.sync.aligned.m16n8k16.row.col.f32.f16.f16.f32 "
        "{%0,%1,%2,%3}, {%4,%5,%6,%7}, {%8,%9}, {%0,%1,%2,%3};"
        : "+f"(c[0]), "+f"(c[1]), "+f"(c[2]), "+f"(c[3])
        : "r"(a[0]), "r"(a[1]), "r"(a[2]), "r"(a[3]), "r"(b[0]), "r"(b[1]));
}

__device__ __forceinline__ uint32_t pack2h(float a, float b) {
    __half2 hh = __floats2half2_rn(a, b);
    return *(uint32_t*)&hh;
}

// ---------------------------------------------------------------------------
// Conversion kernels (fp32 -> single fp16)
// ---------------------------------------------------------------------------
__global__ void xconvert_kernel(const float4* __restrict__ x)
{
    const size_t i = (size_t)blockIdx.x * blockDim.x + threadIdx.x;  // over M_*C_/4
    float4 v = x[i];
    *(uint2*)(g_x + 4 * i) = make_uint2(pack2h(v.x, v.y), pack2h(v.z, v.w));
}

// Transpose: W [1024, NC] fp32 -> Wt [NC, 1024] fp16
template<int NC, int WHICH>
__global__ void wconvert_kernel(const float* __restrict__ W)
{
    __shared__ float ts[32][33];
    const int n0 = blockIdx.x * 32, k0 = blockIdx.y * 32;
    const int tx = threadIdx.x, ty = threadIdx.y;  // 32x8
    #pragma unroll
    for (int i = 0; i < 32; i += 8)
        ts[ty + i][tx] = W[(size_t)(k0 + ty + i) * NC + n0 + tx];
    __syncthreads();
    __half* dst = WHICH ? g_wo : g_wq;
    #pragma unroll
    for (int i = 0; i < 32; i += 8)
        dst[(size_t)(n0 + ty + i) * C_ + k0 + tx] = __float2half_rn(ts[tx][ty + i]);
}

// ---------------------------------------------------------------------------
// HMMA GEMM: D[128x128] = A[128,1024]*B^T, single fp16.
// 128 threads = 4 warps (2m x 2n), warp tile 64x64, BK=64, 3-stage cp.async
// ring. NEW: fragment DOUBLE-BUFFERING — LDSM for kk+1 issued before the
// MMA block of kk, so LDSM latency hides under ~256 cycles of MMA issue and
// warps are never phase-locked in a load bubble.
// MODE 0 epilogue: +bias, scale q, scatter q/k ([bh][t][d]) and v TRANSPOSED
//                  ([bh][d][t]). MODE 1: +bias -> fp32 Cout.
// ---------------------------------------------------------------------------
#define GTILE_B  16384               /* 128 rows x 128 B */
#define GSTAGE_B (2*GTILE_B)         /* A + B = 32 KB */
#define GEMM_SMEM (3*GSTAGE_B)       /* 98304 */
#define NKSTEP   (C_/64)             /* 16 */

template<int MODE>
__global__ __launch_bounds__(128, 2)
void mma_gemm_kernel(const float* __restrict__ bias, float* __restrict__ Cout)
{
    extern __shared__ char sm[];
    const uint32_t sb = smem_u32(sm);
    const int tid  = threadIdx.x;
    const int wid  = tid >> 5, lane = tid & 31;
    const int n0 = blockIdx.x * 128;
    const int m0 = blockIdx.y * 128;
    const int wr = wid & 1;          // m offset wr*64
    const int wc = wid >> 1;         // n offset wc*64

    const __half* srcA = MODE ? g_o  : g_x;
    const __half* srcB = MODE ? g_wo : g_wq;

    auto load_stage = [&](int kt, int s) {
        const uint32_t stb = sb + (uint32_t)s * GSTAGE_B;
        #pragma unroll
        for (int lt = 0; lt < 2; ++lt) {
            const __half* lg = (lt == 0 ? srcA + (size_t)m0 * C_
                                        : srcB + (size_t)n0 * C_) + kt * 64;
            const uint32_t tb = stb + lt * GTILE_B;
            #pragma unroll
            for (int i = 0; i < 8; ++i) {
                const int idx = i * 128 + tid;   // 0..1023
                const int r = idx >> 3, c = idx & 7;
                cpasync16(tb + (uint32_t)(r * 128 + ((c ^ (r & 7)) << 4)),
                          lg + (size_t)r * C_ + c * 8);
            }
        }
    };

    float acc[4][8][4];
    #pragma unroll
    for (int mt = 0; mt < 4; ++mt)
        #pragma unroll
        for (int nt = 0; nt < 8; ++nt)
            #pragma unroll
            for (int q = 0; q < 4; ++q) acc[mt][nt][q] = 0.f;

    const int rl = lane & 15, hib = lane >> 4;
    const int s7 = rl & 7;
    uint32_t aAr[4], aBr[4];
    #pragma unroll
    for (int mt = 0; mt < 4; ++mt) aAr[mt] = (uint32_t)((wr * 64 + mt * 16 + rl) * 128);
    #pragma unroll
    for (int p = 0; p < 4; ++p)    aBr[p]  = (uint32_t)((wc * 64 + p * 16 + rl) * 128) + GTILE_B;

    // fragment ping-pong buffers
    uint32_t ah[2][4][4], bh[2][4][4];
    auto ld_frags = [&](uint32_t stb, int kk, int buf) {
        const uint32_t xo = (uint32_t)(((2 * kk + hib) ^ s7) << 4);
        #pragma unroll
        for (int mt = 0; mt < 4; ++mt)
            ldsm4(ah[buf][mt], stb + aAr[mt] + xo);
        #pragma unroll
        for (int p = 0; p < 4; ++p)
            ldsm4(bh[buf][p], stb + aBr[p] + xo);
    };

    load_stage(0, 0);
    asm volatile("cp.async.commit_group;" ::: "memory");
    load_stage(1, 1);
    asm volatile("cp.async.commit_group;" ::: "memory");

    for (int kt = 0; kt < NKSTEP; ++kt) {
        asm volatile("cp.async.wait_group 1;" ::: "memory");
        __syncthreads();
        if (kt + 2 < NKSTEP) load_stage(kt + 2, (kt + 2) % 3);
        asm volatile("cp.async.commit_group;" ::: "memory");

        const uint32_t stb = sb + (uint32_t)(kt % 3) * GSTAGE_B;
        ld_frags(stb, 0, 0);
        #pragma unroll
        for (int kk = 0; kk < 4; ++kk) {
            const int cur = kk & 1;
            if (kk < 3) ld_frags(stb, kk + 1, cur ^ 1);   // prefetch next frags
            #pragma unroll
            for (int mt = 0; mt < 4; ++mt) {
                #pragma unroll
                for (int p = 0; p < 4; ++p) {
                    uint32_t bf0[2] = { bh[cur][p][0], bh[cur][p][2] };
                    uint32_t bf1[2] = { bh[cur][p][1], bh[cur][p][3] };
                    mma16816(acc[mt][2 * p],     ah[cur][mt], bf0);
                    mma16816(acc[mt][2 * p + 1], ah[cur][mt], bf1);
                }
            }
        }
    }

    const int gr = lane >> 2;
    const int gc = (lane & 3) * 2;
    #pragma unroll
    for (int mt = 0; mt < 4; ++mt) {
        #pragma unroll
        for (int nt = 0; nt < 8; ++nt) {
            const int nc = n0 + wc * 64 + nt * 8 + gc;
            const float b0 = bias[nc], b1 = bias[nc + 1];
            #pragma unroll
            for (int half_ = 0; half_ < 2; ++half_) {
                const int r = m0 + wr * 64 + mt * 16 + gr + half_ * 8;
                const float v0 = acc[mt][nt][half_ * 2 + 0] + b0;
                const float v1 = acc[mt][nt][half_ * 2 + 1] + b1;
                if (MODE == 0) {
                    const int which = nc >> 10;      // 0=q 1=k 2=v
                    const int cc = nc & 1023;
                    const int h = cc >> 6, dd = cc & 63;
                    const int b = r >> 11, t = r & 2047;
                    if (which == 2) {
                        const size_t vo = (((size_t)(b * H_ + h)) * D_ + dd) * T_ + t;
                        g_v[vo]      = __float2half_rn(v0);
                        g_v[vo + T_] = __float2half_rn(v1);
                    } else {
                        const float sc = (which == 0) ? 0.125f : 1.0f;  // fold 1/sqrt(64)
                        const size_t qo = (((size_t)(b * H_ + h)) * T_ + t) * D_ + dd;
                        *(uint32_t*)((which ? g_k : g_q) + qo) = pack2h(v0 * sc, v1 * sc);
                    }
                } else {
                    *(float2*)(Cout + (size_t)r * C_ + nc) = make_float2(v0, v1);
                }
            }
        }
    }
}

// ---------------------------------------------------------------------------
// Tensorized causal flash attention, single fp16.
// 128 threads = 4 warps; each warp owns 32 q-rows (2 row-groups of 16).
// k-tile 64, 3-stage cp.async ring. NEW: K and V fragments double-buffered
// in their j / dj loops (LDSM for next iter issued before this iter's MMAs).
// V pre-transposed [bh][d][t] -> all ldmatrix non-trans.
// ---------------------------------------------------------------------------
#define FL_STAGE 16384
#define FL_SMEM  (3*FL_STAGE)        /* 49152 */

__global__ __launch_bounds__(128, 2)
void flash_mma_kernel()
{
    extern __shared__ char sm[];
    const uint32_t sb = smem_u32(sm);
    const int tid  = threadIdx.x;
    const int lane = tid & 31, w = tid >> 5;     // 4 warps
    const int g = lane >> 2, t4 = lane & 3;
    const int bh = blockIdx.y;
    const int qb = (int)gridDim.x - 1 - (int)blockIdx.x;  // long blocks first
    const int q0 = qb * 128;
    const size_t cb = (size_t)bh * T_ * D_;
    const __half *Qg = g_q + cb;
    const __half *Kg = g_k + cb;
    const __half *Vg = g_v + cb;   // [d][t]

    // ---- stage Q (128x64 fp16 = 16KB) into stage0, read A-fragments ----
    #pragma unroll
    for (int i = 0; i < 8; ++i) {
        const int idx = i * 128 + tid;          // 0..1023
        const int r = idx >> 3, c = idx & 7;
        cpasync16(sb + (uint32_t)(r * 128 + ((c ^ (r & 7)) << 4)),
                  Qg + (size_t)(q0 + r) * D_ + c * 8);
    }
    asm volatile("cp.async.commit_group;\n\tcp.async.wait_group 0;" ::: "memory");
    __syncthreads();

    uint32_t qf[2][4][4];
    {
        const int half_ = (lane >> 4) & 1;
        #pragma unroll
        for (int rg = 0; rg < 2; ++rg) {
            const int qr = w * 32 + rg * 16 + (lane & 7) + (lane & 8);
            #pragma unroll
            for (int s = 0; s < 4; ++s) {
                const int qc = 2 * s + half_;
                ldsm4(qf[rg][s], sb + (uint32_t)(qr * 128 + ((qc ^ (qr & 7)) << 4)));
            }
        }
    }
    __syncthreads();   // all warps done with Q staging before KV overwrite

    // ---- KV tile loader: K@0 (8K), V@8K (8K) within a 16KB stage ----
    auto load_kv = [&](int kt, int st) {
        const uint32_t stb = sb + (uint32_t)st * FL_STAGE;
        #pragma unroll
        for (int i = 0; i < 4; ++i) {
            const int idx = i * 128 + tid;      // 0..511
            const int r = idx >> 3, c = idx & 7;
            const uint32_t d = stb + (uint32_t)(r * 128 + ((c ^ (r & 7)) << 4));
            cpasync16(d,        Kg + (size_t)(kt * 64 + r) * D_ + c * 8);
            cpasync16(d + 8192, Vg + (size_t)r * T_ + kt * 64 + c * 8);
        }
    };

    float oacc[2][8][4];
    #pragma unroll
    for (int rg = 0; rg < 2; ++rg)
        #pragma unroll
        for (int dj = 0; dj < 8; ++dj)
            #pragma unroll
            for (int q = 0; q < 4; ++q) oacc[rg][dj][q] = 0.f;
    float mr[2][2], lr[2][2];
    #pragma unroll
    for (int rg = 0; rg < 2; ++rg) {
        mr[rg][0] = mr[rg][1] = -INFINITY;
        lr[rg][0] = lr[rg][1] = 0.f;
    }

    const int nkt = 2 * qb + 2;
    load_kv(0, 0);
    asm volatile("cp.async.commit_group;" ::: "memory");
    load_kv(1, 1);
    asm volatile("cp.async.commit_group;" ::: "memory");

    const int ktmax_w = (q0 + w * 32 + 31) >> 6;     // last tile this warp needs
    int rowA[2], rowB[2];
    #pragma unroll
    for (int rg = 0; rg < 2; ++rg) {
        rowA[rg] = q0 + w * 32 + rg * 16 + g;
        rowB[rg] = rowA[rg] + 8;
    }

    const int c0 = lane >> 3;
    const int l7 = lane & 7;

    for (int kt = 0; kt < nkt; ++kt) {
        asm volatile("cp.async.wait_group 1;" ::: "memory");
        __syncthreads();
        if (kt + 2 < nkt) load_kv(kt + 2, (kt + 2) % 3);
        asm volatile("cp.async.commit_group;" ::: "memory");

        const uint32_t stb = sb + (uint32_t)(kt % 3) * FL_STAGE;

        if (kt <= ktmax_w) {
            // ---- S = Q K^T  (K fragments double-buffered over j) ----
            float sc[2][8][4];
            uint32_t kf[2][2][4];
            auto ld_kf = [&](int j, int buf) {
                const int kr = 8 * j + l7;
                ldsm4(kf[buf][0], stb + (uint32_t)(kr * 128 + ((c0 ^ (kr & 7)) << 4)));
                ldsm4(kf[buf][1], stb + (uint32_t)(kr * 128 + (((c0 + 4) ^ (kr & 7)) << 4)));
            };
            ld_kf(0, 0);
            #pragma unroll
            for (int j = 0; j < 8; ++j) {
                const int cur = j & 1;
                if (j < 7) ld_kf(j + 1, cur ^ 1);
                #pragma unroll
                for (int rg = 0; rg < 2; ++rg) {
                    sc[rg][j][0] = sc[rg][j][1] = sc[rg][j][2] = sc[rg][j][3] = 0.f;
                    #pragma unroll
                    for (int s = 0; s < 4; ++s) {
                        const uint32_t* kfp = kf[cur][s >> 1];
                        uint32_t bf[2] = { kfp[2 * (s & 1)], kfp[2 * (s & 1) + 1] };
                        mma16816(sc[rg][j], qf[rg][s], bf);
                    }
                }
            }

            // ---- causal mask (only near-diagonal tiles) ----
            if (kt * 64 + 63 > q0 + w * 32) {
                #pragma unroll
                for (int rg = 0; rg < 2; ++rg) {
                    #pragma unroll
                    for (int j = 0; j < 8; ++j) {
                        const int c = kt * 64 + 8 * j + 2 * t4;
                        if (c     > rowA[rg]) sc[rg][j][0] = -INFINITY;
                        if (c + 1 > rowA[rg]) sc[rg][j][1] = -INFINITY;
                        if (c     > rowB[rg]) sc[rg][j][2] = -INFINITY;
                        if (c + 1 > rowB[rg]) sc[rg][j][3] = -INFINITY;
                    }
                }
            }

            // ---- online softmax per row-group (stats over tid4 group) ----
            #pragma unroll
            for (int rg = 0; rg < 2; ++rg) {
                float mxA = -INFINITY, mxB = -INFINITY;
                #pragma unroll
                for (int j = 0; j < 8; ++j) {
                    mxA = fmaxf(mxA, fmaxf(sc[rg][j][0], sc[rg][j][1]));
                    mxB = fmaxf(mxB, fmaxf(sc[rg][j][2], sc[rg][j][3]));
                }
                #pragma unroll
                for (int sh = 1; sh <= 2; sh <<= 1) {
                    mxA = fmaxf(mxA, __shfl_xor_sync(0xffffffffu, mxA, sh));
                    mxB = fmaxf(mxB, __shfl_xor_sync(0xffffffffu, mxB, sh));
                }
                const float mAn = fmaxf(mr[rg][0], mxA), mBn = fmaxf(mr[rg][1], mxB);
                const float cA = __expf(mr[rg][0] - mAn), cB = __expf(mr[rg][1] - mBn);
                mr[rg][0] = mAn; mr[rg][1] = mBn;
                float sA = 0.f, sB = 0.f;
                #pragma unroll
                for (int j = 0; j < 8; ++j) {
                    sc[rg][j][0] = __expf(sc[rg][j][0] - mAn);
                    sc[rg][j][1] = __expf(sc[rg][j][1] - mAn);
                    sc[rg][j][2] = __expf(sc[rg][j][2] - mBn);
                    sc[rg][j][3] = __expf(sc[rg][j][3] - mBn);
                    sA += sc[rg][j][0] + sc[rg][j][1];
                    sB += sc[rg][j][2] + sc[rg][j][3];
                }
                #pragma unroll
                for (int sh = 1; sh <= 2; sh <<= 1) {
                    sA += __shfl_xor_sync(0xffffffffu, sA, sh);
                    sB += __shfl_xor_sync(0xffffffffu, sB, sh);
                }
                lr[rg][0] = lr[rg][0] * cA + sA;
                lr[rg][1] = lr[rg][1] * cB + sB;
                #pragma unroll
                for (int dj = 0; dj < 8; ++dj) {
                    oacc[rg][dj][0] *= cA; oacc[rg][dj][1] *= cA;
                    oacc[rg][dj][2] *= cB; oacc[rg][dj][3] *= cB;
                }
            }

            // ---- P fragments straight from S fragments (single fp16) ----
            uint32_t pf[2][4][4];
            #pragma unroll
            for (int rg = 0; rg < 2; ++rg) {
                #pragma unroll
                for (int s = 0; s < 4; ++s) {
                    pf[rg][s][0] = pack2h(sc[rg][2*s][0],   sc[rg][2*s][1]);
                    pf[rg][s][1] = pack2h(sc[rg][2*s][2],   sc[rg][2*s][3]);
                    pf[rg][s][2] = pack2h(sc[rg][2*s+1][0], sc[rg][2*s+1][1]);
                    pf[rg][s][3] = pack2h(sc[rg][2*s+1][2], sc[rg][2*s+1][3]);
                }
            }

            // ---- O += P V  (V fragments double-buffered over dj) ----
            uint32_t vf[2][2][4];
            auto ld_vf = [&](int dj, int buf) {
                const int vr = 8 * dj + l7;
                ldsm4(vf[buf][0], stb + 8192 + (uint32_t)(vr * 128 + ((c0 ^ (vr & 7)) << 4)));
                ldsm4(vf[buf][1], stb + 8192 + (uint32_t)(vr * 128 + (((c0 + 4) ^ (vr & 7)) << 4)));
            };
            ld_vf(0, 0);
            #pragma unroll
            for (int dj = 0; dj < 8; ++dj) {
                const int cur = dj & 1;
                if (dj < 7) ld_vf(dj + 1, cur ^ 1);
                #pragma unroll
                for (int rg = 0; rg < 2; ++rg) {
                    #pragma unroll
                    for (int s = 0; s < 4; ++s) {
                        const uint32_t* vfp = vf[cur][s >> 1];
                        uint32_t bf[2] = { vfp[2 * (s & 1)], vfp[2 * (s & 1) + 1] };
                        mma16816(oacc[rg][dj], pf[rg][s], bf);
                    }
                }
            }
        }
    }

    // ---- finalize: /l, write single fp16 to [B*T, C] ----
    const int b = bh >> 4, h = bh & 15;
    #pragma unroll
    for (int rg = 0; rg < 2; ++rg) {
        const float iA = 1.f / lr[rg][0], iB = 1.f / lr[rg][1];
        const size_t rAo = (size_t)(b * T_ + rowA[rg]) * C_ + h * 64 + 2 * t4;
        const size_t rBo = rAo + 8 * (size_t)C_;
        #pragma unroll
        for (int dj = 0; dj < 8; ++dj) {
            *(uint32_t*)(g_o + rAo + 8 * dj) = pack2h(oacc[rg][dj][0] * iA, oacc[rg][dj][1] * iA);
            *(uint32_t*)(g_o + rBo + 8 * dj) = pack2h(oacc[rg][dj][2] * iB, oacc[rg][dj][3] * iB);
        }
    }
}

// ---------------------------------------------------------------------------
extern "C" void kernel_launch(void* const* d_in, const int* in_sizes, int n_in,
                              void* d_out, int out_size)
{
    (void)in_sizes; (void)n_in; (void)out_size;
    const float* x     = (const float*)d_in[0];
    const float* W_qkv = (const float*)d_in[1];
    const float* b_qkv = (const float*)d_in[2];
    const float* W_out = (const float*)d_in[3];
    const float* b_out = (const float*)d_in[4];
    float* out = (float*)d_out;

    // 0) fp32 -> fp16 conversions
    xconvert_kernel<<<M_ * C_ / 4 / 256, 256>>>((const float4*)x);
    wconvert_kernel<NQKV, 0><<<dim3(NQKV / 32, C_ / 32), dim3(32, 8)>>>(W_qkv);
    wconvert_kernel<C_,   1><<<dim3(C_   / 32, C_ / 32), dim3(32, 8)>>>(W_out);

    // 1) QKV projection (fp16 HMMA, frag double-buffered) -> q, k, v^T
    cudaFuncSetAttribute(mma_gemm_kernel<0>, cudaFuncAttributeMaxDynamicSharedMemorySize, GEMM_SMEM);
    cudaFuncSetAttribute(mma_gemm_kernel<1>, cudaFuncAttributeMaxDynamicSharedMemorySize, GEMM_SMEM);
    mma_gemm_kernel<0><<<dim3(NQKV / 128, M_ / 128), 128, GEMM_SMEM>>>(b_qkv, nullptr);

    // 2) causal flash attention (fp16 HMMA, frag double-buffered)
    cudaFuncSetAttribute(flash_mma_kernel, cudaFuncAttributeMaxDynamicSharedMemorySize, FL_SMEM);
    flash_mma_kernel<<<dim3(T_ / 128, B_ * H_), 128, FL_SMEM>>>();

    // 3) output projection (fp16 HMMA, frag double-buffered)
    mma_gemm_kernel<1><<<dim3(C_ / 128, M_ / 128), 128, GEMM_SMEM>>>(b_out, out);
}